// round 3
// baseline (speedup 1.0000x reference)
#include <cuda_runtime.h>

#define NN 50000
#define HH 256
#define HHALF 128
#define EE 800000

// Scratch (static device globals: allowed; no allocations anywhere)
__device__ float g_tinv[(size_t)NN * HH];   // MLP_inv(h) per node; later reused for res2
__device__ float g_sums[(size_t)NN * HH];   // segment sums -> neigh
__device__ float g_res [(size_t)NN * HH];   // MLP_and output
__device__ float g_cnt [NN];

// ---------------------------------------------------------------------------
__global__ void zero_kernel() {
    const size_t n4 = (size_t)NN * HH / 4;
    float4* p = (float4*)g_sums;
    float4 z = make_float4(0.f, 0.f, 0.f, 0.f);
    for (size_t i = blockIdx.x * (size_t)blockDim.x + threadIdx.x; i < n4;
         i += (size_t)gridDim.x * blockDim.x)
        p[i] = z;
    for (int i = blockIdx.x * blockDim.x + threadIdx.x; i < NN;
         i += gridDim.x * blockDim.x)
        g_cnt[i] = 0.f;
}

// ---------------------------------------------------------------------------
// Fused 3-layer MLP: 256 -> 128 (leaky) -> 128 (leaky) -> 256 (linear)
// mode 0: plain   (x -> out)
// mode 1: scale rows by 1/max(cnt,1) on load (segment mean)
// mode 2: out[row] = (invf[row]==1) ? mlp(x[row]) : x[row]
// Block: 256 threads, 64 rows per block. Dynamic smem: xs[64][256] h1[64][128] h2[64][128]
__global__ __launch_bounds__(256, 1) void mlp3_kernel(
    const float* __restrict__ x,
    const float* __restrict__ W1, const float* __restrict__ b1,
    const float* __restrict__ W2, const float* __restrict__ b2,
    const float* __restrict__ W3, const float* __restrict__ b3,
    float* __restrict__ out, int mode, const int* __restrict__ invf)
{
    extern __shared__ float sm[];
    float* xs = sm;                 // 64 x 256
    float* h1 = sm + 64 * 256;      // 64 x 128
    float* h2 = h1 + 64 * 128;      // 64 x 128

    const int r0 = blockIdx.x * 64;

    // Load x tile (float4, coalesced), zero-pad tail rows, apply mean-scale in mode 1
    for (int i = threadIdx.x; i < 64 * 64; i += 256) {
        int row = i >> 6, c4 = i & 63;
        int gr = r0 + row;
        float4 v = make_float4(0.f, 0.f, 0.f, 0.f);
        if (gr < NN) {
            v = ((const float4*)x)[(size_t)gr * 64 + c4];
            if (mode == 1) {
                float s = 1.f / fmaxf(g_cnt[gr], 1.f);
                v.x *= s; v.y *= s; v.z *= s; v.w *= s;
            }
        }
        ((float4*)xs)[i] = v;
    }
    __syncthreads();

    const int lane = threadIdx.x & 31;
    const int warp = threadIdx.x >> 5;
    const int rb = warp * 8;

    // ---- Layer 1: K=256, M=128, leaky(0.01) ----
    {
        float bj[4], acc[8][4];
        #pragma unroll
        for (int j = 0; j < 4; j++) bj[j] = b1[lane + 32 * j];
        #pragma unroll
        for (int i = 0; i < 8; i++)
            #pragma unroll
            for (int j = 0; j < 4; j++) acc[i][j] = bj[j];
        for (int k = 0; k < 256; k++) {
            float w[4];
            #pragma unroll
            for (int j = 0; j < 4; j++) w[j] = W1[k * 128 + lane + 32 * j];
            #pragma unroll
            for (int i = 0; i < 8; i++) {
                float xv = xs[(rb + i) * 256 + k];
                #pragma unroll
                for (int j = 0; j < 4; j++) acc[i][j] = fmaf(xv, w[j], acc[i][j]);
            }
        }
        #pragma unroll
        for (int i = 0; i < 8; i++)
            #pragma unroll
            for (int j = 0; j < 4; j++) {
                float v = acc[i][j];
                h1[(rb + i) * 128 + lane + 32 * j] = (v >= 0.f) ? v : 0.01f * v;
            }
    }
    __syncthreads();

    // ---- Layer 2: K=128, M=128, leaky(0.01) ----
    {
        float bj[4], acc[8][4];
        #pragma unroll
        for (int j = 0; j < 4; j++) bj[j] = b2[lane + 32 * j];
        #pragma unroll
        for (int i = 0; i < 8; i++)
            #pragma unroll
            for (int j = 0; j < 4; j++) acc[i][j] = bj[j];
        for (int k = 0; k < 128; k++) {
            float w[4];
            #pragma unroll
            for (int j = 0; j < 4; j++) w[j] = W2[k * 128 + lane + 32 * j];
            #pragma unroll
            for (int i = 0; i < 8; i++) {
                float xv = h1[(rb + i) * 128 + k];
                #pragma unroll
                for (int j = 0; j < 4; j++) acc[i][j] = fmaf(xv, w[j], acc[i][j]);
            }
        }
        #pragma unroll
        for (int i = 0; i < 8; i++)
            #pragma unroll
            for (int j = 0; j < 4; j++) {
                float v = acc[i][j];
                h2[(rb + i) * 128 + lane + 32 * j] = (v >= 0.f) ? v : 0.01f * v;
            }
    }
    __syncthreads();

    // ---- Layer 3: K=128, M=256, linear; store to global with mode-2 select ----
    {
        float bj[8], acc[8][8];
        #pragma unroll
        for (int j = 0; j < 8; j++) bj[j] = b3[lane + 32 * j];
        #pragma unroll
        for (int i = 0; i < 8; i++)
            #pragma unroll
            for (int j = 0; j < 8; j++) acc[i][j] = bj[j];
        for (int k = 0; k < 128; k++) {
            float w[8];
            #pragma unroll
            for (int j = 0; j < 8; j++) w[j] = W3[k * 256 + lane + 32 * j];
            #pragma unroll
            for (int i = 0; i < 8; i++) {
                float xv = h2[(rb + i) * 128 + k];
                #pragma unroll
                for (int j = 0; j < 8; j++) acc[i][j] = fmaf(xv, w[j], acc[i][j]);
            }
        }
        #pragma unroll
        for (int i = 0; i < 8; i++) {
            int row = r0 + rb + i;
            if (row < NN) {
                bool take_mlp = (mode != 2) || (invf[row] == 1);
                #pragma unroll
                for (int j = 0; j < 8; j++) {
                    int c = lane + 32 * j;
                    float v = take_mlp ? acc[i][j] : xs[(rb + i) * 256 + c];
                    out[(size_t)row * 256 + c] = v;
                }
            }
        }
    }
}

// ---------------------------------------------------------------------------
// Edge scatter: one warp per edge. msg = (r==1) ? g_tinv[src] : h[src];
// vectorized L2-side reduction into g_sums[dst], count into g_cnt[dst].
__global__ __launch_bounds__(256) void scatter_kernel(
    const float* __restrict__ h,
    const int* __restrict__ src, const int* __restrict__ dst,
    const int* __restrict__ r)
{
    int wid = (blockIdx.x * 256 + threadIdx.x) >> 5;
    int lane = threadIdx.x & 31;
    if (wid >= EE) return;
    int s = __ldg(src + wid);
    int d = __ldg(dst + wid);
    int rr = __ldg(r + wid);
    const float4* srow =
        (const float4*)((rr == 1 ? g_tinv : h) + (size_t)s * HH);
    float4* drow = (float4*)(g_sums + (size_t)d * HH);
    #pragma unroll
    for (int j = 0; j < 2; j++) {
        float4 v = __ldg(srow + lane + 32 * j);
        float4* p = drow + lane + 32 * j;
        asm volatile("red.global.add.v4.f32 [%0], {%1,%2,%3,%4};"
                     :: "l"(p), "f"(v.x), "f"(v.y), "f"(v.z), "f"(v.w)
                     : "memory");
    }
    if (lane == 0) atomicAdd(&g_cnt[d], 1.0f);
}

// ---------------------------------------------------------------------------
// Projection head: 256 -> 256 (relu) -> 256 (linear)
__global__ __launch_bounds__(256, 1) void proj_kernel(
    const float* __restrict__ x,
    const float* __restrict__ W1, const float* __restrict__ b1,
    const float* __restrict__ W2, const float* __restrict__ b2,
    float* __restrict__ out)
{
    extern __shared__ float sm[];
    float* xs = sm;                 // 64 x 256
    float* hh = sm + 64 * 256;      // 64 x 256

    const int r0 = blockIdx.x * 64;
    for (int i = threadIdx.x; i < 64 * 64; i += 256) {
        int row = i >> 6, c4 = i & 63;
        int gr = r0 + row;
        float4 v = make_float4(0.f, 0.f, 0.f, 0.f);
        if (gr < NN) v = ((const float4*)x)[(size_t)gr * 64 + c4];
        ((float4*)xs)[i] = v;
    }
    __syncthreads();

    const int lane = threadIdx.x & 31;
    const int warp = threadIdx.x >> 5;
    const int rb = warp * 8;

    // Layer 1: K=256, M=256, relu
    {
        float bj[8], acc[8][8];
        #pragma unroll
        for (int j = 0; j < 8; j++) bj[j] = b1[lane + 32 * j];
        #pragma unroll
        for (int i = 0; i < 8; i++)
            #pragma unroll
            for (int j = 0; j < 8; j++) acc[i][j] = bj[j];
        for (int k = 0; k < 256; k++) {
            float w[8];
            #pragma unroll
            for (int j = 0; j < 8; j++) w[j] = W1[k * 256 + lane + 32 * j];
            #pragma unroll
            for (int i = 0; i < 8; i++) {
                float xv = xs[(rb + i) * 256 + k];
                #pragma unroll
                for (int j = 0; j < 8; j++) acc[i][j] = fmaf(xv, w[j], acc[i][j]);
            }
        }
        #pragma unroll
        for (int i = 0; i < 8; i++)
            #pragma unroll
            for (int j = 0; j < 8; j++)
                hh[(rb + i) * 256 + lane + 32 * j] = fmaxf(acc[i][j], 0.f);
    }
    __syncthreads();

    // Layer 2: K=256, M=256, linear -> global
    {
        float bj[8], acc[8][8];
        #pragma unroll
        for (int j = 0; j < 8; j++) bj[j] = b2[lane + 32 * j];
        #pragma unroll
        for (int i = 0; i < 8; i++)
            #pragma unroll
            for (int j = 0; j < 8; j++) acc[i][j] = bj[j];
        for (int k = 0; k < 256; k++) {
            float w[8];
            #pragma unroll
            for (int j = 0; j < 8; j++) w[j] = W2[k * 256 + lane + 32 * j];
            #pragma unroll
            for (int i = 0; i < 8; i++) {
                float xv = hh[(rb + i) * 256 + k];
                #pragma unroll
                for (int j = 0; j < 8; j++) acc[i][j] = fmaf(xv, w[j], acc[i][j]);
            }
        }
        #pragma unroll
        for (int i = 0; i < 8; i++) {
            int row = r0 + rb + i;
            if (row < NN) {
                #pragma unroll
                for (int j = 0; j < 8; j++)
                    out[(size_t)row * 256 + lane + 32 * j] = acc[i][j];
            }
        }
    }
}

// ---------------------------------------------------------------------------
extern "C" void kernel_launch(void* const* d_in, const int* in_sizes, int n_in,
                              void* d_out, int out_size)
{
    const float* h   = (const float*)d_in[0];
    const int*   src = (const int*)  d_in[1];
    const int*   dst = (const int*)  d_in[2];
    const int*   r   = (const int*)  d_in[3];
    const int*   inv = (const int*)  d_in[4];
    const float* iW1 = (const float*)d_in[5];
    const float* ib1 = (const float*)d_in[6];
    const float* iW2 = (const float*)d_in[7];
    const float* ib2 = (const float*)d_in[8];
    const float* iW3 = (const float*)d_in[9];
    const float* ib3 = (const float*)d_in[10];
    const float* aW1 = (const float*)d_in[11];
    const float* ab1 = (const float*)d_in[12];
    const float* aW2 = (const float*)d_in[13];
    const float* ab2 = (const float*)d_in[14];
    const float* aW3 = (const float*)d_in[15];
    const float* ab3 = (const float*)d_in[16];
    const float* pW1 = (const float*)d_in[17];
    const float* pb1 = (const float*)d_in[18];
    const float* pW2 = (const float*)d_in[19];
    const float* pb2 = (const float*)d_in[20];
    float* out = (float*)d_out;

    float *tinv, *sums, *res;
    cudaGetSymbolAddress((void**)&tinv, g_tinv);
    cudaGetSymbolAddress((void**)&sums, g_sums);
    cudaGetSymbolAddress((void**)&res,  g_res);

    const int SMEM_MLP3 = (64 * 256 + 64 * 128 + 64 * 128) * 4;  // 128 KB
    const int SMEM_PROJ = (64 * 256 + 64 * 256) * 4;             // 128 KB
    cudaFuncSetAttribute(mlp3_kernel, cudaFuncAttributeMaxDynamicSharedMemorySize, SMEM_MLP3);
    cudaFuncSetAttribute(proj_kernel, cudaFuncAttributeMaxDynamicSharedMemorySize, SMEM_PROJ);

    const int nblocks = (NN + 63) / 64;

    // 1) zero accumulators
    zero_kernel<<<1024, 256>>>();
    // 2) t_inv = MLP_inv(h) for all nodes (8x FLOP reduction vs per-edge MLP)
    mlp3_kernel<<<nblocks, 256, SMEM_MLP3>>>(h, iW1, ib1, iW2, ib2, iW3, ib3,
                                             tinv, 0, nullptr);
    // 3) edge scatter-mean accumulation
    scatter_kernel<<<(EE * 32 + 255) / 256, 256>>>(h, src, dst, r);
    // 4) res = MLP_and(neigh) with on-the-fly mean
    mlp3_kernel<<<nblocks, 256, SMEM_MLP3>>>(sums, aW1, ab1, aW2, ab2, aW3, ab3,
                                             res, 1, nullptr);
    // 5) res2 = inv ? MLP_inv(res) : res   (reuse g_tinv as res2)
    mlp3_kernel<<<nblocks, 256, SMEM_MLP3>>>(res, iW1, ib1, iW2, ib2, iW3, ib3,
                                             tinv, 2, inv);
    // 6) out = proj(res2)
    proj_kernel<<<nblocks, 256, SMEM_PROJ>>>(tinv, pW1, pb1, pW2, pb2, out);
}

// round 6
// speedup vs baseline: 3.7263x; 3.7263x over previous
#include <cuda_runtime.h>
#include <cuda_bf16.h>
#include <cstdint>

#define NND 50000
#define NP  50048              // padded to 391*128
#define EE  800000

// ---------------------------------------------------------------------------
// Scratch (device globals; no allocations anywhere)
__device__ float g_tinv[(size_t)NP * 256];
__device__ float g_sums[(size_t)NP * 256];
__device__ float g_res [(size_t)NP * 256];
__device__ float g_tmp1[(size_t)NP * 128];
__device__ float g_tmp2[(size_t)NP * 128];
__device__ float g_cnt [NND];

// Pre-transposed + split weights: Wt[n][k] = W[k][n], hi/lo bf16
__device__ __nv_bfloat16 g_iW1h[128*256], g_iW1l[128*256];
__device__ __nv_bfloat16 g_iW2h[128*128], g_iW2l[128*128];
__device__ __nv_bfloat16 g_iW3h[256*128], g_iW3l[256*128];
__device__ __nv_bfloat16 g_aW1h[128*256], g_aW1l[128*256];
__device__ __nv_bfloat16 g_aW2h[128*128], g_aW2l[128*128];
__device__ __nv_bfloat16 g_aW3h[256*128], g_aW3l[256*128];
__device__ __nv_bfloat16 g_pW1h[256*256], g_pW1l[256*256];
__device__ __nv_bfloat16 g_pW2h[256*256], g_pW2l[256*256];

// ---------------------------------------------------------------------------
__device__ __forceinline__ uint32_t smem_u32_of(const void* p) {
    uint32_t a;
    asm("{ .reg .u64 t; cvta.to.shared.u64 t, %1; cvt.u32.u64 %0, t; }"
        : "=r"(a) : "l"(p));
    return a;
}
#define LDSM4(r, addr)                                                         \
    asm volatile("ldmatrix.sync.aligned.m8n8.x4.shared.b16 {%0,%1,%2,%3}, [%4];" \
        : "=r"((r)[0]), "=r"((r)[1]), "=r"((r)[2]), "=r"((r)[3]) : "r"(addr))

__device__ __forceinline__ void mma16816(float* d, const uint32_t* a,
                                         const uint32_t* b) {
    asm volatile("mma.sync.aligned.m16n8k16.row.col.f32.bf16.bf16.f32 "
        "{%0,%1,%2,%3}, {%4,%5,%6,%7}, {%8,%9}, {%0,%1,%2,%3};"
        : "+f"(d[0]), "+f"(d[1]), "+f"(d[2]), "+f"(d[3])
        : "r"(a[0]), "r"(a[1]), "r"(a[2]), "r"(a[3]), "r"(b[0]), "r"(b[1]));
}
__device__ __forceinline__ uint32_t pack2(float a, float b) {
    __nv_bfloat16 x = __float2bfloat16(a), y = __float2bfloat16(b);
    return (uint32_t)__bfloat16_as_ushort(x) | ((uint32_t)__bfloat16_as_ushort(y) << 16);
}

// ---------------------------------------------------------------------------
__global__ void zero_kernel() {
    const size_t n4 = (size_t)NP * 256 / 4;
    float4* p = (float4*)g_sums;
    float4 z = make_float4(0.f, 0.f, 0.f, 0.f);
    for (size_t i = blockIdx.x * (size_t)blockDim.x + threadIdx.x; i < n4;
         i += (size_t)gridDim.x * blockDim.x)
        p[i] = z;
    for (int i = blockIdx.x * blockDim.x + threadIdx.x; i < NND;
         i += gridDim.x * blockDim.x)
        g_cnt[i] = 0.f;
}

// Transpose + hi/lo bf16 split of one weight matrix W[K][N] -> T[N][K]
__global__ void prep_w(const float* __restrict__ W, __nv_bfloat16* __restrict__ Th,
                       __nv_bfloat16* __restrict__ Tl, int K, int N) {
    int i = blockIdx.x * blockDim.x + threadIdx.x;
    if (i >= N * K) return;
    int n = i / K, k = i % K;
    float v = W[(size_t)k * N + n];
    __nv_bfloat16 h = __float2bfloat16(v);
    Th[i] = h;
    Tl[i] = __float2bfloat16(v - __bfloat162float(h));
}

// ---------------------------------------------------------------------------
// Split-bf16 GEMM via mma.sync (HMMA): out[M,N] = act(X[M,K] @ W[K,N] + b)
// CTA tile 128x128, 8 warps (4m x 2n), warp tile 32x64, K chunk 64.
// SMEM (64KB): AH@0, AL@16K, BH@32K, BL@48K; 128B rows, seg^(row&7) swizzle.
// cntp: row-scale X by 1/max(cnt,1). invf/passthru: final inv-select.
__global__ __launch_bounds__(256, 2) void gemm_kernel(
    const float* __restrict__ x,
    const __nv_bfloat16* __restrict__ Bh, const __nv_bfloat16* __restrict__ Bl,
    const float* __restrict__ bias, float* __restrict__ out,
    int K, int N, int act,
    const float* __restrict__ cntp, const int* __restrict__ invf,
    const float* __restrict__ passthru)
{
    extern __shared__ char sm[];
    const uint32_t smb = smem_u32_of(sm);
    const int tid = threadIdx.x, lane = tid & 31, warp = tid >> 5;
    const int warp_m = warp & 3, warp_n = warp >> 2;
    const int r0 = blockIdx.x * 128;
    const int c0 = blockIdx.y * 128;

    const uint32_t AH = 0, AL = 16384, BH = 32768, BL = 49152;

    float c[2][8][4];
    #pragma unroll
    for (int i = 0; i < 2; i++)
        #pragma unroll
        for (int j = 0; j < 8; j++)
            #pragma unroll
            for (int k = 0; k < 4; k++) c[i][j][k] = 0.f;

    const int nch = K >> 6;
    for (int ch = 0; ch < nch; ch++) {
        // ---- stage A chunk (fp32 -> bf16 hi/lo) ----
        for (int u = tid; u < 1024; u += 256) {
            int row = u >> 3, seg = u & 7;
            int gr = r0 + row;
            float v[8];
            if (gr < NND) {
                const float4* s = (const float4*)(x + (size_t)gr * K + ch * 64 + seg * 8);
                float4 a = s[0], b = s[1];
                v[0]=a.x; v[1]=a.y; v[2]=a.z; v[3]=a.w;
                v[4]=b.x; v[5]=b.y; v[6]=b.z; v[7]=b.w;
                if (cntp) {
                    float sc = 1.f / fmaxf(cntp[gr], 1.f);
                    #pragma unroll
                    for (int t = 0; t < 8; t++) v[t] *= sc;
                }
            } else {
                #pragma unroll
                for (int t = 0; t < 8; t++) v[t] = 0.f;
            }
            uint32_t hp[4], lp[4];
            #pragma unroll
            for (int j = 0; j < 4; j++) {
                float va = v[2*j], vb = v[2*j+1];
                __nv_bfloat16 ha = __float2bfloat16(va), hb = __float2bfloat16(vb);
                hp[j] = (uint32_t)__bfloat16_as_ushort(ha)
                      | ((uint32_t)__bfloat16_as_ushort(hb) << 16);
                lp[j] = pack2(va - __bfloat162float(ha), vb - __bfloat162float(hb));
            }
            uint32_t off = (uint32_t)row * 128 + ((uint32_t)(seg ^ (row & 7)) << 4);
            *(uint4*)(sm + AH + off) = make_uint4(hp[0], hp[1], hp[2], hp[3]);
            *(uint4*)(sm + AL + off) = make_uint4(lp[0], lp[1], lp[2], lp[3]);
        }
        // ---- stage B chunk (pre-split bf16, [n][k] rows) ----
        for (int u = tid; u < 1024; u += 256) {
            int row = u >> 3, seg = u & 7;
            uint32_t off = (uint32_t)row * 128 + ((uint32_t)(seg ^ (row & 7)) << 4);
            size_t gb = (size_t)(c0 + row) * K + ch * 64 + seg * 8;
            *(uint4*)(sm + BH + off) = *(const uint4*)(Bh + gb);
            *(uint4*)(sm + BL + off) = *(const uint4*)(Bl + gb);
        }
        __syncthreads();

        #pragma unroll
        for (int ks = 0; ks < 4; ks++) {
            uint32_t ah[2][4], al[2][4];
            #pragma unroll
            for (int mt = 0; mt < 2; mt++) {
                int lr = warp_m * 32 + mt * 16 + (lane & 15);
                int seg = 2 * ks + (lane >> 4);
                uint32_t off = (uint32_t)lr * 128 + ((uint32_t)(seg ^ (lr & 7)) << 4);
                LDSM4(ah[mt], smb + AH + off);
                LDSM4(al[mt], smb + AL + off);
            }
            #pragma unroll
            for (int nq = 0; nq < 4; nq++) {
                int lrb = warp_n * 64 + nq * 16 + (lane & 7) + ((lane >> 4) << 3);
                int segb = 2 * ks + ((lane >> 3) & 1);
                uint32_t offb = (uint32_t)lrb * 128 + ((uint32_t)(segb ^ (lrb & 7)) << 4);
                uint32_t bh[4], bl[4];
                LDSM4(bh, smb + BH + offb);
                LDSM4(bl, smb + BL + offb);
                #pragma unroll
                for (int mt = 0; mt < 2; mt++) {
                    #pragma unroll
                    for (int sub = 0; sub < 2; sub++) {
                        float* d = c[mt][nq * 2 + sub];
                        mma16816(d, ah[mt], bh + sub * 2);
                        mma16816(d, ah[mt], bl + sub * 2);
                        mma16816(d, al[mt], bh + sub * 2);
                    }
                }
            }
        }
        __syncthreads();
    }

    // ---- epilogue: bias + activation + inv-select, direct float2 stores ----
    #pragma unroll
    for (int mt = 0; mt < 2; mt++) {
        #pragma unroll
        for (int q = 0; q < 8; q++) {
            int col = c0 + warp_n * 64 + q * 8 + (lane & 3) * 2;
            float2 bv = *(const float2*)(bias + col);
            #pragma unroll
            for (int half = 0; half < 2; half++) {
                int row = r0 + warp_m * 32 + mt * 16 + (lane >> 2) + half * 8;
                if (row < NND) {
                    float v0 = c[mt][q][half * 2 + 0] + bv.x;
                    float v1 = c[mt][q][half * 2 + 1] + bv.y;
                    if (act == 1) {
                        v0 = (v0 >= 0.f) ? v0 : 0.01f * v0;
                        v1 = (v1 >= 0.f) ? v1 : 0.01f * v1;
                    } else if (act == 2) {
                        v0 = fmaxf(v0, 0.f);
                        v1 = fmaxf(v1, 0.f);
                    }
                    if (invf && invf[row] != 1) {
                        float2 p = *(const float2*)(passthru + (size_t)row * N + col);
                        v0 = p.x; v1 = p.y;
                    }
                    *(float2*)(out + (size_t)row * N + col) = make_float2(v0, v1);
                }
            }
        }
    }
}

// ---------------------------------------------------------------------------
// Edge scatter: warp per edge; msg = (r==1) ? tinv[src] : h[src]
__global__ __launch_bounds__(256) void scatter_kernel(
    const float* __restrict__ h,
    const int* __restrict__ src, const int* __restrict__ dst,
    const int* __restrict__ r)
{
    int wid = (blockIdx.x * 256 + threadIdx.x) >> 5;
    int lane = threadIdx.x & 31;
    if (wid >= EE) return;
    int s = __ldg(src + wid);
    int d = __ldg(dst + wid);
    int rr = __ldg(r + wid);
    const float4* srow = (const float4*)((rr == 1 ? g_tinv : h) + (size_t)s * 256);
    float4* drow = (float4*)(g_sums + (size_t)d * 256);
    #pragma unroll
    for (int j = 0; j < 2; j++) {
        float4 v = __ldg(srow + lane + 32 * j);
        float4* p = drow + lane + 32 * j;
        asm volatile("red.global.add.v4.f32 [%0], {%1,%2,%3,%4};"
                     :: "l"(p), "f"(v.x), "f"(v.y), "f"(v.z), "f"(v.w) : "memory");
    }
    if (lane == 0) atomicAdd(&g_cnt[d], 1.0f);
}

// ---------------------------------------------------------------------------
extern "C" void kernel_launch(void* const* d_in, const int* in_sizes, int n_in,
                              void* d_out, int out_size)
{
    const float* h   = (const float*)d_in[0];
    const int*   src = (const int*)  d_in[1];
    const int*   dst = (const int*)  d_in[2];
    const int*   r   = (const int*)  d_in[3];
    const int*   inv = (const int*)  d_in[4];
    const float* iW1 = (const float*)d_in[5];
    const float* ib1 = (const float*)d_in[6];
    const float* iW2 = (const float*)d_in[7];
    const float* ib2 = (const float*)d_in[8];
    const float* iW3 = (const float*)d_in[9];
    const float* ib3 = (const float*)d_in[10];
    const float* aW1 = (const float*)d_in[11];
    const float* ab1 = (const float*)d_in[12];
    const float* aW2 = (const float*)d_in[13];
    const float* ab2 = (const float*)d_in[14];
    const float* aW3 = (const float*)d_in[15];
    const float* ab3 = (const float*)d_in[16];
    const float* pW1 = (const float*)d_in[17];
    const float* pb1 = (const float*)d_in[18];
    const float* pW2 = (const float*)d_in[19];
    const float* pb2 = (const float*)d_in[20];
    float* out = (float*)d_out;

    float *tinv, *sums, *res, *tmp1, *tmp2, *cnt;
    cudaGetSymbolAddress((void**)&tinv, g_tinv);
    cudaGetSymbolAddress((void**)&sums, g_sums);
    cudaGetSymbolAddress((void**)&res,  g_res);
    cudaGetSymbolAddress((void**)&tmp1, g_tmp1);
    cudaGetSymbolAddress((void**)&tmp2, g_tmp2);
    cudaGetSymbolAddress((void**)&cnt,  g_cnt);

    __nv_bfloat16 *iW1h,*iW1l,*iW2h,*iW2l,*iW3h,*iW3l;
    __nv_bfloat16 *aW1h,*aW1l,*aW2h,*aW2l,*aW3h,*aW3l;
    __nv_bfloat16 *pW1h,*pW1l,*pW2h,*pW2l;
    cudaGetSymbolAddress((void**)&iW1h, g_iW1h); cudaGetSymbolAddress((void**)&iW1l, g_iW1l);
    cudaGetSymbolAddress((void**)&iW2h, g_iW2h); cudaGetSymbolAddress((void**)&iW2l, g_iW2l);
    cudaGetSymbolAddress((void**)&iW3h, g_iW3h); cudaGetSymbolAddress((void**)&iW3l, g_iW3l);
    cudaGetSymbolAddress((void**)&aW1h, g_aW1h); cudaGetSymbolAddress((void**)&aW1l, g_aW1l);
    cudaGetSymbolAddress((void**)&aW2h, g_aW2h); cudaGetSymbolAddress((void**)&aW2l, g_aW2l);
    cudaGetSymbolAddress((void**)&aW3h, g_aW3h); cudaGetSymbolAddress((void**)&aW3l, g_aW3l);
    cudaGetSymbolAddress((void**)&pW1h, g_pW1h); cudaGetSymbolAddress((void**)&pW1l, g_pW1l);
    cudaGetSymbolAddress((void**)&pW2h, g_pW2h); cudaGetSymbolAddress((void**)&pW2l, g_pW2l);

    cudaFuncSetAttribute(gemm_kernel, cudaFuncAttributeMaxDynamicSharedMemorySize, 65536);

    const int NB = (NND + 127) / 128;   // 391
    dim3 g128(NB, 1), g256(NB, 2);

    zero_kernel<<<1024, 256>>>();
    // transpose+split weights
    prep_w<<<(128*256+255)/256, 256>>>(iW1, iW1h, iW1l, 256, 128);
    prep_w<<<(128*128+255)/256, 256>>>(iW2, iW2h, iW2l, 128, 128);
    prep_w<<<(256*128+255)/256, 256>>>(iW3, iW3h, iW3l, 128, 256);
    prep_w<<<(128*256+255)/256, 256>>>(aW1, aW1h, aW1l, 256, 128);
    prep_w<<<(128*128+255)/256, 256>>>(aW2, aW2h, aW2l, 128, 128);
    prep_w<<<(256*128+255)/256, 256>>>(aW3, aW3h, aW3l, 128, 256);
    prep_w<<<(256*256+255)/256, 256>>>(pW1, pW1h, pW1l, 256, 256);
    prep_w<<<(256*256+255)/256, 256>>>(pW2, pW2h, pW2l, 256, 256);

    // tinv = MLP_inv(h)
    gemm_kernel<<<g128, 256, 65536>>>(h,    iW1h, iW1l, ib1, tmp1, 256, 128, 1, 0, 0, 0);
    gemm_kernel<<<g128, 256, 65536>>>(tmp1, iW2h, iW2l, ib2, tmp2, 128, 128, 1, 0, 0, 0);
    gemm_kernel<<<g256, 256, 65536>>>(tmp2, iW3h, iW3l, ib3, tinv, 128, 256, 0, 0, 0, 0);
    // edge scatter-mean
    scatter_kernel<<<(EE * 32 + 255) / 256, 256>>>(h, src, dst, r);
    // res = MLP_and(mean(neigh))
    gemm_kernel<<<g128, 256, 65536>>>(sums, aW1h, aW1l, ab1, tmp1, 256, 128, 1, cnt, 0, 0);
    gemm_kernel<<<g128, 256, 65536>>>(tmp1, aW2h, aW2l, ab2, tmp2, 128, 128, 1, 0, 0, 0);
    gemm_kernel<<<g256, 256, 65536>>>(tmp2, aW3h, aW3l, ab3, res,  128, 256, 0, 0, 0, 0);
    // res2 = inv ? MLP_inv(res) : res   (into tinv)
    gemm_kernel<<<g128, 256, 65536>>>(res,  iW1h, iW1l, ib1, tmp1, 256, 128, 1, 0, 0, 0);
    gemm_kernel<<<g128, 256, 65536>>>(tmp1, iW2h, iW2l, ib2, tmp2, 128, 128, 1, 0, 0, 0);
    gemm_kernel<<<g256, 256, 65536>>>(tmp2, iW3h, iW3l, ib3, tinv, 128, 256, 0, 0, inv, res);
    // proj head (reuse g_sums as hidden)
    gemm_kernel<<<g256, 256, 65536>>>(tinv, pW1h, pW1l, pb1, sums, 256, 256, 2, 0, 0, 0);
    gemm_kernel<<<g256, 256, 65536>>>(sums, pW2h, pW2l, pb2, out,  256, 256, 0, 0, 0, 0);
}

// round 7
// speedup vs baseline: 4.3895x; 1.1780x over previous
#include <cuda_runtime.h>
#include <cuda_bf16.h>
#include <cstdint>

#define NND 50000
#define NP  50048              // padded to 391*128
#define EE  800000

// ---------------------------------------------------------------------------
// Scratch (device globals; no allocations anywhere)
__device__ float g_tinv[(size_t)NP * 256];   // fp32 MLP_inv(h) (scatter msg)
__device__ float g_sums[(size_t)NP * 256];   // segment sums
__device__ float g_cnt [NND];
__device__ int   g_invidx[NND];
__device__ int   g_ninv;

// split-bf16 activation buffers
__device__ __align__(16) __nv_bfloat16 g_xh[(size_t)NP * 256], g_xl[(size_t)NP * 256]; // h split -> res2 split
__device__ __align__(16) __nv_bfloat16 g_sh[(size_t)NP * 256], g_sl[(size_t)NP * 256]; // sums split -> proj hidden
__device__ __align__(16) __nv_bfloat16 g_t1h[(size_t)NP * 128], g_t1l[(size_t)NP * 128];
__device__ __align__(16) __nv_bfloat16 g_t2h[(size_t)NP * 128], g_t2l[(size_t)NP * 128];

// Pre-transposed + split weights: Wt[n][k] = W[k][n], hi/lo bf16
__device__ __align__(16) __nv_bfloat16 g_iW1h[128*256], g_iW1l[128*256];
__device__ __align__(16) __nv_bfloat16 g_iW2h[128*128], g_iW2l[128*128];
__device__ __align__(16) __nv_bfloat16 g_iW3h[256*128], g_iW3l[256*128];
__device__ __align__(16) __nv_bfloat16 g_aW1h[128*256], g_aW1l[128*256];
__device__ __align__(16) __nv_bfloat16 g_aW2h[128*128], g_aW2l[128*128];
__device__ __align__(16) __nv_bfloat16 g_aW3h[256*128], g_aW3l[256*128];
__device__ __align__(16) __nv_bfloat16 g_pW1h[256*256], g_pW1l[256*256];
__device__ __align__(16) __nv_bfloat16 g_pW2h[256*256], g_pW2l[256*256];

// ---------------------------------------------------------------------------
__device__ __forceinline__ uint32_t smem_u32_of(const void* p) {
    uint32_t a;
    asm("{ .reg .u64 t; cvta.to.shared.u64 t, %1; cvt.u32.u64 %0, t; }"
        : "=r"(a) : "l"(p));
    return a;
}
#define LDSM4(r, addr)                                                         \
    asm volatile("ldmatrix.sync.aligned.m8n8.x4.shared.b16 {%0,%1,%2,%3}, [%4];" \
        : "=r"((r)[0]), "=r"((r)[1]), "=r"((r)[2]), "=r"((r)[3]) : "r"(addr))
#define CP_ASYNC16(dst, src, sz)                                               \
    asm volatile("cp.async.cg.shared.global [%0], [%1], 16, %2;"               \
        :: "r"(dst), "l"(src), "r"(sz) : "memory")
#define CP_COMMIT() asm volatile("cp.async.commit_group;" ::: "memory")
#define CP_WAIT1()  asm volatile("cp.async.wait_group 1;" ::: "memory")
#define CP_WAIT0()  asm volatile("cp.async.wait_group 0;" ::: "memory")

__device__ __forceinline__ void mma16816(float* d, const uint32_t* a,
                                         const uint32_t* b) {
    asm volatile("mma.sync.aligned.m16n8k16.row.col.f32.bf16.bf16.f32 "
        "{%0,%1,%2,%3}, {%4,%5,%6,%7}, {%8,%9}, {%0,%1,%2,%3};"
        : "+f"(d[0]), "+f"(d[1]), "+f"(d[2]), "+f"(d[3])
        : "r"(a[0]), "r"(a[1]), "r"(a[2]), "r"(a[3]), "r"(b[0]), "r"(b[1]));
}
__device__ __forceinline__ uint32_t pack2(float a, float b) {
    __nv_bfloat16 x = __float2bfloat16(a), y = __float2bfloat16(b);
    return (uint32_t)__bfloat16_as_ushort(x) | ((uint32_t)__bfloat16_as_ushort(y) << 16);
}

// ---------------------------------------------------------------------------
__global__ void zero_kernel() {
    const size_t n4 = (size_t)NP * 256 / 4;
    float4* p = (float4*)g_sums;
    float4 z = make_float4(0.f, 0.f, 0.f, 0.f);
    for (size_t i = blockIdx.x * (size_t)blockDim.x + threadIdx.x; i < n4;
         i += (size_t)gridDim.x * blockDim.x)
        p[i] = z;
    for (int i = blockIdx.x * blockDim.x + threadIdx.x; i < NND;
         i += gridDim.x * blockDim.x)
        g_cnt[i] = 0.f;
    if (blockIdx.x == 0 && threadIdx.x == 0) g_ninv = 0;
}

__global__ void count_inv(const int* __restrict__ inv) {
    int i = blockIdx.x * blockDim.x + threadIdx.x;
    if (i < NND && inv[i] == 1) {
        int p = atomicAdd(&g_ninv, 1);
        g_invidx[p] = i;
    }
}

// All 8 weight transposes + splits in one launch
__global__ void prep_all(const float* W0, const float* W1, const float* W2,
                         const float* W3, const float* W4, const float* W5,
                         const float* W6, const float* W7) {
    int i = blockIdx.x * blockDim.x + threadIdx.x;
    if (i >= 294912) return;
    const int cum[9]  = {0, 32768, 49152, 81920, 114688, 131072, 163840, 229376, 294912};
    const int Ks[8]   = {256, 128, 128, 256, 128, 128, 256, 256};
    const int Ns[8]   = {128, 128, 256, 128, 128, 256, 256, 256};
    int m = 0;
    #pragma unroll
    for (int t = 1; t < 8; t++) if (i >= cum[t]) m = t;
    int j = i - cum[m], K = Ks[m], N = Ns[m];
    int n = j / K, k = j % K;
    const float* W; __nv_bfloat16 *Th, *Tl;
    switch (m) {
        case 0: W = W0; Th = g_iW1h; Tl = g_iW1l; break;
        case 1: W = W1; Th = g_iW2h; Tl = g_iW2l; break;
        case 2: W = W2; Th = g_iW3h; Tl = g_iW3l; break;
        case 3: W = W3; Th = g_aW1h; Tl = g_aW1l; break;
        case 4: W = W4; Th = g_aW2h; Tl = g_aW2l; break;
        case 5: W = W5; Th = g_aW3h; Tl = g_aW3l; break;
        case 6: W = W6; Th = g_pW1h; Tl = g_pW1l; break;
        default: W = W7; Th = g_pW2h; Tl = g_pW2l; break;
    }
    float v = W[(size_t)k * N + n];
    __nv_bfloat16 h = __float2bfloat16(v);
    Th[j] = h;
    Tl[j] = __float2bfloat16(v - __bfloat162float(h));
}

// fp32 [NND x 256] -> split bf16, optional per-row 1/max(cnt,1) scaling
__global__ void conv_split(const float* __restrict__ x,
                           __nv_bfloat16* __restrict__ oh,
                           __nv_bfloat16* __restrict__ ol,
                           const float* __restrict__ cntp) {
    int u = blockIdx.x * blockDim.x + threadIdx.x;
    if (u >= NND * 32) return;
    int row = u >> 5, seg = u & 31;
    const float4* s = (const float4*)(x + (size_t)row * 256 + seg * 8);
    float4 a = s[0], b = s[1];
    float v[8] = {a.x, a.y, a.z, a.w, b.x, b.y, b.z, b.w};
    if (cntp) {
        float sc = 1.f / fmaxf(cntp[row], 1.f);
        #pragma unroll
        for (int t = 0; t < 8; t++) v[t] *= sc;
    }
    uint4 hp, lp;
    uint32_t* hq = (uint32_t*)&hp; uint32_t* lq = (uint32_t*)&lp;
    #pragma unroll
    for (int j = 0; j < 4; j++) {
        float va = v[2*j], vb = v[2*j+1];
        __nv_bfloat16 ha = __float2bfloat16(va), hb = __float2bfloat16(vb);
        hq[j] = (uint32_t)__bfloat16_as_ushort(ha)
              | ((uint32_t)__bfloat16_as_ushort(hb) << 16);
        lq[j] = pack2(va - __bfloat162float(ha), vb - __bfloat162float(hb));
    }
    *(uint4*)(oh + (size_t)row * 256 + seg * 8) = hp;
    *(uint4*)(ol + (size_t)row * 256 + seg * 8) = lp;
}

// ---------------------------------------------------------------------------
// Split-bf16 GEMM, pre-split A/B in gmem, cp.async double-buffered.
// CTA tile 128x128, 8 warps (4m x 2n), K chunk 64, 2-deep pipeline (128KB smem).
// gin: optional row gather for A; gout: optional row scatter for output;
// nrowp: optional device row count (compact passes) — CTAs past count exit.
// Output: fp32 (outf) and/or split bf16 (outh/outl).
__global__ __launch_bounds__(256, 1) void gemm_bf16(
    const __nv_bfloat16* __restrict__ Ah, const __nv_bfloat16* __restrict__ Al,
    const __nv_bfloat16* __restrict__ Bh, const __nv_bfloat16* __restrict__ Bl,
    const float* __restrict__ bias, int K, int N, int act,
    float* __restrict__ outf,
    __nv_bfloat16* __restrict__ outh, __nv_bfloat16* __restrict__ outl,
    const int* __restrict__ gin, const int* __restrict__ gout,
    const int* __restrict__ nrowp)
{
    extern __shared__ char sm[];
    const uint32_t smb = smem_u32_of(sm);
    const int tid = threadIdx.x, lane = tid & 31, warp = tid >> 5;
    const int warp_m = warp & 3, warp_n = warp >> 2;
    const int r0 = blockIdx.x * 128;
    const int c0 = blockIdx.y * 128;

    const int nrow = nrowp ? __ldg(nrowp) : NND;
    if (r0 >= nrow) return;

    int* sidx_in  = (int*)(sm + 131072);
    int* sidx_out = (int*)(sm + 131584);
    for (int i = tid; i < 128; i += 256) {
        int gr = r0 + i;
        bool ok = gr < nrow;
        sidx_in[i]  = ok ? (gin  ? __ldg(gin  + gr) : gr) : -1;
        sidx_out[i] = ok ? (gout ? __ldg(gout + gr) : gr) : -1;
    }
    __syncthreads();

    float c[2][8][4];
    #pragma unroll
    for (int i = 0; i < 2; i++)
        #pragma unroll
        for (int j = 0; j < 8; j++)
            #pragma unroll
            for (int k = 0; k < 4; k++) c[i][j][k] = 0.f;

    auto stage = [&](int ch, int buf) {
        uint32_t base = smb + (uint32_t)buf * 65536u;
        #pragma unroll
        for (int p = 0; p < 2; p++) {
            const __nv_bfloat16* Asrc = p ? Al : Ah;
            uint32_t abase = base + (p ? 16384u : 0u);
            #pragma unroll
            for (int it = 0; it < 4; it++) {
                int u = tid + it * 256, row = u >> 3, seg = u & 7;
                int grow = sidx_in[row];
                uint32_t sz = (grow >= 0) ? 16u : 0u;
                const void* src = Asrc + (size_t)(grow >= 0 ? grow : 0) * K
                                + ch * 64 + seg * 8;
                uint32_t dst = abase + (uint32_t)row * 128
                             + ((uint32_t)(seg ^ (row & 7)) << 4);
                CP_ASYNC16(dst, src, sz);
            }
        }
        #pragma unroll
        for (int p = 0; p < 2; p++) {
            const __nv_bfloat16* Bsrc = p ? Bl : Bh;
            uint32_t bbase = base + (p ? 49152u : 32768u);
            #pragma unroll
            for (int it = 0; it < 4; it++) {
                int u = tid + it * 256, row = u >> 3, seg = u & 7;
                const void* src = Bsrc + (size_t)(c0 + row) * K + ch * 64 + seg * 8;
                uint32_t dst = bbase + (uint32_t)row * 128
                             + ((uint32_t)(seg ^ (row & 7)) << 4);
                CP_ASYNC16(dst, src, 16u);
            }
        }
        CP_COMMIT();
    };

    auto mma_chunk = [&](int buf) {
        uint32_t base = smb + (uint32_t)buf * 65536u;
        const uint32_t AH = base, AL = base + 16384u, BH = base + 32768u,
                       BL = base + 49152u;
        #pragma unroll
        for (int ks = 0; ks < 4; ks++) {
            uint32_t ah[2][4], al[2][4];
            #pragma unroll
            for (int mt = 0; mt < 2; mt++) {
                int lr = warp_m * 32 + mt * 16 + (lane & 15);
                int seg = 2 * ks + (lane >> 4);
                uint32_t off = (uint32_t)lr * 128 + ((uint32_t)(seg ^ (lr & 7)) << 4);
                LDSM4(ah[mt], AH + off);
                LDSM4(al[mt], AL + off);
            }
            #pragma unroll
            for (int nq = 0; nq < 4; nq++) {
                int lrb = warp_n * 64 + nq * 16 + (lane & 7) + ((lane >> 4) << 3);
                int segb = 2 * ks + ((lane >> 3) & 1);
                uint32_t offb = (uint32_t)lrb * 128 + ((uint32_t)(segb ^ (lrb & 7)) << 4);
                uint32_t bh[4], bl[4];
                LDSM4(bh, BH + offb);
                LDSM4(bl, BL + offb);
                #pragma unroll
                for (int mt = 0; mt < 2; mt++) {
                    #pragma unroll
                    for (int sub = 0; sub < 2; sub++) {
                        float* d = c[mt][nq * 2 + sub];
                        mma16816(d, ah[mt], bh + sub * 2);
                        mma16816(d, ah[mt], bl + sub * 2);
                        mma16816(d, al[mt], bh + sub * 2);
                    }
                }
            }
        }
    };

    const int nch = K >> 6;
    stage(0, 0);
    for (int ch = 0; ch < nch; ch++) {
        int cur = ch & 1;
        if (ch + 1 < nch) { stage(ch + 1, cur ^ 1); CP_WAIT1(); }
        else             { CP_WAIT0(); }
        __syncthreads();
        mma_chunk(cur);
        __syncthreads();
    }

    // ---- epilogue: bias + activation; fp32 and/or split-bf16 stores ----
    #pragma unroll
    for (int mt = 0; mt < 2; mt++) {
        #pragma unroll
        for (int q = 0; q < 8; q++) {
            int col = c0 + warp_n * 64 + q * 8 + (lane & 3) * 2;
            float2 bv = *(const float2*)(bias + col);
            #pragma unroll
            for (int half = 0; half < 2; half++) {
                int lr = warp_m * 32 + mt * 16 + (lane >> 2) + half * 8;
                int orow = sidx_out[lr];
                if (orow >= 0) {
                    float v0 = c[mt][q][half * 2 + 0] + bv.x;
                    float v1 = c[mt][q][half * 2 + 1] + bv.y;
                    if (act == 1) {
                        v0 = (v0 >= 0.f) ? v0 : 0.01f * v0;
                        v1 = (v1 >= 0.f) ? v1 : 0.01f * v1;
                    } else if (act == 2) {
                        v0 = fmaxf(v0, 0.f);
                        v1 = fmaxf(v1, 0.f);
                    }
                    if (outf)
                        *(float2*)(outf + (size_t)orow * N + col) = make_float2(v0, v1);
                    if (outh) {
                        __nv_bfloat16 h0 = __float2bfloat16(v0);
                        __nv_bfloat16 h1 = __float2bfloat16(v1);
                        uint32_t hp = (uint32_t)__bfloat16_as_ushort(h0)
                                    | ((uint32_t)__bfloat16_as_ushort(h1) << 16);
                        uint32_t lp = pack2(v0 - __bfloat162float(h0),
                                            v1 - __bfloat162float(h1));
                        *(uint32_t*)(outh + (size_t)orow * N + col) = hp;
                        *(uint32_t*)(outl + (size_t)orow * N + col) = lp;
                    }
                }
            }
        }
    }
}

// ---------------------------------------------------------------------------
// Edge scatter: warp per edge; msg = (r==1) ? tinv[src] : h[src]
__global__ __launch_bounds__(256) void scatter_kernel(
    const float* __restrict__ h,
    const int* __restrict__ src, const int* __restrict__ dst,
    const int* __restrict__ r)
{
    int wid = (blockIdx.x * 256 + threadIdx.x) >> 5;
    int lane = threadIdx.x & 31;
    if (wid >= EE) return;
    int s = __ldg(src + wid);
    int d = __ldg(dst + wid);
    int rr = __ldg(r + wid);
    const float4* srow = (const float4*)((rr == 1 ? g_tinv : h) + (size_t)s * 256);
    float4* drow = (float4*)(g_sums + (size_t)d * 256);
    #pragma unroll
    for (int j = 0; j < 2; j++) {
        float4 v = __ldg(srow + lane + 32 * j);
        float4* p = drow + lane + 32 * j;
        asm volatile("red.global.add.v4.f32 [%0], {%1,%2,%3,%4};"
                     :: "l"(p), "f"(v.x), "f"(v.y), "f"(v.z), "f"(v.w) : "memory");
    }
    if (lane == 0) atomicAdd(&g_cnt[d], 1.0f);
}

// ---------------------------------------------------------------------------
extern "C" void kernel_launch(void* const* d_in, const int* in_sizes, int n_in,
                              void* d_out, int out_size)
{
    const float* h   = (const float*)d_in[0];
    const int*   src = (const int*)  d_in[1];
    const int*   dst = (const int*)  d_in[2];
    const int*   r   = (const int*)  d_in[3];
    const int*   inv = (const int*)  d_in[4];
    const float* iW1 = (const float*)d_in[5];
    const float* ib1 = (const float*)d_in[6];
    const float* iW2 = (const float*)d_in[7];
    const float* ib2 = (const float*)d_in[8];
    const float* iW3 = (const float*)d_in[9];
    const float* ib3 = (const float*)d_in[10];
    const float* aW1 = (const float*)d_in[11];
    const float* ab1 = (const float*)d_in[12];
    const float* aW2 = (const float*)d_in[13];
    const float* ab2 = (const float*)d_in[14];
    const float* aW3 = (const float*)d_in[15];
    const float* ab3 = (const float*)d_in[16];
    const float* pW1 = (const float*)d_in[17];
    const float* pb1 = (const float*)d_in[18];
    const float* pW2 = (const float*)d_in[19];
    const float* pb2 = (const float*)d_in[20];
    float* out = (float*)d_out;

    float *tinv, *sums, *cnt;
    int *invidx, *ninv;
    cudaGetSymbolAddress((void**)&tinv, g_tinv);
    cudaGetSymbolAddress((void**)&sums, g_sums);
    cudaGetSymbolAddress((void**)&cnt,  g_cnt);
    cudaGetSymbolAddress((void**)&invidx, g_invidx);
    cudaGetSymbolAddress((void**)&ninv, g_ninv);

    __nv_bfloat16 *xh,*xl,*sh,*sl,*t1h,*t1l,*t2h,*t2l;
    cudaGetSymbolAddress((void**)&xh, g_xh);   cudaGetSymbolAddress((void**)&xl, g_xl);
    cudaGetSymbolAddress((void**)&sh, g_sh);   cudaGetSymbolAddress((void**)&sl, g_sl);
    cudaGetSymbolAddress((void**)&t1h, g_t1h); cudaGetSymbolAddress((void**)&t1l, g_t1l);
    cudaGetSymbolAddress((void**)&t2h, g_t2h); cudaGetSymbolAddress((void**)&t2l, g_t2l);

    __nv_bfloat16 *iW1h,*iW1l,*iW2h,*iW2l,*iW3h,*iW3l;
    __nv_bfloat16 *aW1h,*aW1l,*aW2h,*aW2l,*aW3h,*aW3l;
    __nv_bfloat16 *pW1h,*pW1l,*pW2h,*pW2l;
    cudaGetSymbolAddress((void**)&iW1h, g_iW1h); cudaGetSymbolAddress((void**)&iW1l, g_iW1l);
    cudaGetSymbolAddress((void**)&iW2h, g_iW2h); cudaGetSymbolAddress((void**)&iW2l, g_iW2l);
    cudaGetSymbolAddress((void**)&iW3h, g_iW3h); cudaGetSymbolAddress((void**)&iW3l, g_iW3l);
    cudaGetSymbolAddress((void**)&aW1h, g_aW1h); cudaGetSymbolAddress((void**)&aW1l, g_aW1l);
    cudaGetSymbolAddress((void**)&aW2h, g_aW2h); cudaGetSymbolAddress((void**)&aW2l, g_aW2l);
    cudaGetSymbolAddress((void**)&aW3h, g_aW3h); cudaGetSymbolAddress((void**)&aW3l, g_aW3l);
    cudaGetSymbolAddress((void**)&pW1h, g_pW1h); cudaGetSymbolAddress((void**)&pW1l, g_pW1l);
    cudaGetSymbolAddress((void**)&pW2h, g_pW2h); cudaGetSymbolAddress((void**)&pW2l, g_pW2l);

    const int SMEM = 132096;   // 2x64KB double buffer + idx caches
    cudaFuncSetAttribute(gemm_bf16, cudaFuncAttributeMaxDynamicSharedMemorySize, SMEM);

    const int NB = (NND + 127) / 128;   // 391
    dim3 g128(NB, 1), g256(NB, 2);

    zero_kernel<<<512, 256>>>();
    prep_all<<<1152, 256>>>(iW1, iW2, iW3, aW1, aW2, aW3, pW1, pW2);
    count_inv<<<196, 256>>>(inv);
    conv_split<<<6250, 256>>>(h, xh, xl, nullptr);

    // tinv = MLP_inv(h)  (fp32 out for scatter)
    gemm_bf16<<<g128, 256, SMEM>>>(xh, xl, iW1h, iW1l, ib1, 256, 128, 1, 0, t1h, t1l, 0, 0, 0);
    gemm_bf16<<<g128, 256, SMEM>>>(t1h, t1l, iW2h, iW2l, ib2, 128, 128, 1, 0, t2h, t2l, 0, 0, 0);
    gemm_bf16<<<g256, 256, SMEM>>>(t2h, t2l, iW3h, iW3l, ib3, 128, 256, 0, tinv, 0, 0, 0, 0, 0);
    // edge scatter-mean
    scatter_kernel<<<(EE * 32 + 255) / 256, 256>>>(h, src, dst, r);
    conv_split<<<6250, 256>>>(sums, sh, sl, cnt);
    // res = MLP_and(neigh)  -> write straight into res2 (xh/xl)
    gemm_bf16<<<g128, 256, SMEM>>>(sh, sl, aW1h, aW1l, ab1, 256, 128, 1, 0, t1h, t1l, 0, 0, 0);
    gemm_bf16<<<g128, 256, SMEM>>>(t1h, t1l, aW2h, aW2l, ab2, 128, 128, 1, 0, t2h, t2l, 0, 0, 0);
    gemm_bf16<<<g256, 256, SMEM>>>(t2h, t2l, aW3h, aW3l, ab3, 128, 256, 0, 0, xh, xl, 0, 0, 0);
    // res2[invidx] = MLP_inv(res[invidx])  (compact ~25k rows)
    gemm_bf16<<<g128, 256, SMEM>>>(xh, xl, iW1h, iW1l, ib1, 256, 128, 1, 0, t1h, t1l, invidx, 0, ninv);
    gemm_bf16<<<g128, 256, SMEM>>>(t1h, t1l, iW2h, iW2l, ib2, 128, 128, 1, 0, t2h, t2l, 0, 0, ninv);
    gemm_bf16<<<g256, 256, SMEM>>>(t2h, t2l, iW3h, iW3l, ib3, 128, 256, 0, 0, xh, xl, 0, invidx, ninv);
    // proj head (hidden reuses sh/sl)
    gemm_bf16<<<g256, 256, SMEM>>>(xh, xl, pW1h, pW1l, pb1, 256, 256, 2, 0, sh, sl, 0, 0, 0);
    gemm_bf16<<<g256, 256, SMEM>>>(sh, sl, pW2h, pW2l, pb2, 256, 256, 0, out, 0, 0, 0, 0, 0);
}

// round 8
// speedup vs baseline: 4.8644x; 1.1082x over previous
#include <cuda_runtime.h>
#include <cuda_bf16.h>
#include <cstdint>

#define NND 50000
#define NP  50048              // padded to 391*128
#define EE  800000

// ---------------------------------------------------------------------------
// Scratch (device globals; no allocations anywhere)
__device__ float g_tinv[(size_t)NP * 256];   // fp32 MLP_inv(h) (gather msg)
__device__ int   g_hist[NND];
__device__ int   g_rowptr[NND + 1];
__device__ int   g_cursor[NND];
__device__ uint32_t g_edges[EE];             // src | (r==1)<<31, CSR order by dst
__device__ int   g_invidx[NND];
__device__ int   g_ninv;

// split-bf16 activation buffers
__device__ __align__(16) __nv_bfloat16 g_xh[(size_t)NP * 256], g_xl[(size_t)NP * 256]; // h split -> res2 split
__device__ __align__(16) __nv_bfloat16 g_sh[(size_t)NP * 256], g_sl[(size_t)NP * 256]; // neigh split -> proj hidden
__device__ __align__(16) __nv_bfloat16 g_t1h[(size_t)NP * 128], g_t1l[(size_t)NP * 128];
__device__ __align__(16) __nv_bfloat16 g_t2h[(size_t)NP * 128], g_t2l[(size_t)NP * 128];

// Pre-transposed + split weights: Wt[n][k] = W[k][n], hi/lo bf16
__device__ __align__(16) __nv_bfloat16 g_iW1h[128*256], g_iW1l[128*256];
__device__ __align__(16) __nv_bfloat16 g_iW2h[128*128], g_iW2l[128*128];
__device__ __align__(16) __nv_bfloat16 g_iW3h[256*128], g_iW3l[256*128];
__device__ __align__(16) __nv_bfloat16 g_aW1h[128*256], g_aW1l[128*256];
__device__ __align__(16) __nv_bfloat16 g_aW2h[128*128], g_aW2l[128*128];
__device__ __align__(16) __nv_bfloat16 g_aW3h[256*128], g_aW3l[256*128];
__device__ __align__(16) __nv_bfloat16 g_pW1h[256*256], g_pW1l[256*256];
__device__ __align__(16) __nv_bfloat16 g_pW2h[256*256], g_pW2l[256*256];

// ---------------------------------------------------------------------------
__device__ __forceinline__ uint32_t smem_u32_of(const void* p) {
    uint32_t a;
    asm("{ .reg .u64 t; cvta.to.shared.u64 t, %1; cvt.u32.u64 %0, t; }"
        : "=r"(a) : "l"(p));
    return a;
}
#define LDSM4(r, addr)                                                         \
    asm volatile("ldmatrix.sync.aligned.m8n8.x4.shared.b16 {%0,%1,%2,%3}, [%4];" \
        : "=r"((r)[0]), "=r"((r)[1]), "=r"((r)[2]), "=r"((r)[3]) : "r"(addr))
#define CP_ASYNC16(dst, src, sz)                                               \
    asm volatile("cp.async.cg.shared.global [%0], [%1], 16, %2;"               \
        :: "r"(dst), "l"(src), "r"(sz) : "memory")
#define CP_COMMIT() asm volatile("cp.async.commit_group;" ::: "memory")
#define CP_WAIT1()  asm volatile("cp.async.wait_group 1;" ::: "memory")
#define CP_WAIT0()  asm volatile("cp.async.wait_group 0;" ::: "memory")

__device__ __forceinline__ void mma16816(float* d, const uint32_t* a,
                                         const uint32_t* b) {
    asm volatile("mma.sync.aligned.m16n8k16.row.col.f32.bf16.bf16.f32 "
        "{%0,%1,%2,%3}, {%4,%5,%6,%7}, {%8,%9}, {%0,%1,%2,%3};"
        : "+f"(d[0]), "+f"(d[1]), "+f"(d[2]), "+f"(d[3])
        : "r"(a[0]), "r"(a[1]), "r"(a[2]), "r"(a[3]), "r"(b[0]), "r"(b[1]));
}
__device__ __forceinline__ uint32_t pack2(float a, float b) {
    __nv_bfloat16 x = __float2bfloat16(a), y = __float2bfloat16(b);
    return (uint32_t)__bfloat16_as_ushort(x) | ((uint32_t)__bfloat16_as_ushort(y) << 16);
}

// ---------------------------------------------------------------------------
__global__ void zero_kernel() {
    int i = blockIdx.x * blockDim.x + threadIdx.x;
    if (i < NND) g_hist[i] = 0;
    if (i == 0) g_ninv = 0;
}

__global__ void count_inv(const int* __restrict__ inv) {
    int i = blockIdx.x * blockDim.x + threadIdx.x;
    if (i < NND && inv[i] == 1) {
        int p = atomicAdd(&g_ninv, 1);
        g_invidx[p] = i;
    }
}

// ---- CSR build ----
__global__ void hist_kernel(const int* __restrict__ dst) {
    int e = blockIdx.x * blockDim.x + threadIdx.x;
    if (e < EE) atomicAdd(&g_hist[__ldg(dst + e)], 1);
}

// single-block exclusive scan of g_hist -> g_rowptr/g_cursor
__global__ __launch_bounds__(1024, 1) void scan_kernel() {
    __shared__ int warp_sums[32];
    __shared__ int s_carry;
    int tid = threadIdx.x, lane = tid & 31, w = tid >> 5;
    if (tid == 0) s_carry = 0;
    __syncthreads();
    for (int base = 0; base < NND; base += 1024) {
        int i = base + tid;
        int v = (i < NND) ? g_hist[i] : 0;
        int x = v;
        #pragma unroll
        for (int o = 1; o < 32; o <<= 1) {
            int t = __shfl_up_sync(0xFFFFFFFFu, x, o);
            if (lane >= o) x += t;
        }
        if (lane == 31) warp_sums[w] = x;
        __syncthreads();
        if (w == 0) {
            int y = warp_sums[lane];
            #pragma unroll
            for (int o = 1; o < 32; o <<= 1) {
                int t = __shfl_up_sync(0xFFFFFFFFu, y, o);
                if (lane >= o) y += t;
            }
            warp_sums[lane] = y;
        }
        __syncthreads();
        int excl = s_carry + x - v + (w > 0 ? warp_sums[w - 1] : 0);
        if (i < NND) { g_rowptr[i] = excl; g_cursor[i] = excl; }
        __syncthreads();
        if (tid == 0) s_carry += warp_sums[31];
        __syncthreads();
    }
    if (tid == 0) g_rowptr[NND] = s_carry;
}

__global__ void fill_kernel(const int* __restrict__ src,
                            const int* __restrict__ dst,
                            const int* __restrict__ r) {
    int e = blockIdx.x * blockDim.x + threadIdx.x;
    if (e >= EE) return;
    int d = __ldg(dst + e);
    int pos = atomicAdd(&g_cursor[d], 1);
    g_edges[pos] = (uint32_t)__ldg(src + e)
                 | ((uint32_t)(__ldg(r + e) == 1) << 31);
}

// ---- gather-mean: warp per node; emits split bf16 directly ----
__global__ __launch_bounds__(256) void gather_kernel(
    const float* __restrict__ h,
    __nv_bfloat16* __restrict__ oh, __nv_bfloat16* __restrict__ ol)
{
    int wid = (blockIdx.x * 256 + threadIdx.x) >> 5;
    int lane = threadIdx.x & 31;
    if (wid >= NND) return;
    int beg = __ldg(&g_rowptr[wid]), end = __ldg(&g_rowptr[wid + 1]);
    float4 A = make_float4(0.f, 0.f, 0.f, 0.f);
    float4 B = make_float4(0.f, 0.f, 0.f, 0.f);
    for (int e = beg; e < end; e++) {
        uint32_t p = __ldg(&g_edges[e]);
        const float4* row = (const float4*)(((p >> 31) ? g_tinv : h)
                           + (size_t)(p & 0x7FFFFFFFu) * 256);
        float4 x = __ldg(row + lane * 2);
        float4 y = __ldg(row + lane * 2 + 1);
        A.x += x.x; A.y += x.y; A.z += x.z; A.w += x.w;
        B.x += y.x; B.y += y.y; B.z += y.z; B.w += y.w;
    }
    float sc = 1.f / fmaxf((float)(end - beg), 1.f);
    float v[8] = {A.x * sc, A.y * sc, A.z * sc, A.w * sc,
                  B.x * sc, B.y * sc, B.z * sc, B.w * sc};
    uint4 hp, lp;
    uint32_t* hq = (uint32_t*)&hp; uint32_t* lq = (uint32_t*)&lp;
    #pragma unroll
    for (int j = 0; j < 4; j++) {
        float va = v[2*j], vb = v[2*j+1];
        __nv_bfloat16 ha = __float2bfloat16(va), hb = __float2bfloat16(vb);
        hq[j] = (uint32_t)__bfloat16_as_ushort(ha)
              | ((uint32_t)__bfloat16_as_ushort(hb) << 16);
        lq[j] = pack2(va - __bfloat162float(ha), vb - __bfloat162float(hb));
    }
    *(uint4*)(oh + (size_t)wid * 256 + lane * 8) = hp;
    *(uint4*)(ol + (size_t)wid * 256 + lane * 8) = lp;
}

// All 8 weight transposes + splits in one launch
__global__ void prep_all(const float* W0, const float* W1, const float* W2,
                         const float* W3, const float* W4, const float* W5,
                         const float* W6, const float* W7) {
    int i = blockIdx.x * blockDim.x + threadIdx.x;
    if (i >= 294912) return;
    const int cum[9]  = {0, 32768, 49152, 81920, 114688, 131072, 163840, 229376, 294912};
    const int Ks[8]   = {256, 128, 128, 256, 128, 128, 256, 256};
    const int Ns[8]   = {128, 128, 256, 128, 128, 256, 256, 256};
    int m = 0;
    #pragma unroll
    for (int t = 1; t < 8; t++) if (i >= cum[t]) m = t;
    int j = i - cum[m], K = Ks[m], N = Ns[m];
    int n = j / K, k = j % K;
    const float* W; __nv_bfloat16 *Th, *Tl;
    switch (m) {
        case 0: W = W0; Th = g_iW1h; Tl = g_iW1l; break;
        case 1: W = W1; Th = g_iW2h; Tl = g_iW2l; break;
        case 2: W = W2; Th = g_iW3h; Tl = g_iW3l; break;
        case 3: W = W3; Th = g_aW1h; Tl = g_aW1l; break;
        case 4: W = W4; Th = g_aW2h; Tl = g_aW2l; break;
        case 5: W = W5; Th = g_aW3h; Tl = g_aW3l; break;
        case 6: W = W6; Th = g_pW1h; Tl = g_pW1l; break;
        default: W = W7; Th = g_pW2h; Tl = g_pW2l; break;
    }
    float v = W[(size_t)k * N + n];
    __nv_bfloat16 h = __float2bfloat16(v);
    Th[j] = h;
    Tl[j] = __float2bfloat16(v - __bfloat162float(h));
}

// fp32 [NND x 256] -> split bf16
__global__ void conv_split(const float* __restrict__ x,
                           __nv_bfloat16* __restrict__ oh,
                           __nv_bfloat16* __restrict__ ol) {
    int u = blockIdx.x * blockDim.x + threadIdx.x;
    if (u >= NND * 32) return;
    int row = u >> 5, seg = u & 31;
    const float4* s = (const float4*)(x + (size_t)row * 256 + seg * 8);
    float4 a = s[0], b = s[1];
    float v[8] = {a.x, a.y, a.z, a.w, b.x, b.y, b.z, b.w};
    uint4 hp, lp;
    uint32_t* hq = (uint32_t*)&hp; uint32_t* lq = (uint32_t*)&lp;
    #pragma unroll
    for (int j = 0; j < 4; j++) {
        float va = v[2*j], vb = v[2*j+1];
        __nv_bfloat16 ha = __float2bfloat16(va), hb = __float2bfloat16(vb);
        hq[j] = (uint32_t)__bfloat16_as_ushort(ha)
              | ((uint32_t)__bfloat16_as_ushort(hb) << 16);
        lq[j] = pack2(va - __bfloat162float(ha), vb - __bfloat162float(hb));
    }
    *(uint4*)(oh + (size_t)row * 256 + seg * 8) = hp;
    *(uint4*)(ol + (size_t)row * 256 + seg * 8) = lp;
}

// ---------------------------------------------------------------------------
// Split-bf16 GEMM, pre-split A/B in gmem, cp.async double-buffered.
// CTA tile 128x128, 8 warps (4m x 2n), K chunk 64, 2-deep pipeline (128KB smem).
__global__ __launch_bounds__(256, 1) void gemm_bf16(
    const __nv_bfloat16* __restrict__ Ah, const __nv_bfloat16* __restrict__ Al,
    const __nv_bfloat16* __restrict__ Bh, const __nv_bfloat16* __restrict__ Bl,
    const float* __restrict__ bias, int K, int N, int act,
    float* __restrict__ outf,
    __nv_bfloat16* __restrict__ outh, __nv_bfloat16* __restrict__ outl,
    const int* __restrict__ gin, const int* __restrict__ gout,
    const int* __restrict__ nrowp)
{
    extern __shared__ char sm[];
    const uint32_t smb = smem_u32_of(sm);
    const int tid = threadIdx.x, lane = tid & 31, warp = tid >> 5;
    const int warp_m = warp & 3, warp_n = warp >> 2;
    const int r0 = blockIdx.x * 128;
    const int c0 = blockIdx.y * 128;

    const int nrow = nrowp ? __ldg(nrowp) : NND;
    if (r0 >= nrow) return;

    int* sidx_in  = (int*)(sm + 131072);
    int* sidx_out = (int*)(sm + 131584);
    for (int i = tid; i < 128; i += 256) {
        int gr = r0 + i;
        bool ok = gr < nrow;
        sidx_in[i]  = ok ? (gin  ? __ldg(gin  + gr) : gr) : -1;
        sidx_out[i] = ok ? (gout ? __ldg(gout + gr) : gr) : -1;
    }
    __syncthreads();

    float c[2][8][4];
    #pragma unroll
    for (int i = 0; i < 2; i++)
        #pragma unroll
        for (int j = 0; j < 8; j++)
            #pragma unroll
            for (int k = 0; k < 4; k++) c[i][j][k] = 0.f;

    auto stage = [&](int ch, int buf) {
        uint32_t base = smb + (uint32_t)buf * 65536u;
        #pragma unroll
        for (int p = 0; p < 2; p++) {
            const __nv_bfloat16* Asrc = p ? Al : Ah;
            uint32_t abase = base + (p ? 16384u : 0u);
            #pragma unroll
            for (int it = 0; it < 4; it++) {
                int u = tid + it * 256, row = u >> 3, seg = u & 7;
                int grow = sidx_in[row];
                uint32_t sz = (grow >= 0) ? 16u : 0u;
                const void* src = Asrc + (size_t)(grow >= 0 ? grow : 0) * K
                                + ch * 64 + seg * 8;
                uint32_t dst = abase + (uint32_t)row * 128
                             + ((uint32_t)(seg ^ (row & 7)) << 4);
                CP_ASYNC16(dst, src, sz);
            }
        }
        #pragma unroll
        for (int p = 0; p < 2; p++) {
            const __nv_bfloat16* Bsrc = p ? Bl : Bh;
            uint32_t bbase = base + (p ? 49152u : 32768u);
            #pragma unroll
            for (int it = 0; it < 4; it++) {
                int u = tid + it * 256, row = u >> 3, seg = u & 7;
                const void* src = Bsrc + (size_t)(c0 + row) * K + ch * 64 + seg * 8;
                uint32_t dst = bbase + (uint32_t)row * 128
                             + ((uint32_t)(seg ^ (row & 7)) << 4);
                CP_ASYNC16(dst, src, 16u);
            }
        }
        CP_COMMIT();
    };

    auto mma_chunk = [&](int buf) {
        uint32_t base = smb + (uint32_t)buf * 65536u;
        const uint32_t AH = base, AL = base + 16384u, BH = base + 32768u,
                       BL = base + 49152u;
        #pragma unroll
        for (int ks = 0; ks < 4; ks++) {
            uint32_t ah[2][4], al[2][4];
            #pragma unroll
            for (int mt = 0; mt < 2; mt++) {
                int lr = warp_m * 32 + mt * 16 + (lane & 15);
                int seg = 2 * ks + (lane >> 4);
                uint32_t off = (uint32_t)lr * 128 + ((uint32_t)(seg ^ (lr & 7)) << 4);
                LDSM4(ah[mt], AH + off);
                LDSM4(al[mt], AL + off);
            }
            #pragma unroll
            for (int nq = 0; nq < 4; nq++) {
                int lrb = warp_n * 64 + nq * 16 + (lane & 7) + ((lane >> 4) << 3);
                int segb = 2 * ks + ((lane >> 3) & 1);
                uint32_t offb = (uint32_t)lrb * 128 + ((uint32_t)(segb ^ (lrb & 7)) << 4);
                uint32_t bh[4], bl[4];
                LDSM4(bh, BH + offb);
                LDSM4(bl, BL + offb);
                #pragma unroll
                for (int mt = 0; mt < 2; mt++) {
                    #pragma unroll
                    for (int sub = 0; sub < 2; sub++) {
                        float* d = c[mt][nq * 2 + sub];
                        mma16816(d, ah[mt], bh + sub * 2);
                        mma16816(d, ah[mt], bl + sub * 2);
                        mma16816(d, al[mt], bh + sub * 2);
                    }
                }
            }
        }
    };

    const int nch = K >> 6;
    stage(0, 0);
    for (int ch = 0; ch < nch; ch++) {
        int cur = ch & 1;
        if (ch + 1 < nch) { stage(ch + 1, cur ^ 1); CP_WAIT1(); }
        else             { CP_WAIT0(); }
        __syncthreads();
        mma_chunk(cur);
        __syncthreads();
    }

    // ---- epilogue: bias + activation; fp32 and/or split-bf16 stores ----
    #pragma unroll
    for (int mt = 0; mt < 2; mt++) {
        #pragma unroll
        for (int q = 0; q < 8; q++) {
            int col = c0 + warp_n * 64 + q * 8 + (lane & 3) * 2;
            float2 bv = *(const float2*)(bias + col);
            #pragma unroll
            for (int half = 0; half < 2; half++) {
                int lr = warp_m * 32 + mt * 16 + (lane >> 2) + half * 8;
                int orow = sidx_out[lr];
                if (orow >= 0) {
                    float v0 = c[mt][q][half * 2 + 0] + bv.x;
                    float v1 = c[mt][q][half * 2 + 1] + bv.y;
                    if (act == 1) {
                        v0 = (v0 >= 0.f) ? v0 : 0.01f * v0;
                        v1 = (v1 >= 0.f) ? v1 : 0.01f * v1;
                    } else if (act == 2) {
                        v0 = fmaxf(v0, 0.f);
                        v1 = fmaxf(v1, 0.f);
                    }
                    if (outf)
                        *(float2*)(outf + (size_t)orow * N + col) = make_float2(v0, v1);
                    if (outh) {
                        __nv_bfloat16 h0 = __float2bfloat16(v0);
                        __nv_bfloat16 h1 = __float2bfloat16(v1);
                        uint32_t hp = (uint32_t)__bfloat16_as_ushort(h0)
                                    | ((uint32_t)__bfloat16_as_ushort(h1) << 16);
                        uint32_t lp = pack2(v0 - __bfloat162float(h0),
                                            v1 - __bfloat162float(h1));
                        *(uint32_t*)(outh + (size_t)orow * N + col) = hp;
                        *(uint32_t*)(outl + (size_t)orow * N + col) = lp;
                    }
                }
            }
        }
    }
}

// ---------------------------------------------------------------------------
extern "C" void kernel_launch(void* const* d_in, const int* in_sizes, int n_in,
                              void* d_out, int out_size)
{
    const float* h   = (const float*)d_in[0];
    const int*   src = (const int*)  d_in[1];
    const int*   dst = (const int*)  d_in[2];
    const int*   r   = (const int*)  d_in[3];
    const int*   inv = (const int*)  d_in[4];
    const float* iW1 = (const float*)d_in[5];
    const float* ib1 = (const float*)d_in[6];
    const float* iW2 = (const float*)d_in[7];
    const float* ib2 = (const float*)d_in[8];
    const float* iW3 = (const float*)d_in[9];
    const float* ib3 = (const float*)d_in[10];
    const float* aW1 = (const float*)d_in[11];
    const float* ab1 = (const float*)d_in[12];
    const float* aW2 = (const float*)d_in[13];
    const float* ab2 = (const float*)d_in[14];
    const float* aW3 = (const float*)d_in[15];
    const float* ab3 = (const float*)d_in[16];
    const float* pW1 = (const float*)d_in[17];
    const float* pb1 = (const float*)d_in[18];
    const float* pW2 = (const float*)d_in[19];
    const float* pb2 = (const float*)d_in[20];
    float* out = (float*)d_out;

    float *tinv;
    int *invidx, *ninv;
    cudaGetSymbolAddress((void**)&tinv, g_tinv);
    cudaGetSymbolAddress((void**)&invidx, g_invidx);
    cudaGetSymbolAddress((void**)&ninv, g_ninv);

    __nv_bfloat16 *xh,*xl,*sh,*sl,*t1h,*t1l,*t2h,*t2l;
    cudaGetSymbolAddress((void**)&xh, g_xh);   cudaGetSymbolAddress((void**)&xl, g_xl);
    cudaGetSymbolAddress((void**)&sh, g_sh);   cudaGetSymbolAddress((void**)&sl, g_sl);
    cudaGetSymbolAddress((void**)&t1h, g_t1h); cudaGetSymbolAddress((void**)&t1l, g_t1l);
    cudaGetSymbolAddress((void**)&t2h, g_t2h); cudaGetSymbolAddress((void**)&t2l, g_t2l);

    __nv_bfloat16 *iW1h,*iW1l,*iW2h,*iW2l,*iW3h,*iW3l;
    __nv_bfloat16 *aW1h,*aW1l,*aW2h,*aW2l,*aW3h,*aW3l;
    __nv_bfloat16 *pW1h,*pW1l,*pW2h,*pW2l;
    cudaGetSymbolAddress((void**)&iW1h, g_iW1h); cudaGetSymbolAddress((void**)&iW1l, g_iW1l);
    cudaGetSymbolAddress((void**)&iW2h, g_iW2h); cudaGetSymbolAddress((void**)&iW2l, g_iW2l);
    cudaGetSymbolAddress((void**)&iW3h, g_iW3h); cudaGetSymbolAddress((void**)&iW3l, g_iW3l);
    cudaGetSymbolAddress((void**)&aW1h, g_aW1h); cudaGetSymbolAddress((void**)&aW1l, g_aW1l);
    cudaGetSymbolAddress((void**)&aW2h, g_aW2h); cudaGetSymbolAddress((void**)&aW2l, g_aW2l);
    cudaGetSymbolAddress((void**)&aW3h, g_aW3h); cudaGetSymbolAddress((void**)&aW3l, g_aW3l);
    cudaGetSymbolAddress((void**)&pW1h, g_pW1h); cudaGetSymbolAddress((void**)&pW1l, g_pW1l);
    cudaGetSymbolAddress((void**)&pW2h, g_pW2h); cudaGetSymbolAddress((void**)&pW2l, g_pW2l);

    const int SMEM = 132096;   // 2x64KB double buffer + idx caches
    cudaFuncSetAttribute(gemm_bf16, cudaFuncAttributeMaxDynamicSharedMemorySize, SMEM);

    const int NB = (NND + 127) / 128;   // 391
    dim3 g128(NB, 1), g256(NB, 2);

    zero_kernel<<<196, 256>>>();
    prep_all<<<1152, 256>>>(iW1, iW2, iW3, aW1, aW2, aW3, pW1, pW2);
    count_inv<<<196, 256>>>(inv);
    conv_split<<<6250, 256>>>(h, xh, xl);
    // CSR build (hist -> scan -> fill)
    hist_kernel<<<(EE + 255) / 256, 256>>>(dst);
    scan_kernel<<<1, 1024>>>();
    fill_kernel<<<(EE + 255) / 256, 256>>>(src, dst, r);

    // tinv = MLP_inv(h)  (fp32 out for gather)
    gemm_bf16<<<g128, 256, SMEM>>>(xh, xl, iW1h, iW1l, ib1, 256, 128, 1, 0, t1h, t1l, 0, 0, 0);
    gemm_bf16<<<g128, 256, SMEM>>>(t1h, t1l, iW2h, iW2l, ib2, 128, 128, 1, 0, t2h, t2l, 0, 0, 0);
    gemm_bf16<<<g256, 256, SMEM>>>(t2h, t2l, iW3h, iW3l, ib3, 128, 256, 0, tinv, 0, 0, 0, 0, 0);
    // neigh mean via CSR gather -> split bf16 directly
    gather_kernel<<<6250, 256>>>(h, sh, sl);
    // res = MLP_and(neigh)  -> write straight into res2 (xh/xl)
    gemm_bf16<<<g128, 256, SMEM>>>(sh, sl, aW1h, aW1l, ab1, 256, 128, 1, 0, t1h, t1l, 0, 0, 0);
    gemm_bf16<<<g128, 256, SMEM>>>(t1h, t1l, aW2h, aW2l, ab2, 128, 128, 1, 0, t2h, t2l, 0, 0, 0);
    gemm_bf16<<<g256, 256, SMEM>>>(t2h, t2l, aW3h, aW3l, ab3, 128, 256, 0, 0, xh, xl, 0, 0, 0);
    // res2[invidx] = MLP_inv(res[invidx])  (compact ~25k rows)
    gemm_bf16<<<g128, 256, SMEM>>>(xh, xl, iW1h, iW1l, ib1, 256, 128, 1, 0, t1h, t1l, invidx, 0, ninv);
    gemm_bf16<<<g128, 256, SMEM>>>(t1h, t1l, iW2h, iW2l, ib2, 128, 128, 1, 0, t2h, t2l, 0, 0, ninv);
    gemm_bf16<<<g256, 256, SMEM>>>(t2h, t2l, iW3h, iW3l, ib3, 128, 256, 0, 0, xh, xl, 0, invidx, ninv);
    // proj head (hidden reuses sh/sl)
    gemm_bf16<<<g256, 256, SMEM>>>(xh, xl, pW1h, pW1l, pb1, 256, 256, 2, 0, sh, sl, 0, 0, 0);
    gemm_bf16<<<g256, 256, SMEM>>>(sh, sl, pW2h, pW2l, pb2, 256, 256, 0, out, 0, 0, 0, 0, 0);
}

// round 9
// speedup vs baseline: 5.3434x; 1.0985x over previous
#include <cuda_runtime.h>
#include <cuda_bf16.h>
#include <cstdint>

#define NND 50000
#define NP  50048              // padded to 391*128
#define EE  800000

// ---------------------------------------------------------------------------
// Scratch (device globals; no allocations anywhere)
__device__ float g_tinv[(size_t)NP * 256];   // fp32 MLP_inv(h) (gather msg)
__device__ int   g_hist[NND];
__device__ int   g_rowptr[NND + 1];
__device__ int   g_cursor[NND];
__device__ uint32_t g_edges[EE];             // src | (r==1)<<31, CSR order by dst
__device__ int   g_invidx[NND];
__device__ int   g_ninv;

// split-bf16 activation buffers
__device__ __align__(16) __nv_bfloat16 g_xh[(size_t)NP * 256], g_xl[(size_t)NP * 256];
__device__ __align__(16) __nv_bfloat16 g_sh[(size_t)NP * 256], g_sl[(size_t)NP * 256];

// Pre-transposed + split weights: Wt[n][k] = W[k][n], hi/lo bf16
__device__ __align__(16) __nv_bfloat16 g_iW1h[128*256], g_iW1l[128*256];
__device__ __align__(16) __nv_bfloat16 g_iW2h[128*128], g_iW2l[128*128];
__device__ __align__(16) __nv_bfloat16 g_iW3h[256*128], g_iW3l[256*128];
__device__ __align__(16) __nv_bfloat16 g_aW1h[128*256], g_aW1l[128*256];
__device__ __align__(16) __nv_bfloat16 g_aW2h[128*128], g_aW2l[128*128];
__device__ __align__(16) __nv_bfloat16 g_aW3h[256*128], g_aW3l[256*128];
__device__ __align__(16) __nv_bfloat16 g_pW1h[256*256], g_pW1l[256*256];
__device__ __align__(16) __nv_bfloat16 g_pW2h[256*256], g_pW2l[256*256];

// ---------------------------------------------------------------------------
__device__ __forceinline__ uint32_t smem_u32_of(const void* p) {
    uint32_t a;
    asm("{ .reg .u64 t; cvta.to.shared.u64 t, %1; cvt.u32.u64 %0, t; }"
        : "=r"(a) : "l"(p));
    return a;
}
#define LDSM4(r, addr)                                                         \
    asm volatile("ldmatrix.sync.aligned.m8n8.x4.shared.b16 {%0,%1,%2,%3}, [%4];" \
        : "=r"((r)[0]), "=r"((r)[1]), "=r"((r)[2]), "=r"((r)[3]) : "r"(addr))
#define CP_ASYNC16(dst, src, sz)                                               \
    asm volatile("cp.async.cg.shared.global [%0], [%1], 16, %2;"               \
        :: "r"(dst), "l"(src), "r"(sz) : "memory")
#define CP_COMMIT() asm volatile("cp.async.commit_group;" ::: "memory")
#define CP_WAIT1()  asm volatile("cp.async.wait_group 1;" ::: "memory")
#define CP_WAIT0()  asm volatile("cp.async.wait_group 0;" ::: "memory")

__device__ __forceinline__ void mma16816(float* d, const uint32_t* a,
                                         const uint32_t* b) {
    asm volatile("mma.sync.aligned.m16n8k16.row.col.f32.bf16.bf16.f32 "
        "{%0,%1,%2,%3}, {%4,%5,%6,%7}, {%8,%9}, {%0,%1,%2,%3};"
        : "+f"(d[0]), "+f"(d[1]), "+f"(d[2]), "+f"(d[3])
        : "r"(a[0]), "r"(a[1]), "r"(a[2]), "r"(a[3]), "r"(b[0]), "r"(b[1]));
}
__device__ __forceinline__ uint32_t pack2(float a, float b) {
    __nv_bfloat16 x = __float2bfloat16(a), y = __float2bfloat16(b);
    return (uint32_t)__bfloat16_as_ushort(x) | ((uint32_t)__bfloat16_as_ushort(y) << 16);
}

// ---------------------------------------------------------------------------
__global__ void zero_kernel() {
    int i = blockIdx.x * blockDim.x + threadIdx.x;
    if (i < NND) g_hist[i] = 0;
    if (i == 0) g_ninv = 0;
}

__global__ void count_inv(const int* __restrict__ inv) {
    int i = blockIdx.x * blockDim.x + threadIdx.x;
    if (i < NND && inv[i] == 1) {
        int p = atomicAdd(&g_ninv, 1);
        g_invidx[p] = i;
    }
}

// ---- CSR build ----
__global__ void hist_kernel(const int* __restrict__ dst) {
    int e = blockIdx.x * blockDim.x + threadIdx.x;
    if (e < EE) atomicAdd(&g_hist[__ldg(dst + e)], 1);
}

__global__ __launch_bounds__(1024, 1) void scan_kernel() {
    __shared__ int warp_sums[32];
    __shared__ int s_carry;
    int tid = threadIdx.x, lane = tid & 31, w = tid >> 5;
    if (tid == 0) s_carry = 0;
    __syncthreads();
    for (int base = 0; base < NND; base += 1024) {
        int i = base + tid;
        int v = (i < NND) ? g_hist[i] : 0;
        int x = v;
        #pragma unroll
        for (int o = 1; o < 32; o <<= 1) {
            int t = __shfl_up_sync(0xFFFFFFFFu, x, o);
            if (lane >= o) x += t;
        }
        if (lane == 31) warp_sums[w] = x;
        __syncthreads();
        if (w == 0) {
            int y = warp_sums[lane];
            #pragma unroll
            for (int o = 1; o < 32; o <<= 1) {
                int t = __shfl_up_sync(0xFFFFFFFFu, y, o);
                if (lane >= o) y += t;
            }
            warp_sums[lane] = y;
        }
        __syncthreads();
        int excl = s_carry + x - v + (w > 0 ? warp_sums[w - 1] : 0);
        if (i < NND) { g_rowptr[i] = excl; g_cursor[i] = excl; }
        __syncthreads();
        if (tid == 0) s_carry += warp_sums[31];
        __syncthreads();
    }
    if (tid == 0) g_rowptr[NND] = s_carry;
}

__global__ void fill_kernel(const int* __restrict__ src,
                            const int* __restrict__ dst,
                            const int* __restrict__ r) {
    int e = blockIdx.x * blockDim.x + threadIdx.x;
    if (e >= EE) return;
    int d = __ldg(dst + e);
    int pos = atomicAdd(&g_cursor[d], 1);
    g_edges[pos] = (uint32_t)__ldg(src + e)
                 | ((uint32_t)(__ldg(r + e) == 1) << 31);
}

// ---- gather-mean: warp per node; emits split bf16 directly ----
__global__ __launch_bounds__(256) void gather_kernel(
    const float* __restrict__ h,
    __nv_bfloat16* __restrict__ oh, __nv_bfloat16* __restrict__ ol)
{
    int wid = (blockIdx.x * 256 + threadIdx.x) >> 5;
    int lane = threadIdx.x & 31;
    if (wid >= NND) return;
    int beg = __ldg(&g_rowptr[wid]), end = __ldg(&g_rowptr[wid + 1]);
    float4 A = make_float4(0.f, 0.f, 0.f, 0.f);
    float4 B = make_float4(0.f, 0.f, 0.f, 0.f);
    for (int e = beg; e < end; e++) {
        uint32_t p = __ldg(&g_edges[e]);
        const float4* row = (const float4*)(((p >> 31) ? g_tinv : h)
                           + (size_t)(p & 0x7FFFFFFFu) * 256);
        float4 x = __ldg(row + lane * 2);
        float4 y = __ldg(row + lane * 2 + 1);
        A.x += x.x; A.y += x.y; A.z += x.z; A.w += x.w;
        B.x += y.x; B.y += y.y; B.z += y.z; B.w += y.w;
    }
    float sc = 1.f / fmaxf((float)(end - beg), 1.f);
    float v[8] = {A.x * sc, A.y * sc, A.z * sc, A.w * sc,
                  B.x * sc, B.y * sc, B.z * sc, B.w * sc};
    uint4 hp, lp;
    uint32_t* hq = (uint32_t*)&hp; uint32_t* lq = (uint32_t*)&lp;
    #pragma unroll
    for (int j = 0; j < 4; j++) {
        float va = v[2*j], vb = v[2*j+1];
        __nv_bfloat16 ha = __float2bfloat16(va), hb = __float2bfloat16(vb);
        hq[j] = (uint32_t)__bfloat16_as_ushort(ha)
              | ((uint32_t)__bfloat16_as_ushort(hb) << 16);
        lq[j] = pack2(va - __bfloat162float(ha), vb - __bfloat162float(hb));
    }
    *(uint4*)(oh + (size_t)wid * 256 + lane * 8) = hp;
    *(uint4*)(ol + (size_t)wid * 256 + lane * 8) = lp;
}

// All 8 weight transposes + splits in one launch
__global__ void prep_all(const float* W0, const float* W1, const float* W2,
                         const float* W3, const float* W4, const float* W5,
                         const float* W6, const float* W7) {
    int i = blockIdx.x * blockDim.x + threadIdx.x;
    if (i >= 294912) return;
    const int cum[9]  = {0, 32768, 49152, 81920, 114688, 131072, 163840, 229376, 294912};
    const int Ks[8]   = {256, 128, 128, 256, 128, 128, 256, 256};
    const int Ns[8]   = {128, 128, 256, 128, 128, 256, 256, 256};
    int m = 0;
    #pragma unroll
    for (int t = 1; t < 8; t++) if (i >= cum[t]) m = t;
    int j = i - cum[m], K = Ks[m], N = Ns[m];
    int n = j / K, k = j % K;
    const float* W; __nv_bfloat16 *Th, *Tl;
    switch (m) {
        case 0: W = W0; Th = g_iW1h; Tl = g_iW1l; break;
        case 1: W = W1; Th = g_iW2h; Tl = g_iW2l; break;
        case 2: W = W2; Th = g_iW3h; Tl = g_iW3l; break;
        case 3: W = W3; Th = g_aW1h; Tl = g_aW1l; break;
        case 4: W = W4; Th = g_aW2h; Tl = g_aW2l; break;
        case 5: W = W5; Th = g_aW3h; Tl = g_aW3l; break;
        case 6: W = W6; Th = g_pW1h; Tl = g_pW1l; break;
        default: W = W7; Th = g_pW2h; Tl = g_pW2l; break;
    }
    float v = W[(size_t)k * N + n];
    __nv_bfloat16 h = __float2bfloat16(v);
    Th[j] = h;
    Tl[j] = __float2bfloat16(v - __bfloat162float(h));
}

// fp32 [NND x 256] -> split bf16
__global__ void conv_split(const float* __restrict__ x,
                           __nv_bfloat16* __restrict__ oh,
                           __nv_bfloat16* __restrict__ ol) {
    int u = blockIdx.x * blockDim.x + threadIdx.x;
    if (u >= NND * 32) return;
    int row = u >> 5, seg = u & 31;
    const float4* s = (const float4*)(x + (size_t)row * 256 + seg * 8);
    float4 a = s[0], b = s[1];
    float v[8] = {a.x, a.y, a.z, a.w, b.x, b.y, b.z, b.w};
    uint4 hp, lp;
    uint32_t* hq = (uint32_t*)&hp; uint32_t* lq = (uint32_t*)&lp;
    #pragma unroll
    for (int j = 0; j < 4; j++) {
        float va = v[2*j], vb = v[2*j+1];
        __nv_bfloat16 ha = __float2bfloat16(va), hb = __float2bfloat16(vb);
        hq[j] = (uint32_t)__bfloat16_as_ushort(ha)
              | ((uint32_t)__bfloat16_as_ushort(hb) << 16);
        lq[j] = pack2(va - __bfloat162float(ha), vb - __bfloat162float(hb));
    }
    *(uint4*)(oh + (size_t)row * 256 + seg * 8) = hp;
    *(uint4*)(ol + (size_t)row * 256 + seg * 8) = lp;
}

// ---------------------------------------------------------------------------
// Fused 3-layer MLP: 256 ->(leaky) 128 ->(leaky) 128 ->(linear) 256
// CTA owns 128 rows; L1/L2 intermediates live in SMEM (no gmem round-trip).
// SMEM map (bytes):
//   S  = 0      : 2x64KB stage region (L1 double buffer; later W2/W3 staging)
//   I  = 131072 : 64KB inter (hi ch0 @+0, hi ch1 @+16384, lo ch0 @+32768, lo ch1 @+49152)
//   IDX= 196608 : sidx_in[128], sidx_out[128]
__global__ __launch_bounds__(256, 1) void mlp3_fused(
    const __nv_bfloat16* __restrict__ Ah, const __nv_bfloat16* __restrict__ Al,
    const __nv_bfloat16* __restrict__ W1h, const __nv_bfloat16* __restrict__ W1l,
    const float* __restrict__ b1,
    const __nv_bfloat16* __restrict__ W2h, const __nv_bfloat16* __restrict__ W2l,
    const float* __restrict__ b2,
    const __nv_bfloat16* __restrict__ W3h, const __nv_bfloat16* __restrict__ W3l,
    const float* __restrict__ b3,
    float* __restrict__ outf,
    __nv_bfloat16* __restrict__ outh, __nv_bfloat16* __restrict__ outl,
    const int* __restrict__ gin, const int* __restrict__ gout,
    const int* __restrict__ nrowp)
{
    extern __shared__ char sm[];
    const uint32_t smb = smem_u32_of(sm);
    const int tid = threadIdx.x, lane = tid & 31, warp = tid >> 5;
    const int warp_m = warp & 3, warp_n = warp >> 2;
    const int r0 = blockIdx.x * 128;

    const uint32_t S = smb, I = smb + 131072u;

    const int nrow = nrowp ? __ldg(nrowp) : NND;
    if (r0 >= nrow) return;

    int* sidx_in  = (int*)(sm + 196608);
    int* sidx_out = (int*)(sm + 197120);
    for (int i = tid; i < 128; i += 256) {
        int gr = r0 + i;
        bool ok = gr < nrow;
        sidx_in[i]  = ok ? (gin  ? __ldg(gin  + gr) : gr) : -1;
        sidx_out[i] = ok ? (gout ? __ldg(gout + gr) : gr) : -1;
    }
    __syncthreads();

    float c[2][8][4];
    auto zero_c = [&]() {
        #pragma unroll
        for (int i = 0; i < 2; i++)
            #pragma unroll
            for (int j = 0; j < 8; j++)
                #pragma unroll
                for (int k = 0; k < 4; k++) c[i][j][k] = 0.f;
    };

    // stage one gathered A chunk (128 rows x 64 cols) into dstb
    auto stageA = [&](const __nv_bfloat16* src, uint32_t dstb, int k0) {
        #pragma unroll
        for (int it = 0; it < 4; it++) {
            int u = tid + it * 256, row = u >> 3, seg = u & 7;
            int grow = sidx_in[row];
            uint32_t sz = (grow >= 0) ? 16u : 0u;
            const void* sp = src + (size_t)(grow >= 0 ? grow : 0) * 256 + k0 + seg * 8;
            CP_ASYNC16(dstb + (uint32_t)row * 128 + ((uint32_t)(seg ^ (row & 7)) << 4),
                       sp, sz);
        }
    };
    // stage one B chunk: rows x 64 cols from W[rows][K]
    auto stageB = [&](const __nv_bfloat16* src, uint32_t dstb, int rows, int K, int k0) {
        for (int u = tid; u < rows * 8; u += 256) {
            int row = u >> 3, seg = u & 7;
            CP_ASYNC16(dstb + (uint32_t)row * 128 + ((uint32_t)(seg ^ (row & 7)) << 4),
                       src + (size_t)row * K + k0 + seg * 8, 16u);
        }
    };

    auto mma_chunk = [&](uint32_t AHb, uint32_t ALb, uint32_t BHb, uint32_t BLb) {
        #pragma unroll
        for (int ks = 0; ks < 4; ks++) {
            uint32_t ah[2][4], al[2][4];
            #pragma unroll
            for (int mt = 0; mt < 2; mt++) {
                int lr = warp_m * 32 + mt * 16 + (lane & 15);
                int seg = 2 * ks + (lane >> 4);
                uint32_t off = (uint32_t)lr * 128 + ((uint32_t)(seg ^ (lr & 7)) << 4);
                LDSM4(ah[mt], AHb + off);
                LDSM4(al[mt], ALb + off);
            }
            #pragma unroll
            for (int nq = 0; nq < 4; nq++) {
                int lrb = warp_n * 64 + nq * 16 + (lane & 7) + ((lane >> 4) << 3);
                int segb = 2 * ks + ((lane >> 3) & 1);
                uint32_t offb = (uint32_t)lrb * 128 + ((uint32_t)(segb ^ (lrb & 7)) << 4);
                uint32_t bh[4], bl[4];
                LDSM4(bh, BHb + offb);
                LDSM4(bl, BLb + offb);
                #pragma unroll
                for (int mt = 0; mt < 2; mt++) {
                    #pragma unroll
                    for (int sub = 0; sub < 2; sub++) {
                        float* d = c[mt][nq * 2 + sub];
                        mma16816(d, ah[mt], bh + sub * 2);
                        mma16816(d, ah[mt], bl + sub * 2);
                        mma16816(d, al[mt], bh + sub * 2);
                    }
                }
            }
        }
    };

    // epilogue -> inter SMEM (leaky), split hi/lo; N = 128
    auto epi_smem = [&](const float* __restrict__ bias) {
        #pragma unroll
        for (int mt = 0; mt < 2; mt++) {
            #pragma unroll
            for (int q = 0; q < 8; q++) {
                int col = warp_n * 64 + q * 8 + (lane & 3) * 2;
                float2 bv = *(const float2*)(bias + col);
                uint32_t chb = I + (uint32_t)(col >> 6) * 16384u;
                int cc = col & 63;
                #pragma unroll
                for (int half = 0; half < 2; half++) {
                    int lr = warp_m * 32 + mt * 16 + (lane >> 2) + half * 8;
                    float v0 = c[mt][q][half * 2 + 0] + bv.x;
                    float v1 = c[mt][q][half * 2 + 1] + bv.y;
                    v0 = (v0 >= 0.f) ? v0 : 0.01f * v0;
                    v1 = (v1 >= 0.f) ? v1 : 0.01f * v1;
                    __nv_bfloat16 h0 = __float2bfloat16(v0);
                    __nv_bfloat16 h1 = __float2bfloat16(v1);
                    uint32_t hp = (uint32_t)__bfloat16_as_ushort(h0)
                                | ((uint32_t)__bfloat16_as_ushort(h1) << 16);
                    uint32_t lp = pack2(v0 - __bfloat162float(h0),
                                        v1 - __bfloat162float(h1));
                    uint32_t addr = chb + (uint32_t)lr * 128
                                  + ((uint32_t)((cc >> 3) ^ (lr & 7)) << 4)
                                  + (uint32_t)(cc & 7) * 2;
                    asm volatile("st.shared.b32 [%0], %1;" :: "r"(addr), "r"(hp) : "memory");
                    asm volatile("st.shared.b32 [%0], %1;" :: "r"(addr + 32768u), "r"(lp) : "memory");
                }
            }
        }
    };

    // ---- Layer 1: K=256, 4 chunks, double-buffered ----
    zero_c();
    {
        auto stage1 = [&](int ch, int buf) {
            uint32_t base = S + (uint32_t)buf * 65536u;
            stageA(Ah, base, ch * 64);
            stageA(Al, base + 16384u, ch * 64);
            stageB(W1h, base + 32768u, 128, 256, ch * 64);
            stageB(W1l, base + 49152u, 128, 256, ch * 64);
            CP_COMMIT();
        };
        stage1(0, 0);
        for (int ch = 0; ch < 4; ch++) {
            int cur = ch & 1;
            if (ch + 1 < 4) {
                stage1(ch + 1, cur ^ 1);
                CP_WAIT1();
            } else {
                // prefetch W2 (both K-chunks) into buf0 region (free: ch2 consumed)
                stageB(W2h, S + 0u,      128, 128, 0);
                stageB(W2l, S + 16384u,  128, 128, 0);
                stageB(W2h, S + 32768u,  128, 128, 64);
                stageB(W2l, S + 49152u,  128, 128, 64);
                CP_COMMIT();
                CP_WAIT1();
            }
            __syncthreads();
            uint32_t base = S + (uint32_t)cur * 65536u;
            mma_chunk(base, base + 16384u, base + 32768u, base + 49152u);
            __syncthreads();
        }
    }
    epi_smem(b1);   // L1 out -> inter
    __syncthreads();

    // ---- Layer 2: K=128, A = inter, B = W2 (staged in buf0) ----
    CP_WAIT0();
    __syncthreads();
    // prefetch W3 chunk0 (k 0-63, 256 rows) into buf1
    stageB(W3h, S + 65536u, 256, 128, 0);
    stageB(W3l, S + 98304u, 256, 128, 0);
    CP_COMMIT();
    zero_c();
    mma_chunk(I + 0u,      I + 32768u, S + 0u,      S + 16384u);
    mma_chunk(I + 16384u,  I + 49152u, S + 32768u,  S + 49152u);
    __syncthreads();          // all inter reads + W2 reads done
    // stage W3 chunk1 into buf0
    stageB(W3h, S + 0u,      256, 128, 64);
    stageB(W3l, S + 32768u,  256, 128, 64);
    CP_COMMIT();
    epi_smem(b2);             // L2 out -> inter (overwrite)
    __syncthreads();

    // ---- Layer 3: K=128, N=256 (two column halves), linear ----
    CP_WAIT0();
    __syncthreads();
    #pragma unroll
    for (int hf = 0; hf < 2; hf++) {
        zero_c();
        // chunk0 (k 0-63) in buf1, chunk1 (k 64-127) in buf0; B row offset hf*128
        mma_chunk(I + 0u,     I + 32768u, S + 65536u + hf * 16384u, S + 98304u + hf * 16384u);
        mma_chunk(I + 16384u, I + 49152u, S + 0u     + hf * 16384u, S + 32768u + hf * 16384u);
        // epilogue -> gmem
        #pragma unroll
        for (int mt = 0; mt < 2; mt++) {
            #pragma unroll
            for (int q = 0; q < 8; q++) {
                int col = hf * 128 + warp_n * 64 + q * 8 + (lane & 3) * 2;
                float2 bv = *(const float2*)(b3 + col);
                #pragma unroll
                for (int half = 0; half < 2; half++) {
                    int lr = warp_m * 32 + mt * 16 + (lane >> 2) + half * 8;
                    int orow = sidx_out[lr];
                    if (orow >= 0) {
                        float v0 = c[mt][q][half * 2 + 0] + bv.x;
                        float v1 = c[mt][q][half * 2 + 1] + bv.y;
                        if (outf)
                            *(float2*)(outf + (size_t)orow * 256 + col) = make_float2(v0, v1);
                        if (outh) {
                            __nv_bfloat16 h0 = __float2bfloat16(v0);
                            __nv_bfloat16 h1 = __float2bfloat16(v1);
                            uint32_t hp = (uint32_t)__bfloat16_as_ushort(h0)
                                        | ((uint32_t)__bfloat16_as_ushort(h1) << 16);
                            uint32_t lp = pack2(v0 - __bfloat162float(h0),
                                                v1 - __bfloat162float(h1));
                            *(uint32_t*)(outh + (size_t)orow * 256 + col) = hp;
                            *(uint32_t*)(outl + (size_t)orow * 256 + col) = lp;
                        }
                    }
                }
            }
        }
    }
}

// ---------------------------------------------------------------------------
// Generic split-bf16 GEMM (proj head), cp.async double-buffered (as R8).
__global__ __launch_bounds__(256, 1) void gemm_bf16(
    const __nv_bfloat16* __restrict__ Ah, const __nv_bfloat16* __restrict__ Al,
    const __nv_bfloat16* __restrict__ Bh, const __nv_bfloat16* __restrict__ Bl,
    const float* __restrict__ bias, int K, int N, int act,
    float* __restrict__ outf,
    __nv_bfloat16* __restrict__ outh, __nv_bfloat16* __restrict__ outl)
{
    extern __shared__ char sm[];
    const uint32_t smb = smem_u32_of(sm);
    const int tid = threadIdx.x, lane = tid & 31, warp = tid >> 5;
    const int warp_m = warp & 3, warp_n = warp >> 2;
    const int r0 = blockIdx.x * 128;
    const int c0 = blockIdx.y * 128;

    float c[2][8][4];
    #pragma unroll
    for (int i = 0; i < 2; i++)
        #pragma unroll
        for (int j = 0; j < 8; j++)
            #pragma unroll
            for (int k = 0; k < 4; k++) c[i][j][k] = 0.f;

    auto stage = [&](int ch, int buf) {
        uint32_t base = smb + (uint32_t)buf * 65536u;
        #pragma unroll
        for (int p = 0; p < 2; p++) {
            const __nv_bfloat16* Asrc = p ? Al : Ah;
            uint32_t abase = base + (p ? 16384u : 0u);
            #pragma unroll
            for (int it = 0; it < 4; it++) {
                int u = tid + it * 256, row = u >> 3, seg = u & 7;
                int grow = r0 + row;
                uint32_t sz = (grow < NND) ? 16u : 0u;
                const void* src = Asrc + (size_t)(grow < NND ? grow : 0) * K
                                + ch * 64 + seg * 8;
                CP_ASYNC16(base + (p ? 16384u : 0u) + (uint32_t)row * 128
                           + ((uint32_t)(seg ^ (row & 7)) << 4), src, sz);
                (void)abase;
            }
        }
        #pragma unroll
        for (int p = 0; p < 2; p++) {
            const __nv_bfloat16* Bsrc = p ? Bl : Bh;
            uint32_t bbase = base + (p ? 49152u : 32768u);
            #pragma unroll
            for (int it = 0; it < 4; it++) {
                int u = tid + it * 256, row = u >> 3, seg = u & 7;
                CP_ASYNC16(bbase + (uint32_t)row * 128
                           + ((uint32_t)(seg ^ (row & 7)) << 4),
                           Bsrc + (size_t)(c0 + row) * K + ch * 64 + seg * 8, 16u);
            }
        }
        CP_COMMIT();
    };

    auto mma_chunk = [&](int buf) {
        uint32_t base = smb + (uint32_t)buf * 65536u;
        const uint32_t AH = base, AL = base + 16384u, BH = base + 32768u,
                       BL = base + 49152u;
        #pragma unroll
        for (int ks = 0; ks < 4; ks++) {
            uint32_t ah[2][4], al[2][4];
            #pragma unroll
            for (int mt = 0; mt < 2; mt++) {
                int lr = warp_m * 32 + mt * 16 + (lane & 15);
                int seg = 2 * ks + (lane >> 4);
                uint32_t off = (uint32_t)lr * 128 + ((uint32_t)(seg ^ (lr & 7)) << 4);
                LDSM4(ah[mt], AH + off);
                LDSM4(al[mt], AL + off);
            }
            #pragma unroll
            for (int nq = 0; nq < 4; nq++) {
                int lrb = warp_n * 64 + nq * 16 + (lane & 7) + ((lane >> 4) << 3);
                int segb = 2 * ks + ((lane >> 3) & 1);
                uint32_t offb = (uint32_t)lrb * 128 + ((uint32_t)(segb ^ (lrb & 7)) << 4);
                uint32_t bh[4], bl[4];
                LDSM4(bh, BH + offb);
                LDSM4(bl, BL + offb);
                #pragma unroll
                for (int mt = 0; mt < 2; mt++) {
                    #pragma unroll
                    for (int sub = 0; sub < 2; sub++) {
                        float* d = c[mt][nq * 2 + sub];
                        mma16816(d, ah[mt], bh + sub * 2);
                        mma16816(d, ah[mt], bl + sub * 2);
                        mma16816(d, al[mt], bh + sub * 2);
                    }
                }
            }
        }
    };

    const int nch = K >> 6;
    stage(0, 0);
    for (int ch = 0; ch < nch; ch++) {
        int cur = ch & 1;
        if (ch + 1 < nch) { stage(ch + 1, cur ^ 1); CP_WAIT1(); }
        else             { CP_WAIT0(); }
        __syncthreads();
        mma_chunk(cur);
        __syncthreads();
    }

    #pragma unroll
    for (int mt = 0; mt < 2; mt++) {
        #pragma unroll
        for (int q = 0; q < 8; q++) {
            int col = c0 + warp_n * 64 + q * 8 + (lane & 3) * 2;
            float2 bv = *(const float2*)(bias + col);
            #pragma unroll
            for (int half = 0; half < 2; half++) {
                int lr = warp_m * 32 + mt * 16 + (lane >> 2) + half * 8;
                int orow = r0 + lr;
                if (orow < NND) {
                    float v0 = c[mt][q][half * 2 + 0] + bv.x;
                    float v1 = c[mt][q][half * 2 + 1] + bv.y;
                    if (act == 2) { v0 = fmaxf(v0, 0.f); v1 = fmaxf(v1, 0.f); }
                    if (outf)
                        *(float2*)(outf + (size_t)orow * N + col) = make_float2(v0, v1);
                    if (outh) {
                        __nv_bfloat16 h0 = __float2bfloat16(v0);
                        __nv_bfloat16 h1 = __float2bfloat16(v1);
                        uint32_t hp = (uint32_t)__bfloat16_as_ushort(h0)
                                    | ((uint32_t)__bfloat16_as_ushort(h1) << 16);
                        uint32_t lp = pack2(v0 - __bfloat162float(h0),
                                            v1 - __bfloat162float(h1));
                        *(uint32_t*)(outh + (size_t)orow * N + col) = hp;
                        *(uint32_t*)(outl + (size_t)orow * N + col) = lp;
                    }
                }
            }
        }
    }
}

// ---------------------------------------------------------------------------
extern "C" void kernel_launch(void* const* d_in, const int* in_sizes, int n_in,
                              void* d_out, int out_size)
{
    const float* h   = (const float*)d_in[0];
    const int*   src = (const int*)  d_in[1];
    const int*   dst = (const int*)  d_in[2];
    const int*   r   = (const int*)  d_in[3];
    const int*   inv = (const int*)  d_in[4];
    const float* iW1 = (const float*)d_in[5];
    const float* ib1 = (const float*)d_in[6];
    const float* iW2 = (const float*)d_in[7];
    const float* ib2 = (const float*)d_in[8];
    const float* iW3 = (const float*)d_in[9];
    const float* ib3 = (const float*)d_in[10];
    const float* aW1 = (const float*)d_in[11];
    const float* ab1 = (const float*)d_in[12];
    const float* aW2 = (const float*)d_in[13];
    const float* ab2 = (const float*)d_in[14];
    const float* aW3 = (const float*)d_in[15];
    const float* ab3 = (const float*)d_in[16];
    const float* pW1 = (const float*)d_in[17];
    const float* pb1 = (const float*)d_in[18];
    const float* pW2 = (const float*)d_in[19];
    const float* pb2 = (const float*)d_in[20];
    float* out = (float*)d_out;

    float *tinv;
    int *invidx, *ninv;
    cudaGetSymbolAddress((void**)&tinv, g_tinv);
    cudaGetSymbolAddress((void**)&invidx, g_invidx);
    cudaGetSymbolAddress((void**)&ninv, g_ninv);

    __nv_bfloat16 *xh,*xl,*sh,*sl;
    cudaGetSymbolAddress((void**)&xh, g_xh); cudaGetSymbolAddress((void**)&xl, g_xl);
    cudaGetSymbolAddress((void**)&sh, g_sh); cudaGetSymbolAddress((void**)&sl, g_sl);

    __nv_bfloat16 *iW1h,*iW1l,*iW2h,*iW2l,*iW3h,*iW3l;
    __nv_bfloat16 *aW1h,*aW1l,*aW2h,*aW2l,*aW3h,*aW3l;
    __nv_bfloat16 *pW1h,*pW1l,*pW2h,*pW2l;
    cudaGetSymbolAddress((void**)&iW1h, g_iW1h); cudaGetSymbolAddress((void**)&iW1l, g_iW1l);
    cudaGetSymbolAddress((void**)&iW2h, g_iW2h); cudaGetSymbolAddress((void**)&iW2l, g_iW2l);
    cudaGetSymbolAddress((void**)&iW3h, g_iW3h); cudaGetSymbolAddress((void**)&iW3l, g_iW3l);
    cudaGetSymbolAddress((void**)&aW1h, g_aW1h); cudaGetSymbolAddress((void**)&aW1l, g_aW1l);
    cudaGetSymbolAddress((void**)&aW2h, g_aW2h); cudaGetSymbolAddress((void**)&aW2l, g_aW2l);
    cudaGetSymbolAddress((void**)&aW3h, g_aW3h); cudaGetSymbolAddress((void**)&aW3l, g_aW3l);
    cudaGetSymbolAddress((void**)&pW1h, g_pW1h); cudaGetSymbolAddress((void**)&pW1l, g_pW1l);
    cudaGetSymbolAddress((void**)&pW2h, g_pW2h); cudaGetSymbolAddress((void**)&pW2l, g_pW2l);

    const int SMEM_F = 197632;   // fused: 128KB stage + 64KB inter + idx
    const int SMEM_G = 131072;   // proj gemm: 2x64KB
    cudaFuncSetAttribute(mlp3_fused, cudaFuncAttributeMaxDynamicSharedMemorySize, SMEM_F);
    cudaFuncSetAttribute(gemm_bf16,  cudaFuncAttributeMaxDynamicSharedMemorySize, SMEM_G);

    const int NB = (NND + 127) / 128;   // 391
    dim3 g256(NB, 2);

    zero_kernel<<<196, 256>>>();
    prep_all<<<1152, 256>>>(iW1, iW2, iW3, aW1, aW2, aW3, pW1, pW2);
    count_inv<<<196, 256>>>(inv);
    conv_split<<<6250, 256>>>(h, xh, xl);
    hist_kernel<<<(EE + 255) / 256, 256>>>(dst);
    scan_kernel<<<1, 1024>>>();
    fill_kernel<<<(EE + 255) / 256, 256>>>(src, dst, r);

    // tinv = MLP_inv(h)  (fp32 out for gather)
    mlp3_fused<<<NB, 256, SMEM_F>>>(xh, xl, iW1h, iW1l, ib1, iW2h, iW2l, ib2,
                                    iW3h, iW3l, ib3, tinv, 0, 0, 0, 0, 0);
    // neigh mean via CSR gather -> split bf16 directly
    gather_kernel<<<6250, 256>>>(h, sh, sl);
    // res = MLP_and(neigh) -> res2 buffer (xh/xl)
    mlp3_fused<<<NB, 256, SMEM_F>>>(sh, sl, aW1h, aW1l, ab1, aW2h, aW2l, ab2,
                                    aW3h, aW3l, ab3, 0, xh, xl, 0, 0, 0);
    // res2[invidx] = MLP_inv(res[invidx])  (compact ~25k rows)
    mlp3_fused<<<NB, 256, SMEM_F>>>(xh, xl, iW1h, iW1l, ib1, iW2h, iW2l, ib2,
                                    iW3h, iW3l, ib3, 0, xh, xl, invidx, invidx, ninv);
    // proj head (hidden reuses sh/sl)
    gemm_bf16<<<g256, 256, SMEM_G>>>(xh, xl, pW1h, pW1l, pb1, 256, 256, 2, 0, sh, sl);
    gemm_bf16<<<g256, 256, SMEM_G>>>(sh, sl, pW2h, pW2l, pb2, 256, 256, 0, out, 0, 0);
}

// round 11
// speedup vs baseline: 6.7178x; 1.2572x over previous
#include <cuda_runtime.h>
#include <cuda_fp16.h>
#include <cstdint>

#define NND 50000
#define NP  50048              // padded to 391*128
#define EE  800000

// ---------------------------------------------------------------------------
// Scratch (device globals; no allocations anywhere)
__device__ float g_tinv[(size_t)NP * 256];   // fp32 MLP_inv(h) (gather msg)
__device__ int   g_hist[NND];
__device__ int   g_rowptr[NND + 1];
__device__ int   g_cursor[NND];
__device__ uint32_t g_edges[EE];             // src | (r==1)<<31, CSR order by dst
__device__ int   g_invidx[NND];
__device__ int   g_ninv;

// split-fp16 activation buffers
__device__ __align__(16) __half g_xh[(size_t)NP * 256], g_xl[(size_t)NP * 256];
__device__ __align__(16) __half g_sh[(size_t)NP * 256], g_sl[(size_t)NP * 256];

// Pre-transposed fp16 weights (hi only): Wt[n][k] = W[k][n]
__device__ __align__(16) __half g_iW1[128*256];
__device__ __align__(16) __half g_iW2[128*128];
__device__ __align__(16) __half g_iW3[256*128];
__device__ __align__(16) __half g_aW1[128*256];
__device__ __align__(16) __half g_aW2[128*128];
__device__ __align__(16) __half g_aW3[256*128];
__device__ __align__(16) __half g_pW1[256*256];
__device__ __align__(16) __half g_pW2[256*256];

// ---------------------------------------------------------------------------
__device__ __forceinline__ uint32_t smem_u32_of(const void* p) {
    uint32_t a;
    asm("{ .reg .u64 t; cvta.to.shared.u64 t, %1; cvt.u32.u64 %0, t; }"
        : "=r"(a) : "l"(p));
    return a;
}
#define LDSM4(r, addr)                                                         \
    asm volatile("ldmatrix.sync.aligned.m8n8.x4.shared.b16 {%0,%1,%2,%3}, [%4];" \
        : "=r"((r)[0]), "=r"((r)[1]), "=r"((r)[2]), "=r"((r)[3]) : "r"(addr))
#define CP_ASYNC16(dst, src, sz)                                               \
    asm volatile("cp.async.cg.shared.global [%0], [%1], 16, %2;"               \
        :: "r"(dst), "l"(src), "r"(sz) : "memory")
#define CP_COMMIT() asm volatile("cp.async.commit_group;" ::: "memory")
#define CP_WAIT1()  asm volatile("cp.async.wait_group 1;" ::: "memory")
#define CP_WAIT0()  asm volatile("cp.async.wait_group 0;" ::: "memory")

__device__ __forceinline__ void mma_h(float* d, const uint32_t* a,
                                      const uint32_t* b) {
    asm volatile("mma.sync.aligned.m16n8k16.row.col.f32.f16.f16.f32 "
        "{%0,%1,%2,%3}, {%4,%5,%6,%7}, {%8,%9}, {%0,%1,%2,%3};"
        : "+f"(d[0]), "+f"(d[1]), "+f"(d[2]), "+f"(d[3])
        : "r"(a[0]), "r"(a[1]), "r"(a[2]), "r"(a[3]), "r"(b[0]), "r"(b[1]));
}
__device__ __forceinline__ uint32_t packh2(float a, float b) {
    __half x = __float2half_rn(a), y = __float2half_rn(b);
    return (uint32_t)__half_as_ushort(x) | ((uint32_t)__half_as_ushort(y) << 16);
}
// split v into fp16 hi + lo; returns packed pair words via refs
__device__ __forceinline__ void split2(float v0, float v1,
                                       uint32_t& hp, uint32_t& lp) {
    __half h0 = __float2half_rn(v0), h1 = __float2half_rn(v1);
    hp = (uint32_t)__half_as_ushort(h0) | ((uint32_t)__half_as_ushort(h1) << 16);
    lp = packh2(v0 - __half2float(h0), v1 - __half2float(h1));
}

// ---------------------------------------------------------------------------
__global__ void zero_kernel() {
    int i = blockIdx.x * blockDim.x + threadIdx.x;
    if (i < NND) g_hist[i] = 0;
    if (i == 0) g_ninv = 0;
}

// hist on dst + inv compaction in one launch
__global__ void hist_kernel(const int* __restrict__ dst,
                            const int* __restrict__ inv) {
    int e = blockIdx.x * blockDim.x + threadIdx.x;
    if (e < EE) atomicAdd(&g_hist[__ldg(dst + e)], 1);
    if (e < NND && __ldg(inv + e) == 1) {
        int p = atomicAdd(&g_ninv, 1);
        g_invidx[p] = e;
    }
}

__global__ __launch_bounds__(1024, 1) void scan_kernel() {
    __shared__ int warp_sums[32];
    __shared__ int s_carry;
    int tid = threadIdx.x, lane = tid & 31, w = tid >> 5;
    if (tid == 0) s_carry = 0;
    __syncthreads();
    for (int base = 0; base < NND; base += 1024) {
        int i = base + tid;
        int v = (i < NND) ? g_hist[i] : 0;
        int x = v;
        #pragma unroll
        for (int o = 1; o < 32; o <<= 1) {
            int t = __shfl_up_sync(0xFFFFFFFFu, x, o);
            if (lane >= o) x += t;
        }
        if (lane == 31) warp_sums[w] = x;
        __syncthreads();
        if (w == 0) {
            int y = warp_sums[lane];
            #pragma unroll
            for (int o = 1; o < 32; o <<= 1) {
                int t = __shfl_up_sync(0xFFFFFFFFu, y, o);
                if (lane >= o) y += t;
            }
            warp_sums[lane] = y;
        }
        __syncthreads();
        int excl = s_carry + x - v + (w > 0 ? warp_sums[w - 1] : 0);
        if (i < NND) { g_rowptr[i] = excl; g_cursor[i] = excl; }
        __syncthreads();
        if (tid == 0) s_carry += warp_sums[31];
        __syncthreads();
    }
    if (tid == 0) g_rowptr[NND] = s_carry;
}

__global__ void fill_kernel(const int* __restrict__ src,
                            const int* __restrict__ dst,
                            const int* __restrict__ r) {
    int e = blockIdx.x * blockDim.x + threadIdx.x;
    if (e >= EE) return;
    int d = __ldg(dst + e);
    int pos = atomicAdd(&g_cursor[d], 1);
    g_edges[pos] = (uint32_t)__ldg(src + e)
                 | ((uint32_t)(__ldg(r + e) == 1) << 31);
}

// ---- gather-mean: warp per node; emits split fp16 directly ----
__global__ __launch_bounds__(256) void gather_kernel(
    const float* __restrict__ h,
    __half* __restrict__ oh, __half* __restrict__ ol)
{
    int wid = (blockIdx.x * 256 + threadIdx.x) >> 5;
    int lane = threadIdx.x & 31;
    if (wid >= NND) return;
    int beg = __ldg(&g_rowptr[wid]), end = __ldg(&g_rowptr[wid + 1]);
    float4 A = make_float4(0.f, 0.f, 0.f, 0.f);
    float4 B = make_float4(0.f, 0.f, 0.f, 0.f);
    for (int e = beg; e < end; e++) {
        uint32_t p = __ldg(&g_edges[e]);
        const float4* row = (const float4*)(((p >> 31) ? g_tinv : h)
                           + (size_t)(p & 0x7FFFFFFFu) * 256);
        float4 x = __ldg(row + lane * 2);
        float4 y = __ldg(row + lane * 2 + 1);
        A.x += x.x; A.y += x.y; A.z += x.z; A.w += x.w;
        B.x += y.x; B.y += y.y; B.z += y.z; B.w += y.w;
    }
    float sc = 1.f / fmaxf((float)(end - beg), 1.f);
    float v[8] = {A.x * sc, A.y * sc, A.z * sc, A.w * sc,
                  B.x * sc, B.y * sc, B.z * sc, B.w * sc};
    uint4 hp, lp;
    uint32_t* hq = (uint32_t*)&hp; uint32_t* lq = (uint32_t*)&lp;
    #pragma unroll
    for (int j = 0; j < 4; j++) split2(v[2*j], v[2*j+1], hq[j], lq[j]);
    *(uint4*)(oh + (size_t)wid * 256 + lane * 8) = hp;
    *(uint4*)(ol + (size_t)wid * 256 + lane * 8) = lp;
}

// All 8 weight transposes (fp16 hi only) in one launch
__global__ void prep_all(const float* W0, const float* W1, const float* W2,
                         const float* W3, const float* W4, const float* W5,
                         const float* W6, const float* W7) {
    int i = blockIdx.x * blockDim.x + threadIdx.x;
    if (i >= 294912) return;
    const int cum[9]  = {0, 32768, 49152, 81920, 114688, 131072, 163840, 229376, 294912};
    const int Ks[8]   = {256, 128, 128, 256, 128, 128, 256, 256};
    const int Ns[8]   = {128, 128, 256, 128, 128, 256, 256, 256};
    int m = 0;
    #pragma unroll
    for (int t = 1; t < 8; t++) if (i >= cum[t]) m = t;
    int j = i - cum[m], K = Ks[m], N = Ns[m];
    int n = j / K, k = j % K;
    const float* W; __half* Th;
    switch (m) {
        case 0: W = W0; Th = g_iW1; break;
        case 1: W = W1; Th = g_iW2; break;
        case 2: W = W2; Th = g_iW3; break;
        case 3: W = W3; Th = g_aW1; break;
        case 4: W = W4; Th = g_aW2; break;
        case 5: W = W5; Th = g_aW3; break;
        case 6: W = W6; Th = g_pW1; break;
        default: W = W7; Th = g_pW2; break;
    }
    Th[j] = __float2half_rn(W[(size_t)k * N + n]);
}

// fp32 [NND x 256] -> split fp16
__global__ void conv_split(const float* __restrict__ x,
                           __half* __restrict__ oh, __half* __restrict__ ol) {
    int u = blockIdx.x * blockDim.x + threadIdx.x;
    if (u >= NND * 32) return;
    int row = u >> 5, seg = u & 31;
    const float4* s = (const float4*)(x + (size_t)row * 256 + seg * 8);
    float4 a = s[0], b = s[1];
    float v[8] = {a.x, a.y, a.z, a.w, b.x, b.y, b.z, b.w};
    uint4 hp, lp;
    uint32_t* hq = (uint32_t*)&hp; uint32_t* lq = (uint32_t*)&lp;
    #pragma unroll
    for (int j = 0; j < 4; j++) split2(v[2*j], v[2*j+1], hq[j], lq[j]);
    *(uint4*)(oh + (size_t)row * 256 + seg * 8) = hp;
    *(uint4*)(ol + (size_t)row * 256 + seg * 8) = lp;
}

// ---------------------------------------------------------------------------
// Fused 3-layer MLP (fp16 2-term split): 256 ->(leaky) 128 ->(leaky) 128 -> 256
// SMEM map (bytes, rel. smb):
//   buf0 @0      : AH@0  AL@16384  B@32768      (48KB)
//   buf1 @49152  : AH    AL        B            (48KB)
//   inter @98304 : hi ch0, hi ch1 @114688, lo ch0 @131072, lo ch1 @147456
//   idx   @163840: sidx_in[128], sidx_out[128]      -> total 164864
__global__ __launch_bounds__(256, 1) void mlp3_fused(
    const __half* __restrict__ Ah, const __half* __restrict__ Al,
    const __half* __restrict__ W1, const float* __restrict__ b1,
    const __half* __restrict__ W2, const float* __restrict__ b2,
    const __half* __restrict__ W3, const float* __restrict__ b3,
    float* __restrict__ outf,
    __half* __restrict__ outh, __half* __restrict__ outl,
    const int* __restrict__ gin, const int* __restrict__ gout,
    const int* __restrict__ nrowp)
{
    extern __shared__ char sm[];
    const uint32_t smb = smem_u32_of(sm);
    const int tid = threadIdx.x, lane = tid & 31, warp = tid >> 5;
    const int warp_m = warp & 3, warp_n = warp >> 2;
    const int r0 = blockIdx.x * 128;
    const uint32_t S = smb;
    const uint32_t IH0 = smb + 98304u, IH1 = smb + 114688u;
    const uint32_t IL0 = smb + 131072u, IL1 = smb + 147456u;

    const int nrow = nrowp ? __ldg(nrowp) : NND;
    if (r0 >= nrow) return;

    int* sidx_in  = (int*)(sm + 163840);
    int* sidx_out = (int*)(sm + 164352);
    for (int i = tid; i < 128; i += 256) {
        int gr = r0 + i;
        bool ok = gr < nrow;
        sidx_in[i]  = ok ? (gin  ? __ldg(gin  + gr) : gr) : -1;
        sidx_out[i] = ok ? (gout ? __ldg(gout + gr) : gr) : -1;
    }
    __syncthreads();

    float c[2][8][4];
    auto zero_c = [&]() {
        #pragma unroll
        for (int i = 0; i < 2; i++)
            #pragma unroll
            for (int j = 0; j < 8; j++)
                #pragma unroll
                for (int k = 0; k < 4; k++) c[i][j][k] = 0.f;
    };

    auto stageA = [&](const __half* src, uint32_t dstb, int k0) {
        #pragma unroll
        for (int it = 0; it < 4; it++) {
            int u = tid + it * 256, row = u >> 3, seg = u & 7;
            int grow = sidx_in[row];
            uint32_t sz = (grow >= 0) ? 16u : 0u;
            const void* sp = src + (size_t)(grow >= 0 ? grow : 0) * 256 + k0 + seg * 8;
            CP_ASYNC16(dstb + (uint32_t)row * 128 + ((uint32_t)(seg ^ (row & 7)) << 4),
                       sp, sz);
        }
    };
    auto stageB = [&](const __half* src, uint32_t dstb, int rows, int K, int k0) {
        for (int u = tid; u < rows * 8; u += 256) {
            int row = u >> 3, seg = u & 7;
            CP_ASYNC16(dstb + (uint32_t)row * 128 + ((uint32_t)(seg ^ (row & 7)) << 4),
                       src + (size_t)row * K + k0 + seg * 8, 16u);
        }
    };

    // one 64-K chunk: A (hi+lo) x B(hi), 2 MMAs per pair
    auto mma_chunk = [&](uint32_t AHb, uint32_t ALb, uint32_t Bb) {
        #pragma unroll
        for (int ks = 0; ks < 4; ks++) {
            uint32_t ah[2][4], al[2][4];
            #pragma unroll
            for (int mt = 0; mt < 2; mt++) {
                int lr = warp_m * 32 + mt * 16 + (lane & 15);
                int seg = 2 * ks + (lane >> 4);
                uint32_t off = (uint32_t)lr * 128 + ((uint32_t)(seg ^ (lr & 7)) << 4);
                LDSM4(ah[mt], AHb + off);
                LDSM4(al[mt], ALb + off);
            }
            #pragma unroll
            for (int nq = 0; nq < 4; nq++) {
                int lrb = warp_n * 64 + nq * 16 + (lane & 7) + ((lane >> 4) << 3);
                int segb = 2 * ks + ((lane >> 3) & 1);
                uint32_t offb = (uint32_t)lrb * 128 + ((uint32_t)(segb ^ (lrb & 7)) << 4);
                uint32_t bh[4];
                LDSM4(bh, Bb + offb);
                #pragma unroll
                for (int mt = 0; mt < 2; mt++) {
                    #pragma unroll
                    for (int sub = 0; sub < 2; sub++) {
                        float* d = c[mt][nq * 2 + sub];
                        mma_h(d, ah[mt], bh + sub * 2);
                        mma_h(d, al[mt], bh + sub * 2);
                    }
                }
            }
        }
    };

    // epilogue -> inter SMEM (leaky), split fp16 hi/lo; N = 128
    auto epi_smem = [&](const float* __restrict__ bias) {
        #pragma unroll
        for (int mt = 0; mt < 2; mt++) {
            #pragma unroll
            for (int q = 0; q < 8; q++) {
                int col = warp_n * 64 + q * 8 + (lane & 3) * 2;
                float2 bv = *(const float2*)(bias + col);
                uint32_t chb = ((col >> 6) ? IH1 : IH0);
                int cc = col & 63;
                #pragma unroll
                for (int half = 0; half < 2; half++) {
                    int lr = warp_m * 32 + mt * 16 + (lane >> 2) + half * 8;
                    float v0 = c[mt][q][half * 2 + 0] + bv.x;
                    float v1 = c[mt][q][half * 2 + 1] + bv.y;
                    v0 = (v0 >= 0.f) ? v0 : 0.01f * v0;
                    v1 = (v1 >= 0.f) ? v1 : 0.01f * v1;
                    uint32_t hp, lp;
                    split2(v0, v1, hp, lp);
                    uint32_t addr = chb + (uint32_t)lr * 128
                                  + ((uint32_t)((cc >> 3) ^ (lr & 7)) << 4)
                                  + (uint32_t)(cc & 7) * 2;
                    asm volatile("st.shared.b32 [%0], %1;" :: "r"(addr), "r"(hp) : "memory");
                    asm volatile("st.shared.b32 [%0], %1;" :: "r"(addr + 32768u), "r"(lp) : "memory");
                }
            }
        }
    };

    // ---- Layer 1: K=256, 4 chunks, double-buffered (48KB bufs) ----
    zero_c();
    {
        auto stage1 = [&](int ch, int buf) {
            uint32_t base = S + (uint32_t)buf * 49152u;
            stageA(Ah, base, ch * 64);
            stageA(Al, base + 16384u, ch * 64);
            stageB(W1, base + 32768u, 128, 256, ch * 64);
            CP_COMMIT();
        };
        stage1(0, 0);
        for (int ch = 0; ch < 4; ch++) {
            int cur = ch & 1;
            if (ch + 1 < 4) {
                stage1(ch + 1, cur ^ 1);
                CP_WAIT1();
            } else {
                // prefetch W2 (K=128, both chunks) into freed buf0 head
                stageB(W2, S + 0u,     128, 128, 0);
                stageB(W2, S + 16384u, 128, 128, 64);
                CP_COMMIT();
                CP_WAIT1();
            }
            __syncthreads();
            uint32_t base = S + (uint32_t)cur * 49152u;
            mma_chunk(base, base + 16384u, base + 32768u);
            __syncthreads();
        }
    }
    // stage W3 (256 rows x 2 K-chunks) into bytes 32768..98304
    stageB(W3, S + 32768u, 256, 128, 0);
    stageB(W3, S + 65536u, 256, 128, 64);
    CP_COMMIT();
    epi_smem(b1);             // L1 out -> inter
    CP_WAIT1();               // W2 done (W3 may pend)
    __syncthreads();

    // ---- Layer 2: K=128, A = inter, B = W2 ----
    zero_c();
    mma_chunk(IH0, IL0, S + 0u);
    mma_chunk(IH1, IL1, S + 16384u);
    __syncthreads();          // inter reads done before overwrite
    epi_smem(b2);             // L2 out -> inter
    CP_WAIT0();               // W3 done
    __syncthreads();

    // ---- Layer 3: K=128, N=256 (two column halves), linear ----
    #pragma unroll
    for (int hf = 0; hf < 2; hf++) {
        zero_c();
        mma_chunk(IH0, IL0, S + 32768u + (uint32_t)hf * 16384u);
        mma_chunk(IH1, IL1, S + 65536u + (uint32_t)hf * 16384u);
        #pragma unroll
        for (int mt = 0; mt < 2; mt++) {
            #pragma unroll
            for (int q = 0; q < 8; q++) {
                int col = hf * 128 + warp_n * 64 + q * 8 + (lane & 3) * 2;
                float2 bv = *(const float2*)(b3 + col);
                #pragma unroll
                for (int half = 0; half < 2; half++) {
                    int lr = warp_m * 32 + mt * 16 + (lane >> 2) + half * 8;
                    int orow = sidx_out[lr];
                    if (orow >= 0) {
                        float v0 = c[mt][q][half * 2 + 0] + bv.x;
                        float v1 = c[mt][q][half * 2 + 1] + bv.y;
                        if (outf)
                            *(float2*)(outf + (size_t)orow * 256 + col) = make_float2(v0, v1);
                        if (outh) {
                            uint32_t hp, lp;
                            split2(v0, v1, hp, lp);
                            *(uint32_t*)(outh + (size_t)orow * 256 + col) = hp;
                            *(uint32_t*)(outl + (size_t)orow * 256 + col) = lp;
                        }
                    }
                }
            }
        }
    }
}

// ---------------------------------------------------------------------------
// Generic split-fp16 GEMM (proj head), double-buffered 48KB bufs, 2 CTAs/SM.
__global__ __launch_bounds__(256, 2) void gemm_f16(
    const __half* __restrict__ Ah, const __half* __restrict__ Al,
    const __half* __restrict__ B,
    const float* __restrict__ bias, int K, int N, int act,
    float* __restrict__ outf,
    __half* __restrict__ outh, __half* __restrict__ outl)
{
    extern __shared__ char sm[];
    const uint32_t smb = smem_u32_of(sm);
    const int tid = threadIdx.x, lane = tid & 31, warp = tid >> 5;
    const int warp_m = warp & 3, warp_n = warp >> 2;
    const int r0 = blockIdx.x * 128;
    const int c0 = blockIdx.y * 128;

    float c[2][8][4];
    #pragma unroll
    for (int i = 0; i < 2; i++)
        #pragma unroll
        for (int j = 0; j < 8; j++)
            #pragma unroll
            for (int k = 0; k < 4; k++) c[i][j][k] = 0.f;

    auto stage = [&](int ch, int buf) {
        uint32_t base = smb + (uint32_t)buf * 49152u;
        #pragma unroll
        for (int p = 0; p < 2; p++) {
            const __half* Asrc = p ? Al : Ah;
            uint32_t abase = base + (p ? 16384u : 0u);
            #pragma unroll
            for (int it = 0; it < 4; it++) {
                int u = tid + it * 256, row = u >> 3, seg = u & 7;
                int grow = r0 + row;
                uint32_t sz = (grow < NND) ? 16u : 0u;
                CP_ASYNC16(abase + (uint32_t)row * 128
                           + ((uint32_t)(seg ^ (row & 7)) << 4),
                           Asrc + (size_t)(grow < NND ? grow : 0) * K + ch * 64 + seg * 8,
                           sz);
            }
        }
        #pragma unroll
        for (int it = 0; it < 4; it++) {
            int u = tid + it * 256, row = u >> 3, seg = u & 7;
            CP_ASYNC16(base + 32768u + (uint32_t)row * 128
                       + ((uint32_t)(seg ^ (row & 7)) << 4),
                       B + (size_t)(c0 + row) * K + ch * 64 + seg * 8, 16u);
        }
        CP_COMMIT();
    };

    auto mma_chunk = [&](int buf) {
        uint32_t base = smb + (uint32_t)buf * 49152u;
        #pragma unroll
        for (int ks = 0; ks < 4; ks++) {
            uint32_t ah[2][4], al[2][4];
            #pragma unroll
            for (int mt = 0; mt < 2; mt++) {
                int lr = warp_m * 32 + mt * 16 + (lane & 15);
                int seg = 2 * ks + (lane >> 4);
                uint32_t off = (uint32_t)lr * 128 + ((uint32_t)(seg ^ (lr & 7)) << 4);
                LDSM4(ah[mt], base + off);
                LDSM4(al[mt], base + 16384u + off);
            }
            #pragma unroll
            for (int nq = 0; nq < 4; nq++) {
                int lrb = warp_n * 64 + nq * 16 + (lane & 7) + ((lane >> 4) << 3);
                int segb = 2 * ks + ((lane >> 3) & 1);
                uint32_t offb = (uint32_t)lrb * 128 + ((uint32_t)(segb ^ (lrb & 7)) << 4);
                uint32_t bh[4];
                LDSM4(bh, base + 32768u + offb);
                #pragma unroll
                for (int mt = 0; mt < 2; mt++) {
                    #pragma unroll
                    for (int sub = 0; sub < 2; sub++) {
                        float* d = c[mt][nq * 2 + sub];
                        mma_h(d, ah[mt], bh + sub * 2);
                        mma_h(d, al[mt], bh + sub * 2);
                    }
                }
            }
        }
    };

    const int nch = K >> 6;
    stage(0, 0);
    for (int ch = 0; ch < nch; ch++) {
        int cur = ch & 1;
        if (ch + 1 < nch) { stage(ch + 1, cur ^ 1); CP_WAIT1(); }
        else             { CP_WAIT0(); }
        __syncthreads();
        mma_chunk(cur);
        __syncthreads();
    }

    #pragma unroll
    for (int mt = 0; mt < 2; mt++) {
        #pragma unroll
        for (int q = 0; q < 8; q++) {
            int col = c0 + warp_n * 64 + q * 8 + (lane & 3) * 2;
            float2 bv = *(const float2*)(bias + col);
            #pragma unroll
            for (int half = 0; half < 2; half++) {
                int lr = warp_m * 32 + mt * 16 + (lane >> 2) + half * 8;
                int orow = r0 + lr;
                if (orow < NND) {
                    float v0 = c[mt][q][half * 2 + 0] + bv.x;
                    float v1 = c[mt][q][half * 2 + 1] + bv.y;
                    if (act == 2) { v0 = fmaxf(v0, 0.f); v1 = fmaxf(v1, 0.f); }
                    if (outf)
                        *(float2*)(outf + (size_t)orow * N + col) = make_float2(v0, v1);
                    if (outh) {
                        uint32_t hp, lp;
                        split2(v0, v1, hp, lp);
                        *(uint32_t*)(outh + (size_t)orow * N + col) = hp;
                        *(uint32_t*)(outl + (size_t)orow * N + col) = lp;
                    }
                }
            }
        }
    }
}

// ---------------------------------------------------------------------------
extern "C" void kernel_launch(void* const* d_in, const int* in_sizes, int n_in,
                              void* d_out, int out_size)
{
    const float* h   = (const float*)d_in[0];
    const int*   src = (const int*)  d_in[1];
    const int*   dst = (const int*)  d_in[2];
    const int*   r   = (const int*)  d_in[3];
    const int*   inv = (const int*)  d_in[4];
    const float* iW1 = (const float*)d_in[5];
    const float* ib1 = (const float*)d_in[6];
    const float* iW2 = (const float*)d_in[7];
    const float* ib2 = (const float*)d_in[8];
    const float* iW3 = (const float*)d_in[9];
    const float* ib3 = (const float*)d_in[10];
    const float* aW1 = (const float*)d_in[11];
    const float* ab1 = (const float*)d_in[12];
    const float* aW2 = (const float*)d_in[13];
    const float* ab2 = (const float*)d_in[14];
    const float* aW3 = (const float*)d_in[15];
    const float* ab3 = (const float*)d_in[16];
    const float* pW1 = (const float*)d_in[17];
    const float* pb1 = (const float*)d_in[18];
    const float* pW2 = (const float*)d_in[19];
    const float* pb2 = (const float*)d_in[20];
    float* out = (float*)d_out;

    float *tinv;
    int *invidx, *ninv;
    cudaGetSymbolAddress((void**)&tinv, g_tinv);
    cudaGetSymbolAddress((void**)&invidx, g_invidx);
    cudaGetSymbolAddress((void**)&ninv, g_ninv);

    __half *xh,*xl,*sh,*sl;
    cudaGetSymbolAddress((void**)&xh, g_xh); cudaGetSymbolAddress((void**)&xl, g_xl);
    cudaGetSymbolAddress((void**)&sh, g_sh); cudaGetSymbolAddress((void**)&sl, g_sl);

    __half *wi1,*wi2,*wi3,*wa1,*wa2,*wa3,*wp1,*wp2;
    cudaGetSymbolAddress((void**)&wi1, g_iW1);
    cudaGetSymbolAddress((void**)&wi2, g_iW2);
    cudaGetSymbolAddress((void**)&wi3, g_iW3);
    cudaGetSymbolAddress((void**)&wa1, g_aW1);
    cudaGetSymbolAddress((void**)&wa2, g_aW2);
    cudaGetSymbolAddress((void**)&wa3, g_aW3);
    cudaGetSymbolAddress((void**)&wp1, g_pW1);
    cudaGetSymbolAddress((void**)&wp2, g_pW2);

    const int SMEM_F = 164864;   // fused MLP
    const int SMEM_G = 98304;    // proj gemm (2 CTAs/SM)
    cudaFuncSetAttribute(mlp3_fused, cudaFuncAttributeMaxDynamicSharedMemorySize, SMEM_F);
    cudaFuncSetAttribute(gemm_f16,   cudaFuncAttributeMaxDynamicSharedMemorySize, SMEM_G);

    const int NB = (NND + 127) / 128;   // 391
    dim3 g256(NB, 2);

    zero_kernel<<<196, 256>>>();
    prep_all<<<1152, 256>>>(iW1, iW2, iW3, aW1, aW2, aW3, pW1, pW2);
    conv_split<<<6250, 256>>>(h, xh, xl);
    hist_kernel<<<(EE + 255) / 256, 256>>>(dst, inv);
    scan_kernel<<<1, 1024>>>();
    fill_kernel<<<(EE + 255) / 256, 256>>>(src, dst, r);

    // tinv = MLP_inv(h)  (fp32 out for gather)
    mlp3_fused<<<NB, 256, SMEM_F>>>(xh, xl, wi1, ib1, wi2, ib2, wi3, ib3,
                                    tinv, 0, 0, 0, 0, 0);
    // neigh mean via CSR gather -> split fp16 directly
    gather_kernel<<<6250, 256>>>(h, sh, sl);
    // res = MLP_and(neigh) -> res2 buffer (xh/xl)
    mlp3_fused<<<NB, 256, SMEM_F>>>(sh, sl, wa1, ab1, wa2, ab2, wa3, ab3,
                                    0, xh, xl, 0, 0, 0);
    // res2[invidx] = MLP_inv(res[invidx])  (compact ~25k rows)
    mlp3_fused<<<NB, 256, SMEM_F>>>(xh, xl, wi1, ib1, wi2, ib2, wi3, ib3,
                                    0, xh, xl, invidx, invidx, ninv);
    // proj head (hidden reuses sh/sl)
    gemm_f16<<<g256, 256, SMEM_G>>>(xh, xl, wp1, pb1, 256, 256, 2, 0, sh, sl);
    gemm_f16<<<g256, 256, SMEM_G>>>(sh, sl, wp2, pb2, 256, 256, 0, out, 0, 0);
}

// round 13
// speedup vs baseline: 7.2102x; 1.0733x over previous
#include <cuda_runtime.h>
#include <cuda_fp16.h>
#include <cstdint>

#define NND 50000
#define NP  50048              // padded to 391*128
#define EE  800000

// ---------------------------------------------------------------------------
// Scratch (device globals; no allocations anywhere)
__device__ int   g_hist[NND];
__device__ int   g_rowptr[NND + 1];
__device__ int   g_cursor[NND];
__device__ uint32_t g_edges[EE];             // src | (r==1)<<31, CSR order by dst
__device__ int   g_invidx[NND];
__device__ int   g_ninv;

// fp16 message buffer: tinv hi (MLP_inv(h) rounded to fp16)
__device__ __align__(16) __half g_th[(size_t)NP * 256];

// split-fp16 activation buffers
__device__ __align__(16) __half g_xh[(size_t)NP * 256], g_xl[(size_t)NP * 256];
__device__ __align__(16) __half g_sh[(size_t)NP * 256], g_sl[(size_t)NP * 256];

// Pre-transposed fp16 weights (hi only): Wt[n][k] = W[k][n]
__device__ __align__(16) __half g_iW1[128*256];
__device__ __align__(16) __half g_iW2[128*128];
__device__ __align__(16) __half g_iW3[256*128];
__device__ __align__(16) __half g_aW1[128*256];
__device__ __align__(16) __half g_aW2[128*128];
__device__ __align__(16) __half g_aW3[256*128];
__device__ __align__(16) __half g_pW1[256*256];
__device__ __align__(16) __half g_pW2[256*256];

// ---------------------------------------------------------------------------
__device__ __forceinline__ uint32_t smem_u32_of(const void* p) {
    uint32_t a;
    asm("{ .reg .u64 t; cvta.to.shared.u64 t, %1; cvt.u32.u64 %0, t; }"
        : "=r"(a) : "l"(p));
    return a;
}
#define LDSM4(r, addr)                                                         \
    asm volatile("ldmatrix.sync.aligned.m8n8.x4.shared.b16 {%0,%1,%2,%3}, [%4];" \
        : "=r"((r)[0]), "=r"((r)[1]), "=r"((r)[2]), "=r"((r)[3]) : "r"(addr))
#define CP_ASYNC16(dst, src, sz)                                               \
    asm volatile("cp.async.cg.shared.global [%0], [%1], 16, %2;"               \
        :: "r"(dst), "l"(src), "r"(sz) : "memory")
#define CP_COMMIT() asm volatile("cp.async.commit_group;" ::: "memory")
#define CP_WAIT1()  asm volatile("cp.async.wait_group 1;" ::: "memory")
#define CP_WAIT0()  asm volatile("cp.async.wait_group 0;" ::: "memory")

__device__ __forceinline__ void mma_h(float* d, const uint32_t* a,
                                      const uint32_t* b) {
    asm volatile("mma.sync.aligned.m16n8k16.row.col.f32.f16.f16.f32 "
        "{%0,%1,%2,%3}, {%4,%5,%6,%7}, {%8,%9}, {%0,%1,%2,%3};"
        : "+f"(d[0]), "+f"(d[1]), "+f"(d[2]), "+f"(d[3])
        : "r"(a[0]), "r"(a[1]), "r"(a[2]), "r"(a[3]), "r"(b[0]), "r"(b[1]));
}
__device__ __forceinline__ uint32_t packh2(float a, float b) {
    __half x = __float2half_rn(a), y = __float2half_rn(b);
    return (uint32_t)__half_as_ushort(x) | ((uint32_t)__half_as_ushort(y) << 16);
}
__device__ __forceinline__ void split2(float v0, float v1,
                                       uint32_t& hp, uint32_t& lp) {
    __half h0 = __float2half_rn(v0), h1 = __float2half_rn(v1);
    hp = (uint32_t)__half_as_ushort(h0) | ((uint32_t)__half_as_ushort(h1) << 16);
    lp = packh2(v0 - __half2float(h0), v1 - __half2float(h1));
}

// ---------------------------------------------------------------------------
__global__ void zero_kernel() {
    int i = blockIdx.x * blockDim.x + threadIdx.x;
    if (i < NND) g_hist[i] = 0;
    if (i == 0) g_ninv = 0;
}

// hist on dst + inv compaction in one launch
__global__ void hist_kernel(const int* __restrict__ dst,
                            const int* __restrict__ inv) {
    int e = blockIdx.x * blockDim.x + threadIdx.x;
    if (e < EE) atomicAdd(&g_hist[__ldg(dst + e)], 1);
    if (e < NND && __ldg(inv + e) == 1) {
        int p = atomicAdd(&g_ninv, 1);
        g_invidx[p] = e;
    }
}

__global__ __launch_bounds__(1024, 1) void scan_kernel() {
    __shared__ int warp_sums[32];
    __shared__ int s_carry;
    int tid = threadIdx.x, lane = tid & 31, w = tid >> 5;
    if (tid == 0) s_carry = 0;
    __syncthreads();
    for (int base = 0; base < NND; base += 1024) {
        int i = base + tid;
        int v = (i < NND) ? g_hist[i] : 0;
        int x = v;
        #pragma unroll
        for (int o = 1; o < 32; o <<= 1) {
            int t = __shfl_up_sync(0xFFFFFFFFu, x, o);
            if (lane >= o) x += t;
        }
        if (lane == 31) warp_sums[w] = x;
        __syncthreads();
        if (w == 0) {
            int y = warp_sums[lane];
            #pragma unroll
            for (int o = 1; o < 32; o <<= 1) {
                int t = __shfl_up_sync(0xFFFFFFFFu, y, o);
                if (lane >= o) y += t;
            }
            warp_sums[lane] = y;
        }
        __syncthreads();
        int excl = s_carry + x - v + (w > 0 ? warp_sums[w - 1] : 0);
        if (i < NND) { g_rowptr[i] = excl; g_cursor[i] = excl; }
        __syncthreads();
        if (tid == 0) s_carry += warp_sums[31];
        __syncthreads();
    }
    if (tid == 0) g_rowptr[NND] = s_carry;
}

__global__ void fill_kernel(const int* __restrict__ src,
                            const int* __restrict__ dst,
                            const int* __restrict__ r) {
    int e = blockIdx.x * blockDim.x + threadIdx.x;
    if (e >= EE) return;
    int d = __ldg(dst + e);
    int pos = atomicAdd(&g_cursor[d], 1);
    g_edges[pos] = (uint32_t)__ldg(src + e)
                 | ((uint32_t)(__ldg(r + e) == 1) << 31);
}

// ---- gather-mean over fp16 messages: warp per node; emits split fp16 ----
__global__ __launch_bounds__(256) void gather_kernel(
    const __half* __restrict__ xh, const __half* __restrict__ th,
    __half* __restrict__ oh, __half* __restrict__ ol)
{
    int wid = (blockIdx.x * 256 + threadIdx.x) >> 5;
    int lane = threadIdx.x & 31;
    if (wid >= NND) return;
    int beg = __ldg(&g_rowptr[wid]), end = __ldg(&g_rowptr[wid + 1]);
    float acc[8];
    #pragma unroll
    for (int j = 0; j < 8; j++) acc[j] = 0.f;
    int e = beg;
    uint32_t pn = (e < end) ? __ldg(&g_edges[e]) : 0u;
    for (; e < end; e++) {
        uint32_t p = pn;
        if (e + 1 < end) pn = __ldg(&g_edges[e + 1]);
        const uint4* row = (const uint4*)(((p >> 31) ? th : xh)
                          + (size_t)(p & 0x7FFFFFFFu) * 256) + lane;
        uint4 w = __ldg(row);
        const uint32_t ww[4] = {w.x, w.y, w.z, w.w};
        #pragma unroll
        for (int j = 0; j < 4; j++) {
            float2 f = __half22float2(*(const __half2*)&ww[j]);
            acc[2*j]   += f.x;
            acc[2*j+1] += f.y;
        }
    }
    float sc = 1.f / fmaxf((float)(end - beg), 1.f);
    uint4 hp, lp;
    uint32_t* hq = (uint32_t*)&hp; uint32_t* lq = (uint32_t*)&lp;
    #pragma unroll
    for (int j = 0; j < 4; j++)
        split2(acc[2*j] * sc, acc[2*j+1] * sc, hq[j], lq[j]);
    *(uint4*)(oh + (size_t)wid * 256 + lane * 8) = hp;
    *(uint4*)(ol + (size_t)wid * 256 + lane * 8) = lp;
}

// All 8 weight transposes (fp16 hi only) in one launch
__global__ void prep_all(const float* W0, const float* W1, const float* W2,
                         const float* W3, const float* W4, const float* W5,
                         const float* W6, const float* W7) {
    int i = blockIdx.x * blockDim.x + threadIdx.x;
    if (i >= 294912) return;
    const int cum[9]  = {0, 32768, 49152, 81920, 114688, 131072, 163840, 229376, 294912};
    const int Ks[8]   = {256, 128, 128, 256, 128, 128, 256, 256};
    const int Ns[8]   = {128, 128, 256, 128, 128, 256, 256, 256};
    int m = 0;
    #pragma unroll
    for (int t = 1; t < 8; t++) if (i >= cum[t]) m = t;
    int j = i - cum[m], K = Ks[m], N = Ns[m];
    int n = j / K, k = j % K;
    const float* W; __half* Th;
    switch (m) {
        case 0: W = W0; Th = g_iW1; break;
        case 1: W = W1; Th = g_iW2; break;
        case 2: W = W2; Th = g_iW3; break;
        case 3: W = W3; Th = g_aW1; break;
        case 4: W = W4; Th = g_aW2; break;
        case 5: W = W5; Th = g_aW3; break;
        case 6: W = W6; Th = g_pW1; break;
        default: W = W7; Th = g_pW2; break;
    }
    Th[j] = __float2half_rn(W[(size_t)k * N + n]);
}

// fp32 [NND x 256] -> split fp16
__global__ void conv_split(const float* __restrict__ x,
                           __half* __restrict__ oh, __half* __restrict__ ol) {
    int u = blockIdx.x * blockDim.x + threadIdx.x;
    if (u >= NND * 32) return;
    int row = u >> 5, seg = u & 31;
    const float4* s = (const float4*)(x + (size_t)row * 256 + seg * 8);
    float4 a = s[0], b = s[1];
    float v[8] = {a.x, a.y, a.z, a.w, b.x, b.y, b.z, b.w};
    uint4 hp, lp;
    uint32_t* hq = (uint32_t*)&hp; uint32_t* lq = (uint32_t*)&lp;
    #pragma unroll
    for (int j = 0; j < 4; j++) split2(v[2*j], v[2*j+1], hq[j], lq[j]);
    *(uint4*)(oh + (size_t)row * 256 + seg * 8) = hp;
    *(uint4*)(ol + (size_t)row * 256 + seg * 8) = lp;
}

// ---------------------------------------------------------------------------
// Fused 3-layer MLP (fp16 2-term split): 256 ->(leaky) 128 ->(leaky) 128 -> 256
// SMEM map (bytes, rel. smb):
//   buf0 @0      : AH@0  AL@16384  B@32768      (48KB)
//   buf1 @49152  : AH    AL        B            (48KB)
//   inter @98304 : hi ch0, hi ch1 @114688, lo ch0 @131072, lo ch1 @147456
//   idx   @163840: sidx_in[128], sidx_out[128]      -> total 164864
__global__ __launch_bounds__(256, 1) void mlp3_fused(
    const __half* __restrict__ Ah, const __half* __restrict__ Al,
    const __half* __restrict__ W1, const float* __restrict__ b1,
    const __half* __restrict__ W2, const float* __restrict__ b2,
    const __half* __restrict__ W3, const float* __restrict__ b3,
    __half* __restrict__ outh, __half* __restrict__ outl,
    const int* __restrict__ gin, const int* __restrict__ gout,
    const int* __restrict__ nrowp)
{
    extern __shared__ char sm[];
    const uint32_t smb = smem_u32_of(sm);
    const int tid = threadIdx.x, lane = tid & 31, warp = tid >> 5;
    const int warp_m = warp & 3, warp_n = warp >> 2;
    const int r0 = blockIdx.x * 128;
    const uint32_t S = smb;
    const uint32_t IH0 = smb + 98304u, IH1 = smb + 114688u;
    const uint32_t IL0 = smb + 131072u, IL1 = smb + 147456u;

    const int nrow = nrowp ? __ldg(nrowp) : NND;
    if (r0 >= nrow) return;

    int* sidx_in  = (int*)(sm + 163840);
    int* sidx_out = (int*)(sm + 164352);
    for (int i = tid; i < 128; i += 256) {
        int gr = r0 + i;
        bool ok = gr < nrow;
        sidx_in[i]  = ok ? (gin  ? __ldg(gin  + gr) : gr) : -1;
        sidx_out[i] = ok ? (gout ? __ldg(gout + gr) : gr) : -1;
    }
    __syncthreads();

    float c[2][8][4];
    auto zero_c = [&]() {
        #pragma unroll
        for (int i = 0; i < 2; i++)
            #pragma unroll
            for (int j = 0; j < 8; j++)
                #pragma unroll
                for (int k = 0; k < 4; k++) c[i][j][k] = 0.f;
    };

    auto stageA = [&](const __half* src, uint32_t dstb, int k0) {
        #pragma unroll
        for (int it = 0; it < 4; it++) {
            int u = tid + it * 256, row = u >> 3, seg = u & 7;
            int grow = sidx_in[row];
            uint32_t sz = (grow >= 0) ? 16u : 0u;
            const void* sp = src + (size_t)(grow >= 0 ? grow : 0) * 256 + k0 + seg * 8;
            CP_ASYNC16(dstb + (uint32_t)row * 128 + ((uint32_t)(seg ^ (row & 7)) << 4),
                       sp, sz);
        }
    };
    auto stageB = [&](const __half* src, uint32_t dstb, int rows, int K, int k0) {
        for (int u = tid; u < rows * 8; u += 256) {
            int row = u >> 3, seg = u & 7;
            CP_ASYNC16(dstb + (uint32_t)row * 128 + ((uint32_t)(seg ^ (row & 7)) << 4),
                       src + (size_t)row * K + k0 + seg * 8, 16u);
        }
    };

    auto mma_chunk = [&](uint32_t AHb, uint32_t ALb, uint32_t Bb) {
        #pragma unroll
        for (int ks = 0; ks < 4; ks++) {
            uint32_t ah[2][4], al[2][4];
            #pragma unroll
            for (int mt = 0; mt < 2; mt++) {
                int lr = warp_m * 32 + mt * 16 + (lane & 15);
                int seg = 2 * ks + (lane >> 4);
                uint32_t off = (uint32_t)lr * 128 + ((uint32_t)(seg ^ (lr & 7)) << 4);
                LDSM4(ah[mt], AHb + off);
                LDSM4(al[mt], ALb + off);
            }
            #pragma unroll
            for (int nq = 0; nq < 4; nq++) {
                int lrb = warp_n * 64 + nq * 16 + (lane & 7) + ((lane >> 4) << 3);
                int segb = 2 * ks + ((lane >> 3) & 1);
                uint32_t offb = (uint32_t)lrb * 128 + ((uint32_t)(segb ^ (lrb & 7)) << 4);
                uint32_t bh[4];
                LDSM4(bh, Bb + offb);
                #pragma unroll
                for (int mt = 0; mt < 2; mt++) {
                    #pragma unroll
                    for (int sub = 0; sub < 2; sub++) {
                        float* d = c[mt][nq * 2 + sub];
                        mma_h(d, ah[mt], bh + sub * 2);
                        mma_h(d, al[mt], bh + sub * 2);
                    }
                }
            }
        }
    };

    auto epi_smem = [&](const float* __restrict__ bias) {
        #pragma unroll
        for (int mt = 0; mt < 2; mt++) {
            #pragma unroll
            for (int q = 0; q < 8; q++) {
                int col = warp_n * 64 + q * 8 + (lane & 3) * 2;
                float2 bv = *(const float2*)(bias + col);
                uint32_t chb = ((col >> 6) ? IH1 : IH0);
                int cc = col & 63;
                #pragma unroll
                for (int half = 0; half < 2; half++) {
                    int lr = warp_m * 32 + mt * 16 + (lane >> 2) + half * 8;
                    float v0 = c[mt][q][half * 2 + 0] + bv.x;
                    float v1 = c[mt][q][half * 2 + 1] + bv.y;
                    v0 = (v0 >= 0.f) ? v0 : 0.01f * v0;
                    v1 = (v1 >= 0.f) ? v1 : 0.01f * v1;
                    uint32_t hp, lp;
                    split2(v0, v1, hp, lp);
                    uint32_t addr = chb + (uint32_t)lr * 128
                                  + ((uint32_t)((cc >> 3) ^ (lr & 7)) << 4)
                                  + (uint32_t)(cc & 7) * 2;
                    asm volatile("st.shared.b32 [%0], %1;" :: "r"(addr), "r"(hp) : "memory");
                    asm volatile("st.shared.b32 [%0], %1;" :: "r"(addr + 32768u), "r"(lp) : "memory");
                }
            }
        }
    };

    // ---- Layer 1: K=256, 4 chunks, double-buffered (48KB bufs) ----
    zero_c();
    {
        auto stage1 = [&](int ch, int buf) {
            uint32_t base = S + (uint32_t)buf * 49152u;
            stageA(Ah, base, ch * 64);
            stageA(Al, base + 16384u, ch * 64);
            stageB(W1, base + 32768u, 128, 256, ch * 64);
            CP_COMMIT();
        };
        stage1(0, 0);
        for (int ch = 0; ch < 4; ch++) {
            int cur = ch & 1;
            if (ch + 1 < 4) {
                stage1(ch + 1, cur ^ 1);
                CP_WAIT1();
            } else {
                stageB(W2, S + 0u,     128, 128, 0);
                stageB(W2, S + 16384u, 128, 128, 64);
                CP_COMMIT();
                CP_WAIT1();
            }
            __syncthreads();
            uint32_t base = S + (uint32_t)cur * 49152u;
            mma_chunk(base, base + 16384u, base + 32768u);
            __syncthreads();
        }
    }
    stageB(W3, S + 32768u, 256, 128, 0);
    stageB(W3, S + 65536u, 256, 128, 64);
    CP_COMMIT();
    epi_smem(b1);
    CP_WAIT1();
    __syncthreads();

    // ---- Layer 2: K=128, A = inter, B = W2 ----
    zero_c();
    mma_chunk(IH0, IL0, S + 0u);
    mma_chunk(IH1, IL1, S + 16384u);
    __syncthreads();
    epi_smem(b2);
    CP_WAIT0();
    __syncthreads();

    // ---- Layer 3: K=128, N=256 (two column halves), linear ----
    #pragma unroll
    for (int hf = 0; hf < 2; hf++) {
        zero_c();
        mma_chunk(IH0, IL0, S + 32768u + (uint32_t)hf * 16384u);
        mma_chunk(IH1, IL1, S + 65536u + (uint32_t)hf * 16384u);
        #pragma unroll
        for (int mt = 0; mt < 2; mt++) {
            #pragma unroll
            for (int q = 0; q < 8; q++) {
                int col = hf * 128 + warp_n * 64 + q * 8 + (lane & 3) * 2;
                float2 bv = *(const float2*)(b3 + col);
                #pragma unroll
                for (int half = 0; half < 2; half++) {
                    int lr = warp_m * 32 + mt * 16 + (lane >> 2) + half * 8;
                    int orow = sidx_out[lr];
                    if (orow >= 0) {
                        float v0 = c[mt][q][half * 2 + 0] + bv.x;
                        float v1 = c[mt][q][half * 2 + 1] + bv.y;
                        uint32_t hp, lp;
                        split2(v0, v1, hp, lp);
                        *(uint32_t*)(outh + (size_t)orow * 256 + col) = hp;
                        if (outl)
                            *(uint32_t*)(outl + (size_t)orow * 256 + col) = lp;
                    }
                }
            }
        }
    }
}

// ---------------------------------------------------------------------------
// Generic split-fp16 GEMM (proj head), double-buffered 48KB bufs, 2 CTAs/SM.
__global__ __launch_bounds__(256, 2) void gemm_f16(
    const __half* __restrict__ Ah, const __half* __restrict__ Al,
    const __half* __restrict__ B,
    const float* __restrict__ bias, int K, int N, int act,
    float* __restrict__ outf,
    __half* __restrict__ outh, __half* __restrict__ outl)
{
    extern __shared__ char sm[];
    const uint32_t smb = smem_u32_of(sm);
    const int tid = threadIdx.x, lane = tid & 31, warp = tid >> 5;
    const int warp_m = warp & 3, warp_n = warp >> 2;
    const int r0 = blockIdx.x * 128;
    const int c0 = blockIdx.y * 128;

    float c[2][8][4];
    #pragma unroll
    for (int i = 0; i < 2; i++)
        #pragma unroll
        for (int j = 0; j < 8; j++)
            #pragma unroll
            for (int k = 0; k < 4; k++) c[i][j][k] = 0.f;

    auto stage = [&](int ch, int buf) {
        uint32_t base = smb + (uint32_t)buf * 49152u;
        #pragma unroll
        for (int p = 0; p < 2; p++) {
            const __half* Asrc = p ? Al : Ah;
            uint32_t abase = base + (p ? 16384u : 0u);
            #pragma unroll
            for (int it = 0; it < 4; it++) {
                int u = tid + it * 256, row = u >> 3, seg = u & 7;
                int grow = r0 + row;
                uint32_t sz = (grow < NND) ? 16u : 0u;
                CP_ASYNC16(abase + (uint32_t)row * 128
                           + ((uint32_t)(seg ^ (row & 7)) << 4),
                           Asrc + (size_t)(grow < NND ? grow : 0) * K + ch * 64 + seg * 8,
                           sz);
            }
        }
        #pragma unroll
        for (int it = 0; it < 4; it++) {
            int u = tid + it * 256, row = u >> 3, seg = u & 7;
            CP_ASYNC16(base + 32768u + (uint32_t)row * 128
                       + ((uint32_t)(seg ^ (row & 7)) << 4),
                       B + (size_t)(c0 + row) * K + ch * 64 + seg * 8, 16u);
        }
        CP_COMMIT();
    };

    auto mma_chunk = [&](int buf) {
        uint32_t base = smb + (uint32_t)buf * 49152u;
        #pragma unroll
        for (int ks = 0; ks < 4; ks++) {
            uint32_t ah[2][4], al[2][4];
            #pragma unroll
            for (int mt = 0; mt < 2; mt++) {
                int lr = warp_m * 32 + mt * 16 + (lane & 15);
                int seg = 2 * ks + (lane >> 4);
                uint32_t off = (uint32_t)lr * 128 + ((uint32_t)(seg ^ (lr & 7)) << 4);
                LDSM4(ah[mt], base + off);
                LDSM4(al[mt], base + 16384u + off);
            }
            #pragma unroll
            for (int nq = 0; nq < 4; nq++) {
                int lrb = warp_n * 64 + nq * 16 + (lane & 7) + ((lane >> 4) << 3);
                int segb = 2 * ks + ((lane >> 3) & 1);
                uint32_t offb = (uint32_t)lrb * 128 + ((uint32_t)(segb ^ (lrb & 7)) << 4);
                uint32_t bh[4];
                LDSM4(bh, base + 32768u + offb);
                #pragma unroll
                for (int mt = 0; mt < 2; mt++) {
                    #pragma unroll
                    for (int sub = 0; sub < 2; sub++) {
                        float* d = c[mt][nq * 2 + sub];
                        mma_h(d, ah[mt], bh + sub * 2);
                        mma_h(d, al[mt], bh + sub * 2);
                    }
                }
            }
        }
    };

    const int nch = K >> 6;
    stage(0, 0);
    for (int ch = 0; ch < nch; ch++) {
        int cur = ch & 1;
        if (ch + 1 < nch) { stage(ch + 1, cur ^ 1); CP_WAIT1(); }
        else             { CP_WAIT0(); }
        __syncthreads();
        mma_chunk(cur);
        __syncthreads();
    }

    #pragma unroll
    for (int mt = 0; mt < 2; mt++) {
        #pragma unroll
        for (int q = 0; q < 8; q++) {
            int col = c0 + warp_n * 64 + q * 8 + (lane & 3) * 2;
            float2 bv = *(const float2*)(bias + col);
            #pragma unroll
            for (int half = 0; half < 2; half++) {
                int lr = warp_m * 32 + mt * 16 + (lane >> 2) + half * 8;
                int orow = r0 + lr;
                if (orow < NND) {
                    float v0 = c[mt][q][half * 2 + 0] + bv.x;
                    float v1 = c[mt][q][half * 2 + 1] + bv.y;
                    if (act == 2) { v0 = fmaxf(v0, 0.f); v1 = fmaxf(v1, 0.f); }
                    if (outf)
                        *(float2*)(outf + (size_t)orow * N + col) = make_float2(v0, v1);
                    if (outh) {
                        uint32_t hp, lp;
                        split2(v0, v1, hp, lp);
                        *(uint32_t*)(outh + (size_t)orow * N + col) = hp;
                        *(uint32_t*)(outl + (size_t)orow * N + col) = lp;
                    }
                }
            }
        }
    }
}

// ---------------------------------------------------------------------------
extern "C" void kernel_launch(void* const* d_in, const int* in_sizes, int n_in,
                              void* d_out, int out_size)
{
    const float* h   = (const float*)d_in[0];
    const int*   src = (const int*)  d_in[1];
    const int*   dst = (const int*)  d_in[2];
    const int*   r   = (const int*)  d_in[3];
    const int*   inv = (const int*)  d_in[4];
    const float* iW1 = (const float*)d_in[5];
    const float* ib1 = (const float*)d_in[6];
    const float* iW2 = (const float*)d_in[7];
    const float* ib2 = (const float*)d_in[8];
    const float* iW3 = (const float*)d_in[9];
    const float* ib3 = (const float*)d_in[10];
    const float* aW1 = (const float*)d_in[11];
    const float* ab1 = (const float*)d_in[12];
    const float* aW2 = (const float*)d_in[13];
    const float* ab2 = (const float*)d_in[14];
    const float* aW3 = (const float*)d_in[15];
    const float* ab3 = (const float*)d_in[16];
    const float* pW1 = (const float*)d_in[17];
    const float* pb1 = (const float*)d_in[18];
    const float* pW2 = (const float*)d_in[19];
    const float* pb2 = (const float*)d_in[20];
    float* out = (float*)d_out;

    int *invidx, *ninv;
    cudaGetSymbolAddress((void**)&invidx, g_invidx);
    cudaGetSymbolAddress((void**)&ninv, g_ninv);

    __half *th,*xh,*xl,*sh,*sl;
    cudaGetSymbolAddress((void**)&th, g_th);
    cudaGetSymbolAddress((void**)&xh, g_xh); cudaGetSymbolAddress((void**)&xl, g_xl);
    cudaGetSymbolAddress((void**)&sh, g_sh); cudaGetSymbolAddress((void**)&sl, g_sl);

    __half *wi1,*wi2,*wi3,*wa1,*wa2,*wa3,*wp1,*wp2;
    cudaGetSymbolAddress((void**)&wi1, g_iW1);
    cudaGetSymbolAddress((void**)&wi2, g_iW2);
    cudaGetSymbolAddress((void**)&wi3, g_iW3);
    cudaGetSymbolAddress((void**)&wa1, g_aW1);
    cudaGetSymbolAddress((void**)&wa2, g_aW2);
    cudaGetSymbolAddress((void**)&wa3, g_aW3);
    cudaGetSymbolAddress((void**)&wp1, g_pW1);
    cudaGetSymbolAddress((void**)&wp2, g_pW2);

    const int SMEM_F = 164864;   // fused MLP
    const int SMEM_G = 98304;    // proj gemm (2 CTAs/SM)
    cudaFuncSetAttribute(mlp3_fused, cudaFuncAttributeMaxDynamicSharedMemorySize, SMEM_F);
    cudaFuncSetAttribute(gemm_f16,   cudaFuncAttributeMaxDynamicSharedMemorySize, SMEM_G);

    const int NB = (NND + 127) / 128;   // 391
    dim3 g256(NB, 2);

    zero_kernel<<<196, 256>>>();
    prep_all<<<1152, 256>>>(iW1, iW2, iW3, aW1, aW2, aW3, pW1, pW2);
    conv_split<<<6250, 256>>>(h, xh, xl);
    hist_kernel<<<(EE + 255) / 256, 256>>>(dst, inv);
    scan_kernel<<<1, 1024>>>();
    fill_kernel<<<(EE + 255) / 256, 256>>>(src, dst, r);

    // th = fp16(MLP_inv(h))  (fp16-hi message for gather)
    mlp3_fused<<<NB, 256, SMEM_F>>>(xh, xl, wi1, ib1, wi2, ib2, wi3, ib3,
                                    th, 0, 0, 0, 0);
    // neigh mean over fp16 messages (xh for r==0, th for r==1)
    gather_kernel<<<6250, 256>>>(xh, th, sh, sl);
    // res = MLP_and(neigh) -> res2 buffer (xh/xl)
    mlp3_fused<<<NB, 256, SMEM_F>>>(sh, sl, wa1, ab1, wa2, ab2, wa3, ab3,
                                    xh, xl, 0, 0, 0);
    // res2[invidx] = MLP_inv(res[invidx])  (compact ~25k rows)
    mlp3_fused<<<NB, 256, SMEM_F>>>(xh, xl, wi1, ib1, wi2, ib2, wi3, ib3,
                                    xh, xl, invidx, invidx, ninv);
    // proj head (hidden reuses sh/sl)
    gemm_f16<<<g256, 256, SMEM_G>>>(xh, xl, wp1, pb1, 256, 256, 2, 0, sh, sl);
    gemm_f16<<<g256, 256, SMEM_G>>>(sh, sl, wp2, pb2, 256, 256, 0, out, 0, 0);
}

// round 14
// speedup vs baseline: 8.8298x; 1.2246x over previous
#include <cuda_runtime.h>
#include <cuda_fp16.h>
#include <cstdint>

#define NND 50000
#define NP  50048              // padded to 391*128
#define EE  800000

// ---------------------------------------------------------------------------
// Scratch (device globals; no allocations anywhere)
__device__ int   g_hist[NND];
__device__ int   g_rowptr[NND + 1];
__device__ int   g_cursor[NND];
__device__ uint32_t g_edges[EE];             // src | (r==1)<<31, CSR order by dst
__device__ int   g_invidx[NND];
__device__ int   g_ninv;

// fp16 message buffer: tinv hi (MLP_inv(h) rounded to fp16)
__device__ __align__(16) __half g_th[(size_t)NP * 256];

// split-fp16 activation buffers
__device__ __align__(16) __half g_xh[(size_t)NP * 256], g_xl[(size_t)NP * 256];
__device__ __align__(16) __half g_sh[(size_t)NP * 256], g_sl[(size_t)NP * 256];

// Pre-transposed fp16 weights (hi only): Wt[n][k] = W[k][n]
__device__ __align__(16) __half g_iW1[128*256];
__device__ __align__(16) __half g_iW2[128*128];
__device__ __align__(16) __half g_iW3[256*128];
__device__ __align__(16) __half g_aW1[128*256];
__device__ __align__(16) __half g_aW2[128*128];
__device__ __align__(16) __half g_aW3[256*128];
__device__ __align__(16) __half g_pW1[256*256];
__device__ __align__(16) __half g_pW2[256*256];

// ---------------------------------------------------------------------------
__device__ __forceinline__ uint32_t smem_u32_of(const void* p) {
    uint32_t a;
    asm("{ .reg .u64 t; cvta.to.shared.u64 t, %1; cvt.u32.u64 %0, t; }"
        : "=r"(a) : "l"(p));
    return a;
}
#define LDSM4(r, addr)                                                         \
    asm volatile("ldmatrix.sync.aligned.m8n8.x4.shared.b16 {%0,%1,%2,%3}, [%4];" \
        : "=r"((r)[0]), "=r"((r)[1]), "=r"((r)[2]), "=r"((r)[3]) : "r"(addr))
#define CP_ASYNC16(dst, src, sz)                                               \
    asm volatile("cp.async.cg.shared.global [%0], [%1], 16, %2;"               \
        :: "r"(dst), "l"(src), "r"(sz) : "memory")
#define CP_COMMIT() asm volatile("cp.async.commit_group;" ::: "memory")
#define CP_WAIT1()  asm volatile("cp.async.wait_group 1;" ::: "memory")
#define CP_WAIT0()  asm volatile("cp.async.wait_group 0;" ::: "memory")

__device__ __forceinline__ void mma_h(float* d, const uint32_t* a,
                                      const uint32_t* b) {
    asm volatile("mma.sync.aligned.m16n8k16.row.col.f32.f16.f16.f32 "
        "{%0,%1,%2,%3}, {%4,%5,%6,%7}, {%8,%9}, {%0,%1,%2,%3};"
        : "+f"(d[0]), "+f"(d[1]), "+f"(d[2]), "+f"(d[3])
        : "r"(a[0]), "r"(a[1]), "r"(a[2]), "r"(a[3]), "r"(b[0]), "r"(b[1]));
}
__device__ __forceinline__ uint32_t packh2(float a, float b) {
    __half x = __float2half_rn(a), y = __float2half_rn(b);
    return (uint32_t)__half_as_ushort(x) | ((uint32_t)__half_as_ushort(y) << 16);
}
__device__ __forceinline__ void split2(float v0, float v1,
                                       uint32_t& hp, uint32_t& lp) {
    __half h0 = __float2half_rn(v0), h1 = __float2half_rn(v1);
    hp = (uint32_t)__half_as_ushort(h0) | ((uint32_t)__half_as_ushort(h1) << 16);
    lp = packh2(v0 - __half2float(h0), v1 - __half2float(h1));
}

// ---------------------------------------------------------------------------
__global__ void zero_kernel() {
    int i = blockIdx.x * blockDim.x + threadIdx.x;
    if (i < NND) g_hist[i] = 0;
    if (i == 0) g_ninv = 0;
}

// hist on dst + inv compaction in one launch
__global__ void hist_kernel(const int* __restrict__ dst,
                            const int* __restrict__ inv) {
    int e = blockIdx.x * blockDim.x + threadIdx.x;
    if (e < EE) atomicAdd(&g_hist[__ldg(dst + e)], 1);
    if (e < NND && __ldg(inv + e) == 1) {
        int p = atomicAdd(&g_ninv, 1);
        g_invidx[p] = e;
    }
}

__global__ __launch_bounds__(1024, 1) void scan_kernel() {
    __shared__ int warp_sums[32];
    __shared__ int s_carry;
    int tid = threadIdx.x, lane = tid & 31, w = tid >> 5;
    if (tid == 0) s_carry = 0;
    __syncthreads();
    for (int base = 0; base < NND; base += 1024) {
        int i = base + tid;
        int v = (i < NND) ? g_hist[i] : 0;
        int x = v;
        #pragma unroll
        for (int o = 1; o < 32; o <<= 1) {
            int t = __shfl_up_sync(0xFFFFFFFFu, x, o);
            if (lane >= o) x += t;
        }
        if (lane == 31) warp_sums[w] = x;
        __syncthreads();
        if (w == 0) {
            int y = warp_sums[lane];
            #pragma unroll
            for (int o = 1; o < 32; o <<= 1) {
                int t = __shfl_up_sync(0xFFFFFFFFu, y, o);
                if (lane >= o) y += t;
            }
            warp_sums[lane] = y;
        }
        __syncthreads();
        int excl = s_carry + x - v + (w > 0 ? warp_sums[w - 1] : 0);
        if (i < NND) { g_rowptr[i] = excl; g_cursor[i] = excl; }
        __syncthreads();
        if (tid == 0) s_carry += warp_sums[31];
        __syncthreads();
    }
    if (tid == 0) g_rowptr[NND] = s_carry;
}

__global__ void fill_kernel(const int* __restrict__ src,
                            const int* __restrict__ dst,
                            const int* __restrict__ r) {
    int e = blockIdx.x * blockDim.x + threadIdx.x;
    if (e >= EE) return;
    int d = __ldg(dst + e);
    int pos = atomicAdd(&g_cursor[d], 1);
    g_edges[pos] = (uint32_t)__ldg(src + e)
                 | ((uint32_t)(__ldg(r + e) == 1) << 31);
}

// ---- gather-mean over fp16 messages: warp per node; emits split fp16 ----
__global__ __launch_bounds__(256) void gather_kernel(
    const __half* __restrict__ xh, const __half* __restrict__ th,
    __half* __restrict__ oh, __half* __restrict__ ol)
{
    int wid = (blockIdx.x * 256 + threadIdx.x) >> 5;
    int lane = threadIdx.x & 31;
    if (wid >= NND) return;
    int beg = __ldg(&g_rowptr[wid]), end = __ldg(&g_rowptr[wid + 1]);
    float acc[8];
    #pragma unroll
    for (int j = 0; j < 8; j++) acc[j] = 0.f;
    int e = beg;
    uint32_t pn = (e < end) ? __ldg(&g_edges[e]) : 0u;
    for (; e < end; e++) {
        uint32_t p = pn;
        if (e + 1 < end) pn = __ldg(&g_edges[e + 1]);
        const uint4* row = (const uint4*)(((p >> 31) ? th : xh)
                          + (size_t)(p & 0x7FFFFFFFu) * 256) + lane;
        uint4 w = __ldg(row);
        const uint32_t ww[4] = {w.x, w.y, w.z, w.w};
        #pragma unroll
        for (int j = 0; j < 4; j++) {
            float2 f = __half22float2(*(const __half2*)&ww[j]);
            acc[2*j]   += f.x;
            acc[2*j+1] += f.y;
        }
    }
    float sc = 1.f / fmaxf((float)(end - beg), 1.f);
    uint4 hp, lp;
    uint32_t* hq = (uint32_t*)&hp; uint32_t* lq = (uint32_t*)&lp;
    #pragma unroll
    for (int j = 0; j < 4; j++)
        split2(acc[2*j] * sc, acc[2*j+1] * sc, hq[j], lq[j]);
    *(uint4*)(oh + (size_t)wid * 256 + lane * 8) = hp;
    *(uint4*)(ol + (size_t)wid * 256 + lane * 8) = lp;
}

// All 8 weight transposes (fp16 hi only) in one launch
__global__ void prep_all(const float* W0, const float* W1, const float* W2,
                         const float* W3, const float* W4, const float* W5,
                         const float* W6, const float* W7) {
    int i = blockIdx.x * blockDim.x + threadIdx.x;
    if (i >= 294912) return;
    const int cum[9]  = {0, 32768, 49152, 81920, 114688, 131072, 163840, 229376, 294912};
    const int Ks[8]   = {256, 128, 128, 256, 128, 128, 256, 256};
    const int Ns[8]   = {128, 128, 256, 128, 128, 256, 256, 256};
    int m = 0;
    #pragma unroll
    for (int t = 1; t < 8; t++) if (i >= cum[t]) m = t;
    int j = i - cum[m], K = Ks[m], N = Ns[m];
    int n = j / K, k = j % K;
    const float* W; __half* Th;
    switch (m) {
        case 0: W = W0; Th = g_iW1; break;
        case 1: W = W1; Th = g_iW2; break;
        case 2: W = W2; Th = g_iW3; break;
        case 3: W = W3; Th = g_aW1; break;
        case 4: W = W4; Th = g_aW2; break;
        case 5: W = W5; Th = g_aW3; break;
        case 6: W = W6; Th = g_pW1; break;
        default: W = W7; Th = g_pW2; break;
    }
    Th[j] = __float2half_rn(W[(size_t)k * N + n]);
}

// fp32 [NND x 256] -> split fp16
__global__ void conv_split(const float* __restrict__ x,
                           __half* __restrict__ oh, __half* __restrict__ ol) {
    int u = blockIdx.x * blockDim.x + threadIdx.x;
    if (u >= NND * 32) return;
    int row = u >> 5, seg = u & 31;
    const float4* s = (const float4*)(x + (size_t)row * 256 + seg * 8);
    float4 a = s[0], b = s[1];
    float v[8] = {a.x, a.y, a.z, a.w, b.x, b.y, b.z, b.w};
    uint4 hp, lp;
    uint32_t* hq = (uint32_t*)&hp; uint32_t* lq = (uint32_t*)&lp;
    #pragma unroll
    for (int j = 0; j < 4; j++) split2(v[2*j], v[2*j+1], hq[j], lq[j]);
    *(uint4*)(oh + (size_t)row * 256 + seg * 8) = hp;
    *(uint4*)(ol + (size_t)row * 256 + seg * 8) = lp;
}

// ---------------------------------------------------------------------------
// Fused 3-layer MLP (fp16 split): 256 ->(leaky) 128 ->(leaky) 128 -> 256
// Al == nullptr => single-term input (L1 uses A-hi only). Inter stays 2-term.
// SMEM map: buf0@0 (48KB: AH,AL,B) buf1@49152, inter@98304 (64KB), idx@163840
__global__ __launch_bounds__(256, 1) void mlp3_fused(
    const __half* __restrict__ Ah, const __half* __restrict__ Al,
    const __half* __restrict__ W1, const float* __restrict__ b1,
    const __half* __restrict__ W2, const float* __restrict__ b2,
    const __half* __restrict__ W3, const float* __restrict__ b3,
    __half* __restrict__ outh, __half* __restrict__ outl,
    const int* __restrict__ gin, const int* __restrict__ gout,
    const int* __restrict__ nrowp)
{
    extern __shared__ char sm[];
    const uint32_t smb = smem_u32_of(sm);
    const int tid = threadIdx.x, lane = tid & 31, warp = tid >> 5;
    const int warp_m = warp & 3, warp_n = warp >> 2;
    const int r0 = blockIdx.x * 128;
    const uint32_t S = smb;
    const uint32_t IH0 = smb + 98304u, IH1 = smb + 114688u;
    const uint32_t IL0 = smb + 131072u, IL1 = smb + 147456u;
    const bool two = (Al != nullptr);

    const int nrow = nrowp ? __ldg(nrowp) : NND;
    if (r0 >= nrow) return;

    int* sidx_in  = (int*)(sm + 163840);
    int* sidx_out = (int*)(sm + 164352);
    for (int i = tid; i < 128; i += 256) {
        int gr = r0 + i;
        bool ok = gr < nrow;
        sidx_in[i]  = ok ? (gin  ? __ldg(gin  + gr) : gr) : -1;
        sidx_out[i] = ok ? (gout ? __ldg(gout + gr) : gr) : -1;
    }
    __syncthreads();

    float c[2][8][4];
    auto zero_c = [&]() {
        #pragma unroll
        for (int i = 0; i < 2; i++)
            #pragma unroll
            for (int j = 0; j < 8; j++)
                #pragma unroll
                for (int k = 0; k < 4; k++) c[i][j][k] = 0.f;
    };

    auto stageA = [&](const __half* src, uint32_t dstb, int k0) {
        #pragma unroll
        for (int it = 0; it < 4; it++) {
            int u = tid + it * 256, row = u >> 3, seg = u & 7;
            int grow = sidx_in[row];
            uint32_t sz = (grow >= 0) ? 16u : 0u;
            const void* sp = src + (size_t)(grow >= 0 ? grow : 0) * 256 + k0 + seg * 8;
            CP_ASYNC16(dstb + (uint32_t)row * 128 + ((uint32_t)(seg ^ (row & 7)) << 4),
                       sp, sz);
        }
    };
    auto stageB = [&](const __half* src, uint32_t dstb, int rows, int K, int k0) {
        for (int u = tid; u < rows * 8; u += 256) {
            int row = u >> 3, seg = u & 7;
            CP_ASYNC16(dstb + (uint32_t)row * 128 + ((uint32_t)(seg ^ (row & 7)) << 4),
                       src + (size_t)row * K + k0 + seg * 8, 16u);
        }
    };

    auto mma_chunk = [&](uint32_t AHb, uint32_t ALb, uint32_t Bb, bool useAL) {
        #pragma unroll
        for (int ks = 0; ks < 4; ks++) {
            uint32_t ah[2][4], al[2][4];
            #pragma unroll
            for (int mt = 0; mt < 2; mt++) {
                int lr = warp_m * 32 + mt * 16 + (lane & 15);
                int seg = 2 * ks + (lane >> 4);
                uint32_t off = (uint32_t)lr * 128 + ((uint32_t)(seg ^ (lr & 7)) << 4);
                LDSM4(ah[mt], AHb + off);
                if (useAL) LDSM4(al[mt], ALb + off);
            }
            #pragma unroll
            for (int nq = 0; nq < 4; nq++) {
                int lrb = warp_n * 64 + nq * 16 + (lane & 7) + ((lane >> 4) << 3);
                int segb = 2 * ks + ((lane >> 3) & 1);
                uint32_t offb = (uint32_t)lrb * 128 + ((uint32_t)(segb ^ (lrb & 7)) << 4);
                uint32_t bh[4];
                LDSM4(bh, Bb + offb);
                #pragma unroll
                for (int mt = 0; mt < 2; mt++) {
                    #pragma unroll
                    for (int sub = 0; sub < 2; sub++) {
                        float* d = c[mt][nq * 2 + sub];
                        mma_h(d, ah[mt], bh + sub * 2);
                        if (useAL) mma_h(d, al[mt], bh + sub * 2);
                    }
                }
            }
        }
    };

    auto epi_smem = [&](const float* __restrict__ bias) {
        #pragma unroll
        for (int mt = 0; mt < 2; mt++) {
            #pragma unroll
            for (int q = 0; q < 8; q++) {
                int col = warp_n * 64 + q * 8 + (lane & 3) * 2;
                float2 bv = *(const float2*)(bias + col);
                uint32_t chb = ((col >> 6) ? IH1 : IH0);
                int cc = col & 63;
                #pragma unroll
                for (int half = 0; half < 2; half++) {
                    int lr = warp_m * 32 + mt * 16 + (lane >> 2) + half * 8;
                    float v0 = c[mt][q][half * 2 + 0] + bv.x;
                    float v1 = c[mt][q][half * 2 + 1] + bv.y;
                    v0 = (v0 >= 0.f) ? v0 : 0.01f * v0;
                    v1 = (v1 >= 0.f) ? v1 : 0.01f * v1;
                    uint32_t hp, lp;
                    split2(v0, v1, hp, lp);
                    uint32_t addr = chb + (uint32_t)lr * 128
                                  + ((uint32_t)((cc >> 3) ^ (lr & 7)) << 4)
                                  + (uint32_t)(cc & 7) * 2;
                    asm volatile("st.shared.b32 [%0], %1;" :: "r"(addr), "r"(hp) : "memory");
                    asm volatile("st.shared.b32 [%0], %1;" :: "r"(addr + 32768u), "r"(lp) : "memory");
                }
            }
        }
    };

    // ---- Layer 1: K=256, 4 chunks, double-buffered ----
    zero_c();
    {
        auto stage1 = [&](int ch, int buf) {
            uint32_t base = S + (uint32_t)buf * 49152u;
            stageA(Ah, base, ch * 64);
            if (two) stageA(Al, base + 16384u, ch * 64);
            stageB(W1, base + 32768u, 128, 256, ch * 64);
            CP_COMMIT();
        };
        stage1(0, 0);
        for (int ch = 0; ch < 4; ch++) {
            int cur = ch & 1;
            if (ch + 1 < 4) {
                stage1(ch + 1, cur ^ 1);
                CP_WAIT1();
            } else {
                stageB(W2, S + 0u,     128, 128, 0);
                stageB(W2, S + 16384u, 128, 128, 64);
                CP_COMMIT();
                CP_WAIT1();
            }
            __syncthreads();
            uint32_t base = S + (uint32_t)cur * 49152u;
            mma_chunk(base, base + 16384u, base + 32768u, two);
            __syncthreads();
        }
    }
    stageB(W3, S + 32768u, 256, 128, 0);
    stageB(W3, S + 65536u, 256, 128, 64);
    CP_COMMIT();
    epi_smem(b1);
    CP_WAIT1();
    __syncthreads();

    // ---- Layer 2: K=128, A = inter, B = W2 ----
    zero_c();
    mma_chunk(IH0, IL0, S + 0u, true);
    mma_chunk(IH1, IL1, S + 16384u, true);
    __syncthreads();
    epi_smem(b2);
    CP_WAIT0();
    __syncthreads();

    // ---- Layer 3: K=128, N=256 (two column halves), linear ----
    #pragma unroll
    for (int hf = 0; hf < 2; hf++) {
        zero_c();
        mma_chunk(IH0, IL0, S + 32768u + (uint32_t)hf * 16384u, true);
        mma_chunk(IH1, IL1, S + 65536u + (uint32_t)hf * 16384u, true);
        #pragma unroll
        for (int mt = 0; mt < 2; mt++) {
            #pragma unroll
            for (int q = 0; q < 8; q++) {
                int col = hf * 128 + warp_n * 64 + q * 8 + (lane & 3) * 2;
                float2 bv = *(const float2*)(b3 + col);
                #pragma unroll
                for (int half = 0; half < 2; half++) {
                    int lr = warp_m * 32 + mt * 16 + (lane >> 2) + half * 8;
                    int orow = sidx_out[lr];
                    if (orow >= 0) {
                        float v0 = c[mt][q][half * 2 + 0] + bv.x;
                        float v1 = c[mt][q][half * 2 + 1] + bv.y;
                        uint32_t hp, lp;
                        split2(v0, v1, hp, lp);
                        *(uint32_t*)(outh + (size_t)orow * 256 + col) = hp;
                        if (outl)
                            *(uint32_t*)(outl + (size_t)orow * 256 + col) = lp;
                    }
                }
            }
        }
    }
}

// ---------------------------------------------------------------------------
// Generic fp16 GEMM (proj head). Al == nullptr => single-term A. 2 CTAs/SM.
__global__ __launch_bounds__(256, 2) void gemm_f16(
    const __half* __restrict__ Ah, const __half* __restrict__ Al,
    const __half* __restrict__ B,
    const float* __restrict__ bias, int K, int N, int act,
    float* __restrict__ outf, __half* __restrict__ outh)
{
    extern __shared__ char sm[];
    const uint32_t smb = smem_u32_of(sm);
    const int tid = threadIdx.x, lane = tid & 31, warp = tid >> 5;
    const int warp_m = warp & 3, warp_n = warp >> 2;
    const int r0 = blockIdx.x * 128;
    const int c0 = blockIdx.y * 128;
    const bool two = (Al != nullptr);

    float c[2][8][4];
    #pragma unroll
    for (int i = 0; i < 2; i++)
        #pragma unroll
        for (int j = 0; j < 8; j++)
            #pragma unroll
            for (int k = 0; k < 4; k++) c[i][j][k] = 0.f;

    auto stage = [&](int ch, int buf) {
        uint32_t base = smb + (uint32_t)buf * 49152u;
        #pragma unroll
        for (int it = 0; it < 4; it++) {
            int u = tid + it * 256, row = u >> 3, seg = u & 7;
            int grow = r0 + row;
            uint32_t sz = (grow < NND) ? 16u : 0u;
            CP_ASYNC16(base + (uint32_t)row * 128
                       + ((uint32_t)(seg ^ (row & 7)) << 4),
                       Ah + (size_t)(grow < NND ? grow : 0) * K + ch * 64 + seg * 8,
                       sz);
        }
        if (two) {
            #pragma unroll
            for (int it = 0; it < 4; it++) {
                int u = tid + it * 256, row = u >> 3, seg = u & 7;
                int grow = r0 + row;
                uint32_t sz = (grow < NND) ? 16u : 0u;
                CP_ASYNC16(base + 16384u + (uint32_t)row * 128
                           + ((uint32_t)(seg ^ (row & 7)) << 4),
                           Al + (size_t)(grow < NND ? grow : 0) * K + ch * 64 + seg * 8,
                           sz);
            }
        }
        #pragma unroll
        for (int it = 0; it < 4; it++) {
            int u = tid + it * 256, row = u >> 3, seg = u & 7;
            CP_ASYNC16(base + 32768u + (uint32_t)row * 128
                       + ((uint32_t)(seg ^ (row & 7)) << 4),
                       B + (size_t)(c0 + row) * K + ch * 64 + seg * 8, 16u);
        }
        CP_COMMIT();
    };

    auto mma_chunk = [&](int buf) {
        uint32_t base = smb + (uint32_t)buf * 49152u;
        #pragma unroll
        for (int ks = 0; ks < 4; ks++) {
            uint32_t ah[2][4], al[2][4];
            #pragma unroll
            for (int mt = 0; mt < 2; mt++) {
                int lr = warp_m * 32 + mt * 16 + (lane & 15);
                int seg = 2 * ks + (lane >> 4);
                uint32_t off = (uint32_t)lr * 128 + ((uint32_t)(seg ^ (lr & 7)) << 4);
                LDSM4(ah[mt], base + off);
                if (two) LDSM4(al[mt], base + 16384u + off);
            }
            #pragma unroll
            for (int nq = 0; nq < 4; nq++) {
                int lrb = warp_n * 64 + nq * 16 + (lane & 7) + ((lane >> 4) << 3);
                int segb = 2 * ks + ((lane >> 3) & 1);
                uint32_t offb = (uint32_t)lrb * 128 + ((uint32_t)(segb ^ (lrb & 7)) << 4);
                uint32_t bh[4];
                LDSM4(bh, base + 32768u + offb);
                #pragma unroll
                for (int mt = 0; mt < 2; mt++) {
                    #pragma unroll
                    for (int sub = 0; sub < 2; sub++) {
                        float* d = c[mt][nq * 2 + sub];
                        mma_h(d, ah[mt], bh + sub * 2);
                        if (two) mma_h(d, al[mt], bh + sub * 2);
                    }
                }
            }
        }
    };

    const int nch = K >> 6;
    stage(0, 0);
    for (int ch = 0; ch < nch; ch++) {
        int cur = ch & 1;
        if (ch + 1 < nch) { stage(ch + 1, cur ^ 1); CP_WAIT1(); }
        else             { CP_WAIT0(); }
        __syncthreads();
        mma_chunk(cur);
        __syncthreads();
    }

    #pragma unroll
    for (int mt = 0; mt < 2; mt++) {
        #pragma unroll
        for (int q = 0; q < 8; q++) {
            int col = c0 + warp_n * 64 + q * 8 + (lane & 3) * 2;
            float2 bv = *(const float2*)(bias + col);
            #pragma unroll
            for (int half = 0; half < 2; half++) {
                int lr = warp_m * 32 + mt * 16 + (lane >> 2) + half * 8;
                int orow = r0 + lr;
                if (orow < NND) {
                    float v0 = c[mt][q][half * 2 + 0] + bv.x;
                    float v1 = c[mt][q][half * 2 + 1] + bv.y;
                    if (act == 2) { v0 = fmaxf(v0, 0.f); v1 = fmaxf(v1, 0.f); }
                    if (outf)
                        *(float2*)(outf + (size_t)orow * N + col) = make_float2(v0, v1);
                    if (outh) {
                        uint32_t hp = packh2(v0, v1);
                        *(uint32_t*)(outh + (size_t)orow * N + col) = hp;
                    }
                }
            }
        }
    }
}

// ---------------------------------------------------------------------------
extern "C" void kernel_launch(void* const* d_in, const int* in_sizes, int n_in,
                              void* d_out, int out_size)
{
    const float* h   = (const float*)d_in[0];
    const int*   src = (const int*)  d_in[1];
    const int*   dst = (const int*)  d_in[2];
    const int*   r   = (const int*)  d_in[3];
    const int*   inv = (const int*)  d_in[4];
    const float* iW1 = (const float*)d_in[5];
    const float* ib1 = (const float*)d_in[6];
    const float* iW2 = (const float*)d_in[7];
    const float* ib2 = (const float*)d_in[8];
    const float* iW3 = (const float*)d_in[9];
    const float* ib3 = (const float*)d_in[10];
    const float* aW1 = (const float*)d_in[11];
    const float* ab1 = (const float*)d_in[12];
    const float* aW2 = (const float*)d_in[13];
    const float* ab2 = (const float*)d_in[14];
    const float* aW3 = (const float*)d_in[15];
    const float* ab3 = (const float*)d_in[16];
    const float* pW1 = (const float*)d_in[17];
    const float* pb1 = (const float*)d_in[18];
    const float* pW2 = (const float*)d_in[19];
    const float* pb2 = (const float*)d_in[20];
    float* out = (float*)d_out;

    int *invidx, *ninv;
    cudaGetSymbolAddress((void**)&invidx, g_invidx);
    cudaGetSymbolAddress((void**)&ninv, g_ninv);

    __half *th,*xh,*xl,*sh,*sl;
    cudaGetSymbolAddress((void**)&th, g_th);
    cudaGetSymbolAddress((void**)&xh, g_xh); cudaGetSymbolAddress((void**)&xl, g_xl);
    cudaGetSymbolAddress((void**)&sh, g_sh); cudaGetSymbolAddress((void**)&sl, g_sl);

    __half *wi1,*wi2,*wi3,*wa1,*wa2,*wa3,*wp1,*wp2;
    cudaGetSymbolAddress((void**)&wi1, g_iW1);
    cudaGetSymbolAddress((void**)&wi2, g_iW2);
    cudaGetSymbolAddress((void**)&wi3, g_iW3);
    cudaGetSymbolAddress((void**)&wa1, g_aW1);
    cudaGetSymbolAddress((void**)&wa2, g_aW2);
    cudaGetSymbolAddress((void**)&wa3, g_aW3);
    cudaGetSymbolAddress((void**)&wp1, g_pW1);
    cudaGetSymbolAddress((void**)&wp2, g_pW2);

    const int SMEM_F = 164864;   // fused MLP
    const int SMEM_G = 98304;    // proj gemm (2 CTAs/SM)
    cudaFuncSetAttribute(mlp3_fused, cudaFuncAttributeMaxDynamicSharedMemorySize, SMEM_F);
    cudaFuncSetAttribute(gemm_f16,   cudaFuncAttributeMaxDynamicSharedMemorySize, SMEM_G);

    // Secondary stream + fork/join events (created once; capture-safe pattern)
    static cudaStream_t s2 = nullptr;
    static cudaEvent_t evFork = nullptr, evJoin = nullptr;
    if (!s2) {
        cudaStreamCreateWithFlags(&s2, cudaStreamNonBlocking);
        cudaEventCreateWithFlags(&evFork, cudaEventDisableTiming);
        cudaEventCreateWithFlags(&evJoin, cudaEventDisableTiming);
    }

    const int NB = (NND + 127) / 128;   // 391
    dim3 g256(NB, 2);

    // fork: CSR build on s2, overlapped with prep/conv/tinv-MLP on stream 0
    cudaEventRecord(evFork, 0);
    cudaStreamWaitEvent(s2, evFork, 0);
    zero_kernel<<<196, 256, 0, s2>>>();
    hist_kernel<<<(EE + 255) / 256, 256, 0, s2>>>(dst, inv);
    scan_kernel<<<1, 1024, 0, s2>>>();
    fill_kernel<<<(EE + 255) / 256, 256, 0, s2>>>(src, dst, r);
    cudaEventRecord(evJoin, s2);

    prep_all<<<1152, 256>>>(iW1, iW2, iW3, aW1, aW2, aW3, pW1, pW2);
    conv_split<<<6250, 256>>>(h, xh, xl);
    // th = fp16(MLP_inv(h))  (fp16-hi message for gather)
    mlp3_fused<<<NB, 256, SMEM_F>>>(xh, xl, wi1, ib1, wi2, ib2, wi3, ib3,
                                    th, 0, 0, 0, 0);
    cudaStreamWaitEvent(0, evJoin, 0);

    // neigh mean over fp16 messages (xh for r==0, th for r==1)
    gather_kernel<<<6250, 256>>>(xh, th, sh, sl);
    // res = MLP_and(neigh) -> xh (hi only; downstream is single-term)
    mlp3_fused<<<NB, 256, SMEM_F>>>(sh, sl, wa1, ab1, wa2, ab2, wa3, ab3,
                                    xh, 0, 0, 0, 0);
    // res2[invidx] = MLP_inv(res[invidx])  (compact, single-term input)
    mlp3_fused<<<NB, 256, SMEM_F>>>(xh, 0, wi1, ib1, wi2, ib2, wi3, ib3,
                                    xh, 0, invidx, invidx, ninv);
    // proj head (single-term A)
    gemm_f16<<<g256, 256, SMEM_G>>>(xh, 0, wp1, pb1, 256, 256, 2, 0, sh);
    gemm_f16<<<g256, 256, SMEM_G>>>(sh, 0, wp2, pb2, 256, 256, 0, out, 0);
}

// round 16
// speedup vs baseline: 10.2294x; 1.1585x over previous
#include <cuda_runtime.h>
#include <cuda_fp16.h>
#include <cstdint>

#define NND 50000
#define NP  50048              // padded to 391*128
#define EE  800000

// ---------------------------------------------------------------------------
// Scratch (device globals; no allocations anywhere)
__device__ int   g_hist[NND];
__device__ int   g_rowptr[NND + 1];
__device__ int   g_cursor[NND];
__device__ uint32_t g_edges[EE];             // src | (r==1)<<31, CSR order by dst
__device__ int   g_invidx[NND];
__device__ int   g_ninv;

// fp16 buffers (hi-precision planes only; value-path is single-term fp16)
__device__ __align__(16) __half g_th[(size_t)NP * 256];   // fp16(MLP_inv(h))
__device__ __align__(16) __half g_xh[(size_t)NP * 256];   // fp16(h) -> res/res2
__device__ __align__(16) __half g_sh[(size_t)NP * 256];   // neigh mean -> proj hidden

// Pre-transposed fp16 weights (hi only): Wt[n][k] = W[k][n]
__device__ __align__(16) __half g_iW1[128*256];
__device__ __align__(16) __half g_iW2[128*128];
__device__ __align__(16) __half g_iW3[256*128];
__device__ __align__(16) __half g_aW1[128*256];
__device__ __align__(16) __half g_aW2[128*128];
__device__ __align__(16) __half g_aW3[256*128];
__device__ __align__(16) __half g_pW1[256*256];
__device__ __align__(16) __half g_pW2[256*256];

// ---------------------------------------------------------------------------
__device__ __forceinline__ uint32_t smem_u32_of(const void* p) {
    uint32_t a;
    asm("{ .reg .u64 t; cvta.to.shared.u64 t, %1; cvt.u32.u64 %0, t; }"
        : "=r"(a) : "l"(p));
    return a;
}
#define LDSM4(r, addr)                                                         \
    asm volatile("ldmatrix.sync.aligned.m8n8.x4.shared.b16 {%0,%1,%2,%3}, [%4];" \
        : "=r"((r)[0]), "=r"((r)[1]), "=r"((r)[2]), "=r"((r)[3]) : "r"(addr))
#define CP_ASYNC16(dst, src, sz)                                               \
    asm volatile("cp.async.cg.shared.global [%0], [%1], 16, %2;"               \
        :: "r"(dst), "l"(src), "r"(sz) : "memory")
#define CP_COMMIT() asm volatile("cp.async.commit_group;" ::: "memory")
#define CP_WAIT1()  asm volatile("cp.async.wait_group 1;" ::: "memory")
#define CP_WAIT0()  asm volatile("cp.async.wait_group 0;" ::: "memory")

__device__ __forceinline__ void mma_h(float* d, const uint32_t* a,
                                      const uint32_t* b) {
    asm volatile("mma.sync.aligned.m16n8k16.row.col.f32.f16.f16.f32 "
        "{%0,%1,%2,%3}, {%4,%5,%6,%7}, {%8,%9}, {%0,%1,%2,%3};"
        : "+f"(d[0]), "+f"(d[1]), "+f"(d[2]), "+f"(d[3])
        : "r"(a[0]), "r"(a[1]), "r"(a[2]), "r"(a[3]), "r"(b[0]), "r"(b[1]));
}
__device__ __forceinline__ uint32_t packh2(float a, float b) {
    __half x = __float2half_rn(a), y = __float2half_rn(b);
    return (uint32_t)__half_as_ushort(x) | ((uint32_t)__half_as_ushort(y) << 16);
}
__device__ __forceinline__ void split2(float v0, float v1,
                                       uint32_t& hp, uint32_t& lp) {
    __half h0 = __float2half_rn(v0), h1 = __float2half_rn(v1);
    hp = (uint32_t)__half_as_ushort(h0) | ((uint32_t)__half_as_ushort(h1) << 16);
    lp = packh2(v0 - __half2float(h0), v1 - __half2float(h1));
}

// ---------------------------------------------------------------------------
__global__ void zero_kernel() {
    int i = blockIdx.x * blockDim.x + threadIdx.x;
    if (i < NND) g_hist[i] = 0;
    if (i == 0) g_ninv = 0;
}

// hist on dst + inv compaction in one launch
__global__ void hist_kernel(const int* __restrict__ dst,
                            const int* __restrict__ inv) {
    int e = blockIdx.x * blockDim.x + threadIdx.x;
    if (e < EE) atomicAdd(&g_hist[__ldg(dst + e)], 1);
    if (e < NND && __ldg(inv + e) == 1) {
        int p = atomicAdd(&g_ninv, 1);
        g_invidx[p] = e;
    }
}

__global__ __launch_bounds__(1024, 1) void scan_kernel() {
    __shared__ int warp_sums[32];
    __shared__ int s_carry;
    int tid = threadIdx.x, lane = tid & 31, w = tid >> 5;
    if (tid == 0) s_carry = 0;
    __syncthreads();
    for (int base = 0; base < NND; base += 1024) {
        int i = base + tid;
        int v = (i < NND) ? g_hist[i] : 0;
        int x = v;
        #pragma unroll
        for (int o = 1; o < 32; o <<= 1) {
            int t = __shfl_up_sync(0xFFFFFFFFu, x, o);
            if (lane >= o) x += t;
        }
        if (lane == 31) warp_sums[w] = x;
        __syncthreads();
        if (w == 0) {
            int y = warp_sums[lane];
            #pragma unroll
            for (int o = 1; o < 32; o <<= 1) {
                int t = __shfl_up_sync(0xFFFFFFFFu, y, o);
                if (lane >= o) y += t;
            }
            warp_sums[lane] = y;
        }
        __syncthreads();
        int excl = s_carry + x - v + (w > 0 ? warp_sums[w - 1] : 0);
        if (i < NND) { g_rowptr[i] = excl; g_cursor[i] = excl; }
        __syncthreads();
        if (tid == 0) s_carry += warp_sums[31];
        __syncthreads();
    }
    if (tid == 0) g_rowptr[NND] = s_carry;
}

__global__ void fill_kernel(const int* __restrict__ src,
                            const int* __restrict__ dst,
                            const int* __restrict__ r) {
    int e = blockIdx.x * blockDim.x + threadIdx.x;
    if (e >= EE) return;
    int d = __ldg(dst + e);
    int pos = atomicAdd(&g_cursor[d], 1);
    g_edges[pos] = (uint32_t)__ldg(src + e)
                 | ((uint32_t)(__ldg(r + e) == 1) << 31);
}

// ---- gather-mean over fp16 messages: warp per node; emits fp16-hi only ----
__global__ __launch_bounds__(256) void gather_kernel(
    const __half* __restrict__ xh, const __half* __restrict__ th,
    __half* __restrict__ oh)
{
    int wid = (blockIdx.x * 256 + threadIdx.x) >> 5;
    int lane = threadIdx.x & 31;
    if (wid >= NND) return;
    int beg = __ldg(&g_rowptr[wid]), end = __ldg(&g_rowptr[wid + 1]);
    float acc[8];
    #pragma unroll
    for (int j = 0; j < 8; j++) acc[j] = 0.f;
    int e = beg;
    uint32_t pn = (e < end) ? __ldg(&g_edges[e]) : 0u;
    for (; e < end; e++) {
        uint32_t p = pn;
        if (e + 1 < end) pn = __ldg(&g_edges[e + 1]);
        const uint4* row = (const uint4*)(((p >> 31) ? th : xh)
                          + (size_t)(p & 0x7FFFFFFFu) * 256) + lane;
        uint4 w = __ldg(row);
        const uint32_t ww[4] = {w.x, w.y, w.z, w.w};
        #pragma unroll
        for (int j = 0; j < 4; j++) {
            float2 f = __half22float2(*(const __half2*)&ww[j]);
            acc[2*j]   += f.x;
            acc[2*j+1] += f.y;
        }
    }
    float sc = 1.f / fmaxf((float)(end - beg), 1.f);
    uint4 hp;
    uint32_t* hq = (uint32_t*)&hp;
    #pragma unroll
    for (int j = 0; j < 4; j++)
        hq[j] = packh2(acc[2*j] * sc, acc[2*j+1] * sc);
    *(uint4*)(oh + (size_t)wid * 256 + lane * 8) = hp;
}

// All 8 weight transposes (fp16 hi only) in one launch
__global__ void prep_all(const float* W0, const float* W1, const float* W2,
                         const float* W3, const float* W4, const float* W5,
                         const float* W6, const float* W7) {
    int i = blockIdx.x * blockDim.x + threadIdx.x;
    if (i >= 294912) return;
    const int cum[9]  = {0, 32768, 49152, 81920, 114688, 131072, 163840, 229376, 294912};
    const int Ks[8]   = {256, 128, 128, 256, 128, 128, 256, 256};
    const int Ns[8]   = {128, 128, 256, 128, 128, 256, 256, 256};
    int m = 0;
    #pragma unroll
    for (int t = 1; t < 8; t++) if (i >= cum[t]) m = t;
    int j = i - cum[m], K = Ks[m], N = Ns[m];
    int n = j / K, k = j % K;
    const float* W; __half* Th;
    switch (m) {
        case 0: W = W0; Th = g_iW1; break;
        case 1: W = W1; Th = g_iW2; break;
        case 2: W = W2; Th = g_iW3; break;
        case 3: W = W3; Th = g_aW1; break;
        case 4: W = W4; Th = g_aW2; break;
        case 5: W = W5; Th = g_aW3; break;
        case 6: W = W6; Th = g_pW1; break;
        default: W = W7; Th = g_pW2; break;
    }
    Th[j] = __float2half_rn(W[(size_t)k * N + n]);
}

// fp32 [NND x 256] -> fp16 hi only
__global__ void conv_hi(const float* __restrict__ x, __half* __restrict__ oh) {
    int u = blockIdx.x * blockDim.x + threadIdx.x;
    if (u >= NND * 32) return;
    int row = u >> 5, seg = u & 31;
    const float4* s = (const float4*)(x + (size_t)row * 256 + seg * 8);
    float4 a = s[0], b = s[1];
    uint4 hp;
    uint32_t* hq = (uint32_t*)&hp;
    hq[0] = packh2(a.x, a.y);
    hq[1] = packh2(a.z, a.w);
    hq[2] = packh2(b.x, b.y);
    hq[3] = packh2(b.z, b.w);
    *(uint4*)(oh + (size_t)row * 256 + seg * 8) = hp;
}

// ---------------------------------------------------------------------------
// Fused 3-layer MLP (fp16, single-term gmem input, 2-term smem inter):
// 256 ->(leaky) 128 ->(leaky) 128 -> 256
// SMEM map: buf0@0 (48KB: AH,-,B) buf1@49152, inter@98304 (64KB), idx@163840
__global__ __launch_bounds__(256, 1) void mlp3_fused(
    const __half* __restrict__ Ah,
    const __half* __restrict__ W1, const float* __restrict__ b1,
    const __half* __restrict__ W2, const float* __restrict__ b2,
    const __half* __restrict__ W3, const float* __restrict__ b3,
    __half* __restrict__ outh,
    const int* __restrict__ gin, const int* __restrict__ gout,
    const int* __restrict__ nrowp)
{
    extern __shared__ char sm[];
    const uint32_t smb = smem_u32_of(sm);
    const int tid = threadIdx.x, lane = tid & 31, warp = tid >> 5;
    const int warp_m = warp & 3, warp_n = warp >> 2;
    const int r0 = blockIdx.x * 128;
    const uint32_t S = smb;
    const uint32_t IH0 = smb + 98304u, IH1 = smb + 114688u;
    const uint32_t IL0 = smb + 131072u, IL1 = smb + 147456u;

    const int nrow = nrowp ? __ldg(nrowp) : NND;
    if (r0 >= nrow) return;

    int* sidx_in  = (int*)(sm + 163840);
    int* sidx_out = (int*)(sm + 164352);
    for (int i = tid; i < 128; i += 256) {
        int gr = r0 + i;
        bool ok = gr < nrow;
        sidx_in[i]  = ok ? (gin  ? __ldg(gin  + gr) : gr) : -1;
        sidx_out[i] = ok ? (gout ? __ldg(gout + gr) : gr) : -1;
    }
    __syncthreads();

    float c[2][8][4];
    auto zero_c = [&]() {
        #pragma unroll
        for (int i = 0; i < 2; i++)
            #pragma unroll
            for (int j = 0; j < 8; j++)
                #pragma unroll
                for (int k = 0; k < 4; k++) c[i][j][k] = 0.f;
    };

    auto stageA = [&](const __half* src, uint32_t dstb, int k0) {
        #pragma unroll
        for (int it = 0; it < 4; it++) {
            int u = tid + it * 256, row = u >> 3, seg = u & 7;
            int grow = sidx_in[row];
            uint32_t sz = (grow >= 0) ? 16u : 0u;
            const void* sp = src + (size_t)(grow >= 0 ? grow : 0) * 256 + k0 + seg * 8;
            CP_ASYNC16(dstb + (uint32_t)row * 128 + ((uint32_t)(seg ^ (row & 7)) << 4),
                       sp, sz);
        }
    };
    auto stageB = [&](const __half* src, uint32_t dstb, int rows, int K, int k0) {
        for (int u = tid; u < rows * 8; u += 256) {
            int row = u >> 3, seg = u & 7;
            CP_ASYNC16(dstb + (uint32_t)row * 128 + ((uint32_t)(seg ^ (row & 7)) << 4),
                       src + (size_t)row * K + k0 + seg * 8, 16u);
        }
    };

    auto mma_chunk = [&](uint32_t AHb, uint32_t ALb, uint32_t Bb, bool useAL) {
        #pragma unroll
        for (int ks = 0; ks < 4; ks++) {
            uint32_t ah[2][4], al[2][4];
            #pragma unroll
            for (int mt = 0; mt < 2; mt++) {
                int lr = warp_m * 32 + mt * 16 + (lane & 15);
                int seg = 2 * ks + (lane >> 4);
                uint32_t off = (uint32_t)lr * 128 + ((uint32_t)(seg ^ (lr & 7)) << 4);
                LDSM4(ah[mt], AHb + off);
                if (useAL) LDSM4(al[mt], ALb + off);
            }
            #pragma unroll
            for (int nq = 0; nq < 4; nq++) {
                int lrb = warp_n * 64 + nq * 16 + (lane & 7) + ((lane >> 4) << 3);
                int segb = 2 * ks + ((lane >> 3) & 1);
                uint32_t offb = (uint32_t)lrb * 128 + ((uint32_t)(segb ^ (lrb & 7)) << 4);
                uint32_t bh[4];
                LDSM4(bh, Bb + offb);
                #pragma unroll
                for (int mt = 0; mt < 2; mt++) {
                    #pragma unroll
                    for (int sub = 0; sub < 2; sub++) {
                        float* d = c[mt][nq * 2 + sub];
                        mma_h(d, ah[mt], bh + sub * 2);
                        if (useAL) mma_h(d, al[mt], bh + sub * 2);
                    }
                }
            }
        }
    };

    auto epi_smem = [&](const float* __restrict__ bias) {
        #pragma unroll
        for (int mt = 0; mt < 2; mt++) {
            #pragma unroll
            for (int q = 0; q < 8; q++) {
                int col = warp_n * 64 + q * 8 + (lane & 3) * 2;
                float2 bv = *(const float2*)(bias + col);
                uint32_t chb = ((col >> 6) ? IH1 : IH0);
                int cc = col & 63;
                #pragma unroll
                for (int half = 0; half < 2; half++) {
                    int lr = warp_m * 32 + mt * 16 + (lane >> 2) + half * 8;
                    float v0 = c[mt][q][half * 2 + 0] + bv.x;
                    float v1 = c[mt][q][half * 2 + 1] + bv.y;
                    v0 = (v0 >= 0.f) ? v0 : 0.01f * v0;
                    v1 = (v1 >= 0.f) ? v1 : 0.01f * v1;
                    uint32_t hp, lp;
                    split2(v0, v1, hp, lp);
                    uint32_t addr = chb + (uint32_t)lr * 128
                                  + ((uint32_t)((cc >> 3) ^ (lr & 7)) << 4)
                                  + (uint32_t)(cc & 7) * 2;
                    asm volatile("st.shared.b32 [%0], %1;" :: "r"(addr), "r"(hp) : "memory");
                    asm volatile("st.shared.b32 [%0], %1;" :: "r"(addr + 32768u), "r"(lp) : "memory");
                }
            }
        }
    };

    // ---- Layer 1: K=256, 4 chunks, double-buffered, single-term A ----
    zero_c();
    {
        auto stage1 = [&](int ch, int buf) {
            uint32_t base = S + (uint32_t)buf * 49152u;
            stageA(Ah, base, ch * 64);
            stageB(W1, base + 32768u, 128, 256, ch * 64);
            CP_COMMIT();
        };
        stage1(0, 0);
        for (int ch = 0; ch < 4; ch++) {
            int cur = ch & 1;
            if (ch + 1 < 4) {
                stage1(ch + 1, cur ^ 1);
                CP_WAIT1();
            } else {
                stageB(W2, S + 0u,     128, 128, 0);
                stageB(W2, S + 16384u, 128, 128, 64);
                CP_COMMIT();
                CP_WAIT1();
            }
            __syncthreads();
            uint32_t base = S + (uint32_t)cur * 49152u;
            mma_chunk(base, 0u, base + 32768u, false);
            __syncthreads();
        }
    }
    stageB(W3, S + 32768u, 256, 128, 0);
    stageB(W3, S + 65536u, 256, 128, 64);
    CP_COMMIT();
    epi_smem(b1);
    CP_WAIT1();
    __syncthreads();

    // ---- Layer 2: K=128, A = inter (2-term), B = W2 ----
    zero_c();
    mma_chunk(IH0, IL0, S + 0u, true);
    mma_chunk(IH1, IL1, S + 16384u, true);
    __syncthreads();
    epi_smem(b2);
    CP_WAIT0();
    __syncthreads();

    // ---- Layer 3: K=128, N=256 (two column halves), linear ----
    #pragma unroll
    for (int hf = 0; hf < 2; hf++) {
        zero_c();
        mma_chunk(IH0, IL0, S + 32768u + (uint32_t)hf * 16384u, true);
        mma_chunk(IH1, IL1, S + 65536u + (uint32_t)hf * 16384u, true);
        #pragma unroll
        for (int mt = 0; mt < 2; mt++) {
            #pragma unroll
            for (int q = 0; q < 8; q++) {
                int col = hf * 128 + warp_n * 64 + q * 8 + (lane & 3) * 2;
                float2 bv = *(const float2*)(b3 + col);
                #pragma unroll
                for (int half = 0; half < 2; half++) {
                    int lr = warp_m * 32 + mt * 16 + (lane >> 2) + half * 8;
                    int orow = sidx_out[lr];
                    if (orow >= 0) {
                        float v0 = c[mt][q][half * 2 + 0] + bv.x;
                        float v1 = c[mt][q][half * 2 + 1] + bv.y;
                        *(uint32_t*)(outh + (size_t)orow * 256 + col) = packh2(v0, v1);
                    }
                }
            }
        }
    }
}

// ---------------------------------------------------------------------------
// Generic fp16 GEMM (proj head), single-term A, 2 CTAs/SM.
__global__ __launch_bounds__(256, 2) void gemm_f16(
    const __half* __restrict__ Ah,
    const __half* __restrict__ B,
    const float* __restrict__ bias, int K, int N, int act,
    float* __restrict__ outf, __half* __restrict__ outh)
{
    extern __shared__ char sm[];
    const uint32_t smb = smem_u32_of(sm);
    const int tid = threadIdx.x, lane = tid & 31, warp = tid >> 5;
    const int warp_m = warp & 3, warp_n = warp >> 2;
    const int r0 = blockIdx.x * 128;
    const int c0 = blockIdx.y * 128;

    float c[2][8][4];
    #pragma unroll
    for (int i = 0; i < 2; i++)
        #pragma unroll
        for (int j = 0; j < 8; j++)
            #pragma unroll
            for (int k = 0; k < 4; k++) c[i][j][k] = 0.f;

    auto stage = [&](int ch, int buf) {
        uint32_t base = smb + (uint32_t)buf * 49152u;
        #pragma unroll
        for (int it = 0; it < 4; it++) {
            int u = tid + it * 256, row = u >> 3, seg = u & 7;
            int grow = r0 + row;
            uint32_t sz = (grow < NND) ? 16u : 0u;
            CP_ASYNC16(base + (uint32_t)row * 128
                       + ((uint32_t)(seg ^ (row & 7)) << 4),
                       Ah + (size_t)(grow < NND ? grow : 0) * K + ch * 64 + seg * 8,
                       sz);
        }
        #pragma unroll
        for (int it = 0; it < 4; it++) {
            int u = tid + it * 256, row = u >> 3, seg = u & 7;
            CP_ASYNC16(base + 32768u + (uint32_t)row * 128
                       + ((uint32_t)(seg ^ (row & 7)) << 4),
                       B + (size_t)(c0 + row) * K + ch * 64 + seg * 8, 16u);
        }
        CP_COMMIT();
    };

    auto mma_chunk = [&](int buf) {
        uint32_t base = smb + (uint32_t)buf * 49152u;
        #pragma unroll
        for (int ks = 0; ks < 4; ks++) {
            uint32_t ah[2][4];
            #pragma unroll
            for (int mt = 0; mt < 2; mt++) {
                int lr = warp_m * 32 + mt * 16 + (lane & 15);
                int seg = 2 * ks + (lane >> 4);
                uint32_t off = (uint32_t)lr * 128 + ((uint32_t)(seg ^ (lr & 7)) << 4);
                LDSM4(ah[mt], base + off);
            }
            #pragma unroll
            for (int nq = 0; nq < 4; nq++) {
                int lrb = warp_n * 64 + nq * 16 + (lane & 7) + ((lane >> 4) << 3);
                int segb = 2 * ks + ((lane >> 3) & 1);
                uint32_t offb = (uint32_t)lrb * 128 + ((uint32_t)(segb ^ (lrb & 7)) << 4);
                uint32_t bh[4];
                LDSM4(bh, base + 32768u + offb);
                #pragma unroll
                for (int mt = 0; mt < 2; mt++) {
                    #pragma unroll
                    for (int sub = 0; sub < 2; sub++) {
                        float* d = c[mt][nq * 2 + sub];
                        mma_h(d, ah[mt], bh + sub * 2);
                    }
                }
            }
        }
    };

    const int nch = K >> 6;
    stage(0, 0);
    for (int ch = 0; ch < nch; ch++) {
        int cur = ch & 1;
        if (ch + 1 < nch) { stage(ch + 1, cur ^ 1); CP_WAIT1(); }
        else             { CP_WAIT0(); }
        __syncthreads();
        mma_chunk(cur);
        __syncthreads();
    }

    #pragma unroll
    for (int mt = 0; mt < 2; mt++) {
        #pragma unroll
        for (int q = 0; q < 8; q++) {
            int col = c0 + warp_n * 64 + q * 8 + (lane & 3) * 2;
            float2 bv = *(const float2*)(bias + col);
            #pragma unroll
            for (int half = 0; half < 2; half++) {
                int lr = warp_m * 32 + mt * 16 + (lane >> 2) + half * 8;
                int orow = r0 + lr;
                if (orow < NND) {
                    float v0 = c[mt][q][half * 2 + 0] + bv.x;
                    float v1 = c[mt][q][half * 2 + 1] + bv.y;
                    if (act == 2) { v0 = fmaxf(v0, 0.f); v1 = fmaxf(v1, 0.f); }
                    if (outf)
                        *(float2*)(outf + (size_t)orow * N + col) = make_float2(v0, v1);
                    if (outh)
                        *(uint32_t*)(outh + (size_t)orow * N + col) = packh2(v0, v1);
                }
            }
        }
    }
}

// ---------------------------------------------------------------------------
extern "C" void kernel_launch(void* const* d_in, const int* in_sizes, int n_in,
                              void* d_out, int out_size)
{
    const float* h   = (const float*)d_in[0];
    const int*   src = (const int*)  d_in[1];
    const int*   dst = (const int*)  d_in[2];
    const int*   r   = (const int*)  d_in[3];
    const int*   inv = (const int*)  d_in[4];
    const float* iW1 = (const float*)d_in[5];
    const float* ib1 = (const float*)d_in[6];
    const float* iW2 = (const float*)d_in[7];
    const float* ib2 = (const float*)d_in[8];
    const float* iW3 = (const float*)d_in[9];
    const float* ib3 = (const float*)d_in[10];
    const float* aW1 = (const float*)d_in[11];
    const float* ab1 = (const float*)d_in[12];
    const float* aW2 = (const float*)d_in[13];
    const float* ab2 = (const float*)d_in[14];
    const float* aW3 = (const float*)d_in[15];
    const float* ab3 = (const float*)d_in[16];
    const float* pW1 = (const float*)d_in[17];
    const float* pb1 = (const float*)d_in[18];
    const float* pW2 = (const float*)d_in[19];
    const float* pb2 = (const float*)d_in[20];
    float* out = (float*)d_out;

    int *invidx, *ninv;
    cudaGetSymbolAddress((void**)&invidx, g_invidx);
    cudaGetSymbolAddress((void**)&ninv, g_ninv);

    __half *th,*xh,*sh;
    cudaGetSymbolAddress((void**)&th, g_th);
    cudaGetSymbolAddress((void**)&xh, g_xh);
    cudaGetSymbolAddress((void**)&sh, g_sh);

    __half *wi1,*wi2,*wi3,*wa1,*wa2,*wa3,*wp1,*wp2;
    cudaGetSymbolAddress((void**)&wi1, g_iW1);
    cudaGetSymbolAddress((void**)&wi2, g_iW2);
    cudaGetSymbolAddress((void**)&wi3, g_iW3);
    cudaGetSymbolAddress((void**)&wa1, g_aW1);
    cudaGetSymbolAddress((void**)&wa2, g_aW2);
    cudaGetSymbolAddress((void**)&wa3, g_aW3);
    cudaGetSymbolAddress((void**)&wp1, g_pW1);
    cudaGetSymbolAddress((void**)&wp2, g_pW2);

    const int SMEM_F = 164864;   // fused MLP
    const int SMEM_G = 98304;    // proj gemm (2 CTAs/SM)
    cudaFuncSetAttribute(mlp3_fused, cudaFuncAttributeMaxDynamicSharedMemorySize, SMEM_F);
    cudaFuncSetAttribute(gemm_f16,   cudaFuncAttributeMaxDynamicSharedMemorySize, SMEM_G);

    // Secondary stream + fork/join events (created once; capture-safe pattern)
    static cudaStream_t s2 = nullptr;
    static cudaEvent_t evFork = nullptr, evJoin = nullptr;
    if (!s2) {
        cudaStreamCreateWithFlags(&s2, cudaStreamNonBlocking);
        cudaEventCreateWithFlags(&evFork, cudaEventDisableTiming);
        cudaEventCreateWithFlags(&evJoin, cudaEventDisableTiming);
    }

    const int NB = (NND + 127) / 128;   // 391
    dim3 g256(NB, 2);

    // fork: CSR build on s2, overlapped with prep/conv/tinv-MLP on stream 0
    cudaEventRecord(evFork, 0);
    cudaStreamWaitEvent(s2, evFork, 0);
    zero_kernel<<<196, 256, 0, s2>>>();
    hist_kernel<<<(EE + 255) / 256, 256, 0, s2>>>(dst, inv);
    scan_kernel<<<1, 1024, 0, s2>>>();
    fill_kernel<<<(EE + 255) / 256, 256, 0, s2>>>(src, dst, r);
    cudaEventRecord(evJoin, s2);

    prep_all<<<1152, 256>>>(iW1, iW2, iW3, aW1, aW2, aW3, pW1, pW2);
    conv_hi<<<6250, 256>>>(h, xh);
    // th = fp16(MLP_inv(h))  (single-term input)
    mlp3_fused<<<NB, 256, SMEM_F>>>(xh, wi1, ib1, wi2, ib2, wi3, ib3,
                                    th, 0, 0, 0);
    cudaStreamWaitEvent(0, evJoin, 0);

    // neigh mean over fp16 messages (xh for r==0, th for r==1), hi-only out
    gather_kernel<<<6250, 256>>>(xh, th, sh);
    // res = MLP_and(neigh) -> xh
    mlp3_fused<<<NB, 256, SMEM_F>>>(sh, wa1, ab1, wa2, ab2, wa3, ab3,
                                    xh, 0, 0, 0);
    // res2[invidx] = MLP_inv(res[invidx])  (compact)
    mlp3_fused<<<NB, 256, SMEM_F>>>(xh, wi1, ib1, wi2, ib2, wi3, ib3,
                                    xh, invidx, invidx, ninv);
    // proj head
    gemm_f16<<<g256, 256, SMEM_G>>>(xh, wp1, pb1, 256, 256, 2, 0, sh);
    gemm_f16<<<g256, 256, SMEM_G>>>(sh, wp2, pb2, 256, 256, 0, out, 0);
}